// round 1
// baseline (speedup 1.0000x reference)
#include <cuda_runtime.h>
#include <math.h>

#define B_ 4
#define T_ 4096
#define D_ 1024
#define H_ 8
#define K_ 128
#define C_ 64
#define NCH 64            // T_/C_
#define M_ (B_*T_)        // 16384
#define RS 129            // padded smem row stride (bank-conflict-free column reads)
#define SLICES 4
#define SW 32

// ---------------- scratch (device globals; no cudaMalloc allowed) -------------
__device__ float g_xwv [B_*T_*D_];
__device__ float g_gate[B_*T_*D_];
__device__ float g_v   [B_*T_*D_];
__device__ float g_rk  [B_*T_*D_];
__device__ float g_wk  [B_*T_*D_];
__device__ float g_wkc [B_*T_*D_];
__device__ float g_o   [B_*T_*D_];
__device__ float g_beta[B_*T_*H_];
__device__ float g_dec [B_*T_*H_];
__device__ float g_dcum[B_*T_*H_];
__device__ float g_attn[B_*H_*NCH*C_*C_];

// ---------------- SGEMM: C[m,n] = sum_k A[m,k]*W[n,k]  (A: MxKd, W: NxKd) -----
__device__ __forceinline__ void sgemm_body(const float* __restrict__ A,
                                           const float* __restrict__ W,
                                           float* __restrict__ C,
                                           int N, int Kd) {
    __shared__ float As[8][128];
    __shared__ float Bs[8][128];
    const int tid = threadIdx.x;
    const int m0 = blockIdx.y * 128;
    const int n0 = blockIdx.x * 128;
    const int tx = tid & 15, ty = tid >> 4;
    const int lrow = tid >> 1;
    const int lcol = (tid & 1) << 2;
    float acc[8][8];
#pragma unroll
    for (int i = 0; i < 8; i++)
#pragma unroll
        for (int j = 0; j < 8; j++) acc[i][j] = 0.f;

    for (int k0 = 0; k0 < Kd; k0 += 8) {
        float4 av = *reinterpret_cast<const float4*>(A + (size_t)(m0 + lrow) * Kd + k0 + lcol);
        float4 bv = *reinterpret_cast<const float4*>(W + (size_t)(n0 + lrow) * Kd + k0 + lcol);
        As[lcol + 0][lrow] = av.x; As[lcol + 1][lrow] = av.y;
        As[lcol + 2][lrow] = av.z; As[lcol + 3][lrow] = av.w;
        Bs[lcol + 0][lrow] = bv.x; Bs[lcol + 1][lrow] = bv.y;
        Bs[lcol + 2][lrow] = bv.z; Bs[lcol + 3][lrow] = bv.w;
        __syncthreads();
#pragma unroll
        for (int kk = 0; kk < 8; kk++) {
            float ra[8], rb[8];
#pragma unroll
            for (int i = 0; i < 8; i++) ra[i] = As[kk][ty * 8 + i];
#pragma unroll
            for (int j = 0; j < 8; j++) rb[j] = Bs[kk][tx * 8 + j];
#pragma unroll
            for (int i = 0; i < 8; i++)
#pragma unroll
                for (int j = 0; j < 8; j++) acc[i][j] = fmaf(ra[i], rb[j], acc[i][j]);
        }
        __syncthreads();
    }
#pragma unroll
    for (int i = 0; i < 8; i++) {
        float* cp = C + (size_t)(m0 + ty * 8 + i) * N + n0 + tx * 8;
#pragma unroll
        for (int j = 0; j < 8; j += 4) {
            float4 o4 = make_float4(acc[i][j], acc[i][j + 1], acc[i][j + 2], acc[i][j + 3]);
            *reinterpret_cast<float4*>(cp + j) = o4;
        }
    }
}

__global__ void __launch_bounds__(256) gemm_xWv(const float* __restrict__ x, const float* __restrict__ Wv) {
    sgemm_body(x, Wv, g_xwv, D_, D_);
}
__global__ void __launch_bounds__(256) gemm_xWg(const float* __restrict__ x, const float* __restrict__ Wg) {
    sgemm_body(x, Wg, g_gate, D_, D_);
}
__global__ void __launch_bounds__(256) gemm_out(const float* __restrict__ Wo, float* __restrict__ out) {
    sgemm_body(g_xwv, Wo, out, D_, D_);
}

// ---------------- beta / decay small projections ------------------------------
__global__ void __launch_bounds__(256) proj_small(const float* __restrict__ x,
                                                  const float* __restrict__ Wb,
                                                  const float* __restrict__ Wa,
                                                  const float* __restrict__ dt_bias,
                                                  const float* __restrict__ A_log) {
    const int row = blockIdx.x;   // b*T + t
    __shared__ float sx[D_];
    for (int i = threadIdx.x; i < D_; i += 256) sx[i] = x[(size_t)row * D_ + i];
    __syncthreads();
    const int w = threadIdx.x >> 5, lane = threadIdx.x & 31;   // warp = head
    const float* wb = Wb + w * D_;
    const float* wa = Wa + w * D_;
    float db = 0.f, da = 0.f;
    for (int k = lane; k < D_; k += 32) {
        float xv = sx[k];
        db = fmaf(xv, wb[k], db);
        da = fmaf(xv, wa[k], da);
    }
#pragma unroll
    for (int off = 16; off; off >>= 1) {
        db += __shfl_down_sync(0xffffffffu, db, off);
        da += __shfl_down_sync(0xffffffffu, da, off);
    }
    if (lane == 0) {
        g_beta[row * H_ + w] = 1.f / (1.f + expf(-db));
        float z = da + dt_bias[w];
        float sp = (z > 20.f) ? z : log1pf(expf(z));
        g_dec[row * H_ + w] = -expf(A_log[w]) * sp;
    }
}

// ---------------- causal depthwise conv + SiLU + beta --------------------------
__global__ void conv_silu(const float* __restrict__ conv_w, const float* __restrict__ conv_b) {
    long idx = (long)blockIdx.x * 256 + threadIdx.x;   // over B*T*D
    const int d = (int)(idx & (D_ - 1));
    const long bt = idx >> 10;
    const int t = (int)(bt & (T_ - 1));
    float acc = conv_b[d];
#pragma unroll
    for (int j = 0; j < 4; j++) {
        int tt = t + j - 3;
        if (tt >= 0) acc = fmaf(g_xwv[idx + (long)(j - 3) * D_], conv_w[d * 4 + j], acc);
    }
    float s = acc / (1.f + expf(-acc));                // silu
    g_v[idx] = s * g_beta[bt * H_ + (d >> 7)];
}

// ---------------- rk / wk per-head L2 norms ------------------------------------
__global__ void __launch_bounds__(128) norm_rw(const float* __restrict__ x) {
    const int bh = blockIdx.x;       // (b*T+t)*H + h
    const int h = bh & 7;
    const long bt = (long)(bh >> 3);
    const int t = (int)(bt & (T_ - 1));
    const int k = threadIdx.x;
    float xv = x[bt * D_ + h * K_ + k];
    float xs = (t > 0) ? x[(bt - 1) * D_ + h * K_ + k] : 0.f;
    float s1 = xv * xv, s2 = xs * xs;
#pragma unroll
    for (int off = 16; off; off >>= 1) {
        s1 += __shfl_xor_sync(0xffffffffu, s1, off);
        s2 += __shfl_xor_sync(0xffffffffu, s2, off);
    }
    __shared__ float r1[4], r2[4];
    const int w = k >> 5, lane = k & 31;
    if (lane == 0) { r1[w] = s1; r2[w] = s2; }
    __syncthreads();
    float S1 = r1[0] + r1[1] + r1[2] + r1[3];
    float S2 = r2[0] + r2[1] + r2[2] + r2[3];
    g_rk[(long)bh * K_ + k] = xv * rsqrtf(S1 + 1e-6f) * 0.08838834764831845f; // /sqrt(128)
    g_wk[(long)bh * K_ + k] = xs * rsqrtf(S2 + 1e-6f);
}

// ---------------- within-chunk cumulative decay --------------------------------
__global__ void __launch_bounds__(64) cumsum_dec() {
    const int id = blockIdx.x;       // (b*H+h)*NCH + chunk
    const int chunk = id & 63;
    const int bh = id >> 6;
    const int b = bh >> 3, h = bh & 7;
    __shared__ float s[C_];
    const int c = threadIdx.x;
    const long base = (long)b * T_ + chunk * C_;
    s[c] = g_dec[(base + c) * H_ + h];
    __syncthreads();
    float acc = 0.f;
    for (int j = 0; j <= c; j++) acc += s[j];
    g_dcum[(base + c) * H_ + h] = acc;
}

// ---------------- per-chunk: A_strict, attn, triangular solve -------------------
__global__ void __launch_bounds__(128) chunk_prep() {
    extern __shared__ float sm[];
    float* sA = sm;                 // 64*64
    float* s1 = sm + 4096;          // 64*RS : wk -> u
    float* s2 = s1 + C_ * RS;       // 64*RS : rk -> v
    __shared__ float sdec[C_], sbeta[C_];
    const int id = blockIdx.x;      // (b*H+h)*NCH + chunk
    const int chunk = id & 63;
    const int bh = id >> 6;
    const int b = bh >> 3, h = bh & 7;
    const long t0 = (long)b * T_ + chunk * C_;
    const long base = (t0 * H_ + h) * K_;       // token row stride = D_
    const int tid = threadIdx.x;

    for (int i = tid; i < C_ * K_; i += 128) {
        int c = i >> 7, k = i & 127;
        s1[c * RS + k] = g_wk[base + (long)c * D_ + k];
        s2[c * RS + k] = g_rk[base + (long)c * D_ + k];
    }
    if (tid < C_) {
        sdec[tid] = g_dcum[(t0 + tid) * H_ + h];
        sbeta[tid] = g_beta[(t0 + tid) * H_ + h];
    }
    __syncthreads();

    // A_strict (smem) and attn (global), both (i,j) with L_ij = exp(dec_i - dec_j)
    for (int p = tid; p < C_ * C_; p += 128) {
        int i = p >> 6, j = p & 63;
        float av = 0.f, atv = 0.f;
        if (j <= i) {
            const float* wi = s1 + i * RS;
            const float* wj = s1 + j * RS;
            const float* ri = s2 + i * RS;
            float dwk = 0.f, drk = 0.f;
#pragma unroll 4
            for (int k = 0; k < K_; k++) {
                float w = wj[k];
                dwk = fmaf(wi[k], w, dwk);
                drk = fmaf(ri[k], w, drk);
            }
            float l = __expf(sdec[i] - sdec[j]);
            atv = drk * l;
            if (j < i) av = -dwk * sbeta[i] * l;
        }
        g_attn[(long)id * 4096 + p] = atv;
        sA[p] = av;
    }
    __syncthreads();

    // s1 -> u = wk*beta*exp(dcum),  s2 -> v
    for (int i = tid; i < C_ * K_; i += 128) {
        int c = i >> 7, k = i & 127;
        s1[c * RS + k] *= sbeta[c] * __expf(sdec[c]);
        s2[c * RS + k] = g_v[base + (long)c * D_ + k];
    }
    __syncthreads();

    // forward substitution: X[i] += sum_{j<i} A[i,j] X[j]  (per-column, no deps)
    {
        const int k = tid;           // 128 threads == 128 columns
        for (int i = 1; i < C_; i++) {
            float a1 = 0.f, a2 = 0.f;
            const float* Ai = sA + i * 64;
#pragma unroll 4
            for (int j = 0; j < i; j++) {
                float a = Ai[j];
                a1 = fmaf(a, s1[j * RS + k], a1);
                a2 = fmaf(a, s2[j * RS + k], a2);
            }
            s1[i * RS + k] += a1;
            s2[i * RS + k] += a2;
        }
    }
    __syncthreads();

    for (int i = tid; i < C_ * K_; i += 128) {
        int c = i >> 7, k = i & 127;
        g_wkc[base + (long)c * D_ + k] = s1[c * RS + k];
        g_v  [base + (long)c * D_ + k] = s2[c * RS + k];
    }
}

// ---------------- sequential chunk scan (value-dim sliced) ----------------------
__global__ void __launch_bounds__(256) scan_kernel() {
    extern __shared__ float sm[];
    float* sS    = sm;               // 128*32
    float* srk   = sS + 4096;        // 64*128
    float* swk   = srk + 8192;       // 64*128
    float* swkc  = swk + 8192;       // 64*128
    float* sattn = swkc + 8192;      // 64*64
    float* sv    = sattn + 4096;     // 64*32
    __shared__ float sdec[C_], sdw[C_];
    const int bh = blockIdx.x >> 2;
    const int slice = blockIdx.x & 3;
    const int b = bh >> 3, h = bh & 7;
    const int j0g = slice * SW;
    const int tid = threadIdx.x;

    for (int i = tid; i < 4096; i += 256) sS[i] = 0.f;
    __syncthreads();

    for (int chunk = 0; chunk < NCH; chunk++) {
        const long t0 = (long)b * T_ + chunk * C_;
        const long base = (t0 * H_ + h) * K_;
        for (int i = tid; i < C_ * K_; i += 256) {
            int c = i >> 7, k = i & 127;
            long g = base + (long)c * D_ + k;
            srk[i] = g_rk[g]; swk[i] = g_wk[g]; swkc[i] = g_wkc[g];
        }
        for (int i = tid; i < C_ * SW; i += 256) {
            int c = i >> 5, j = i & 31;
            sv[i] = g_v[base + (long)c * D_ + j0g + j];
        }
        {
            long ab = ((long)bh * NCH + chunk) * 4096;
            for (int i = tid; i < 4096; i += 256) sattn[i] = g_attn[ab + i];
        }
        if (tid < C_) sdec[tid] = g_dcum[(t0 + tid) * H_ + h];
        __syncthreads();
        if (tid < C_) sdw[tid] = __expf(sdec[63] - sdec[tid]);   // used after 2 syncs

        // v_new = v - wkc @ S   (in place into sv; per-thread elements only)
        {
            const int c = tid >> 2, j0 = (tid & 3) << 3;
            float acc[8];
#pragma unroll
            for (int i = 0; i < 8; i++) acc[i] = sv[c * SW + j0 + i];
            for (int k = 0; k < K_; k++) {
                float w = swkc[c * K_ + k];
                const float* sp = sS + k * SW + j0;
#pragma unroll
                for (int i = 0; i < 8; i++) acc[i] = fmaf(-w, sp[i], acc[i]);
            }
#pragma unroll
            for (int i = 0; i < 8; i++) sv[c * SW + j0 + i] = acc[i];
        }
        __syncthreads();

        // o = exp(dec_c) * (rk @ S) + attn @ v_new
        {
            const int c = tid >> 2, j0 = (tid & 3) << 3;
            float acc[8];
#pragma unroll
            for (int i = 0; i < 8; i++) acc[i] = 0.f;
            for (int k = 0; k < K_; k++) {
                float r = srk[c * K_ + k];
                const float* sp = sS + k * SW + j0;
#pragma unroll
                for (int i = 0; i < 8; i++) acc[i] = fmaf(r, sp[i], acc[i]);
            }
            float ec = __expf(sdec[c]);
#pragma unroll
            for (int i = 0; i < 8; i++) acc[i] *= ec;
            for (int jj = 0; jj < C_; jj++) {
                float a = sattn[c * 64 + jj];
                const float* vp = sv + jj * SW + j0;
#pragma unroll
                for (int i = 0; i < 8; i++) acc[i] = fmaf(a, vp[i], acc[i]);
            }
            float* op = g_o + base + (long)c * D_ + j0g + j0;
#pragma unroll
            for (int i = 0; i < 8; i++) op[i] = acc[i];
        }
        __syncthreads();

        // S = S*exp(dec_63) + (wk * dw)^T @ v_new
        {
            const int k = tid >> 1, j0 = (tid & 1) << 4;
            float acc[16];
#pragma unroll
            for (int i = 0; i < 16; i++) acc[i] = 0.f;
            for (int c = 0; c < C_; c++) {
                float w = swk[c * K_ + k] * sdw[c];
                const float* vp = sv + c * SW + j0;
#pragma unroll
                for (int i = 0; i < 16; i++) acc[i] = fmaf(w, vp[i], acc[i]);
            }
            float e63 = __expf(sdec[63]);
            float* sp = sS + k * SW + j0;
#pragma unroll
            for (int i = 0; i < 16; i++) sp[i] = sp[i] * e63 + acc[i];
        }
        __syncthreads();
    }
}

// ---------------- per-head RMSNorm + gated SiLU ---------------------------------
__global__ void __launch_bounds__(128) rms_gate(const float* __restrict__ norm_w) {
    const int bhk = blockIdx.x;      // (b*T+t)*H + h
    const int k = threadIdx.x;
    const long gi = (long)bhk * K_ + k;    // == bt*D_ + h*K_ + k
    float ov = g_o[gi];
    float s = ov * ov;
#pragma unroll
    for (int off = 16; off; off >>= 1) s += __shfl_xor_sync(0xffffffffu, s, off);
    __shared__ float red[4];
    if ((k & 31) == 0) red[k >> 5] = s;
    __syncthreads();
    float tot = red[0] + red[1] + red[2] + red[3];
    float r = rsqrtf(tot * (1.f / 128.f) + 1e-5f);
    float g = g_gate[gi];
    float sg = g / (1.f + expf(-g));
    g_xwv[gi] = ov * r * norm_w[k] * sg;   // reuse g_xwv as epilogue input
}

// ---------------- launcher ------------------------------------------------------
extern "C" void kernel_launch(void* const* d_in, const int* in_sizes, int n_in,
                              void* d_out, int out_size) {
    const float* x       = (const float*)d_in[0];
    const float* Wv      = (const float*)d_in[1];
    const float* Wg      = (const float*)d_in[2];
    const float* Wo      = (const float*)d_in[3];
    const float* Wb      = (const float*)d_in[4];
    const float* Wa      = (const float*)d_in[5];
    const float* dt_bias = (const float*)d_in[6];
    const float* A_log   = (const float*)d_in[7];
    const float* norm_w  = (const float*)d_in[8];
    const float* conv_w  = (const float*)d_in[9];
    const float* conv_b  = (const float*)d_in[10];
    float* out = (float*)d_out;

    const int CP_SMEM   = (4096 + 2 * C_ * RS) * 4;                       // 82432 B
    const int SCAN_SMEM = (4096 + 3 * 8192 + 4096 + 2048) * 4;            // 139264 B
    cudaFuncSetAttribute(chunk_prep,  cudaFuncAttributeMaxDynamicSharedMemorySize, CP_SMEM);
    cudaFuncSetAttribute(scan_kernel, cudaFuncAttributeMaxDynamicSharedMemorySize, SCAN_SMEM);

    dim3 gg(D_ / 128, M_ / 128);
    gemm_xWv<<<gg, 256>>>(x, Wv);
    gemm_xWg<<<gg, 256>>>(x, Wg);
    proj_small<<<M_, 256>>>(x, Wb, Wa, dt_bias, A_log);
    conv_silu<<<(B_ * T_ * D_) / 256, 256>>>(conv_w, conv_b);
    norm_rw<<<M_ * H_, 128>>>(x);
    cumsum_dec<<<B_ * H_ * NCH, C_>>>();
    chunk_prep<<<B_ * H_ * NCH, 128, CP_SMEM>>>();
    scan_kernel<<<B_ * H_ * SLICES, 256, SCAN_SMEM>>>();
    rms_gate<<<M_ * H_, 128>>>(norm_w);
    gemm_out<<<gg, 256>>>(Wo, out);
}

// round 3
// speedup vs baseline: 1.3637x; 1.3637x over previous
#include <cuda_runtime.h>
#include <cuda_bf16.h>
#include <math.h>
#include <cstdint>

#define B_ 4
#define T_ 4096
#define D_ 1024
#define H_ 8
#define K_ 128
#define C_ 64
#define NCH 64            // T_/C_
#define M_ (B_*T_)        // 16384
#define RS 129            // padded smem row stride
#define SLICES 4
#define SW 32
#define STR 40            // bf16 smem stride for GEMM tiles (conflict-free)

// ---------------- scratch (device globals; no cudaMalloc allowed) -------------
__device__ float g_xwv [B_*T_*D_];
__device__ float g_gate[B_*T_*D_];
__device__ float g_v   [B_*T_*D_];
__device__ float g_rk  [B_*T_*D_];
__device__ float g_wk  [B_*T_*D_];
__device__ float g_wkc [B_*T_*D_];
__device__ float g_o   [B_*T_*D_];
__device__ float g_beta[B_*T_*H_];
__device__ float g_dec [B_*T_*H_];
__device__ float g_dcum[B_*T_*H_];
__device__ float g_attn[B_*H_*NCH*C_*C_];
// split-bf16 operands for tensor-core GEMMs
__device__ __nv_bfloat16 g_xhi[M_*D_], g_xlo[M_*D_];
__device__ __nv_bfloat16 g_ahi[M_*D_], g_alo[M_*D_];
__device__ __nv_bfloat16 g_Wvhi[D_*D_], g_Wvlo[D_*D_];
__device__ __nv_bfloat16 g_Wghi[D_*D_], g_Wglo[D_*D_];
__device__ __nv_bfloat16 g_Wohi[D_*D_], g_Wolo[D_*D_];

// ================= low-level helpers (baseline ISA only: sm_80+) ==============
__device__ __forceinline__ uint32_t smem_u32(const void* p) {
    uint32_t a;
    asm("{ .reg .u64 t; cvta.to.shared.u64 t, %1; cvt.u32.u64 %0, t; }" : "=r"(a) : "l"(p));
    return a;
}
__device__ __forceinline__ void cpasync16(uint32_t saddr, const void* gaddr) {
    asm volatile("cp.async.cg.shared.global [%0], [%1], 16;" :: "r"(saddr), "l"(gaddr));
}
#define CP_COMMIT() asm volatile("cp.async.commit_group;" ::: "memory")
#define CP_WAIT0()  asm volatile("cp.async.wait_group 0;" ::: "memory")

__device__ __forceinline__ void ldsm4(uint32_t* r, uint32_t saddr) {
    asm volatile("ldmatrix.sync.aligned.m8n8.x4.shared.b16 {%0,%1,%2,%3}, [%4];"
        : "=r"(r[0]), "=r"(r[1]), "=r"(r[2]), "=r"(r[3]) : "r"(saddr));
}
__device__ __forceinline__ void mma16816(float* c, const uint32_t* a, uint32_t b0, uint32_t b1) {
    asm volatile(
        "mma.sync.aligned.m16n8k16.row.col.f32.bf16.bf16.f32 "
        "{%0,%1,%2,%3}, {%4,%5,%6,%7}, {%8,%9}, {%0,%1,%2,%3};"
        : "+f"(c[0]), "+f"(c[1]), "+f"(c[2]), "+f"(c[3])
        : "r"(a[0]), "r"(a[1]), "r"(a[2]), "r"(a[3]), "r"(b0), "r"(b1));
}

// ================= split-bf16 conversion kernels ================================
__device__ __forceinline__ void split4(const float* __restrict__ src,
                                       __nv_bfloat16* __restrict__ hi,
                                       __nv_bfloat16* __restrict__ lo, long i) {
    float4 v = *reinterpret_cast<const float4*>(src + i);
    __nv_bfloat16 h0 = __float2bfloat16(v.x), h1 = __float2bfloat16(v.y);
    __nv_bfloat16 h2 = __float2bfloat16(v.z), h3 = __float2bfloat16(v.w);
    __nv_bfloat16 l0 = __float2bfloat16(v.x - __bfloat162float(h0));
    __nv_bfloat16 l1 = __float2bfloat16(v.y - __bfloat162float(h1));
    __nv_bfloat16 l2 = __float2bfloat16(v.z - __bfloat162float(h2));
    __nv_bfloat16 l3 = __float2bfloat16(v.w - __bfloat162float(h3));
    *reinterpret_cast<__nv_bfloat162*>(hi + i)     = __nv_bfloat162(h0, h1);
    *reinterpret_cast<__nv_bfloat162*>(hi + i + 2) = __nv_bfloat162(h2, h3);
    *reinterpret_cast<__nv_bfloat162*>(lo + i)     = __nv_bfloat162(l0, l1);
    *reinterpret_cast<__nv_bfloat162*>(lo + i + 2) = __nv_bfloat162(l2, l3);
}
__global__ void __launch_bounds__(256) split_x_k(const float* __restrict__ x) {
    long i = ((long)blockIdx.x * 256 + threadIdx.x) * 4;
    split4(x, g_xhi, g_xlo, i);
}
__global__ void __launch_bounds__(256) split_w_k(const float* __restrict__ Wv,
                                                 const float* __restrict__ Wg,
                                                 const float* __restrict__ Wo) {
    long i = ((long)blockIdx.x * 256 + threadIdx.x) * 4;   // over 3*1M
    if (i < 1048576)            split4(Wv, g_Wvhi, g_Wvlo, i);
    else if (i < 2097152)       split4(Wg, g_Wghi, g_Wglo, i - 1048576);
    else                        split4(Wo, g_Wohi, g_Wolo, i - 2097152);
}

// ================= HMMA split-bf16 GEMM =========================================
// C[m,n] = sum_k A[m,k]*B[n,k].  3 passes: Ahi*Bhi + Alo*Bhi + Ahi*Blo, fp32 acc.
__device__ __forceinline__ void gemm_hmma_body(
    const __nv_bfloat16* __restrict__ Ahi, const __nv_bfloat16* __restrict__ Alo,
    const __nv_bfloat16* __restrict__ Bhi, const __nv_bfloat16* __restrict__ Blo,
    float* __restrict__ Cm) {
    __shared__ alignas(16) __nv_bfloat16 sA[2][128 * STR];
    __shared__ alignas(16) __nv_bfloat16 sB[2][128 * STR];
    const int tid = threadIdx.x;
    const int wid = tid >> 5, lane = tid & 31;
    const int wm = wid & 1;        // 2 warps along M (64 rows each)
    const int wn = wid >> 1;       // 4 warps along N (32 cols each)
    const int m0 = blockIdx.y * 128;
    const int n0 = blockIdx.x * 128;

    float acc[4][4][4];
#pragma unroll
    for (int mt = 0; mt < 4; mt++)
#pragma unroll
        for (int nt = 0; nt < 4; nt++)
#pragma unroll
            for (int q = 0; q < 4; q++) acc[mt][nt][q] = 0.f;

    // per-thread load slots: u = tid + {0,256}; row = u>>2, seg = u&3 (16B each)
    const int lrow0 = tid >> 2, lseg = (tid & 3) * 8;
    const int lrow1 = lrow0 + 64;

    auto load_chunk = [&](int ci, int buf) {
        const int p = ci >> 5;
        const int kc = (ci & 31) * 32;
        const __nv_bfloat16* ag = ((p == 1) ? Alo : Ahi) + (size_t)m0 * 1024 + kc;
        const __nv_bfloat16* bg = ((p == 2) ? Blo : Bhi) + (size_t)n0 * 1024 + kc;
        uint32_t sa = smem_u32(&sA[buf][0]);
        uint32_t sb = smem_u32(&sB[buf][0]);
        cpasync16(sa + (lrow0 * STR + lseg) * 2, ag + (size_t)lrow0 * 1024 + lseg);
        cpasync16(sa + (lrow1 * STR + lseg) * 2, ag + (size_t)lrow1 * 1024 + lseg);
        cpasync16(sb + (lrow0 * STR + lseg) * 2, bg + (size_t)lrow0 * 1024 + lseg);
        cpasync16(sb + (lrow1 * STR + lseg) * 2, bg + (size_t)lrow1 * 1024 + lseg);
        CP_COMMIT();
    };

    const int r8 = lane & 7, sel = lane >> 3;

    load_chunk(0, 0);
    for (int i = 0; i < 96; i++) {
        CP_WAIT0();
        __syncthreads();
        if (i + 1 < 96) load_chunk(i + 1, (i + 1) & 1);
        const int buf = i & 1;
#pragma unroll
        for (int ks = 0; ks < 2; ks++) {
            const int k16 = ks * 16;
            uint32_t af[4][4];
#pragma unroll
            for (int mt = 0; mt < 4; mt++) {
                int row = wm * 64 + mt * 16 + (sel & 1) * 8 + r8;
                int col = k16 + (sel >> 1) * 8;
                ldsm4(af[mt], smem_u32(&sA[buf][row * STR + col]));
            }
            uint32_t bf2[2][4];
#pragma unroll
            for (int bt = 0; bt < 2; bt++) {
                int nrow = wn * 32 + bt * 16 + (sel >> 1) * 8 + r8;
                int col = k16 + (sel & 1) * 8;
                ldsm4(bf2[bt], smem_u32(&sB[buf][nrow * STR + col]));
            }
#pragma unroll
            for (int mt = 0; mt < 4; mt++)
#pragma unroll
                for (int nt = 0; nt < 4; nt++)
                    mma16816(acc[mt][nt], af[mt],
                             bf2[nt >> 1][(nt & 1) * 2], bf2[nt >> 1][(nt & 1) * 2 + 1]);
        }
        __syncthreads();
    }

    // epilogue: c0,c1 -> (row, col..col+1); c2,c3 -> (row+8, ...)
    const int erow = lane >> 2, ecol = (lane & 3) * 2;
#pragma unroll
    for (int mt = 0; mt < 4; mt++) {
        const size_t row0 = (size_t)(m0 + wm * 64 + mt * 16 + erow);
#pragma unroll
        for (int nt = 0; nt < 4; nt++) {
            const size_t cb = (size_t)(n0 + wn * 32 + nt * 8 + ecol);
            *reinterpret_cast<float2*>(Cm + row0 * 1024 + cb) =
                make_float2(acc[mt][nt][0], acc[mt][nt][1]);
            *reinterpret_cast<float2*>(Cm + (row0 + 8) * 1024 + cb) =
                make_float2(acc[mt][nt][2], acc[mt][nt][3]);
        }
    }
}

__global__ void __launch_bounds__(256) gemm_v_tc() { gemm_hmma_body(g_xhi, g_xlo, g_Wvhi, g_Wvlo, g_xwv); }
__global__ void __launch_bounds__(256) gemm_g_tc() { gemm_hmma_body(g_xhi, g_xlo, g_Wghi, g_Wglo, g_gate); }
__global__ void __launch_bounds__(256) gemm_o_tc(float* __restrict__ out) {
    gemm_hmma_body(g_ahi, g_alo, g_Wohi, g_Wolo, out);
}

// ---------------- beta / decay small projections ------------------------------
__global__ void __launch_bounds__(256) proj_small(const float* __restrict__ x,
                                                  const float* __restrict__ Wb,
                                                  const float* __restrict__ Wa,
                                                  const float* __restrict__ dt_bias,
                                                  const float* __restrict__ A_log) {
    const int row = blockIdx.x;   // b*T + t
    __shared__ float sx[D_];
    for (int i = threadIdx.x; i < D_; i += 256) sx[i] = x[(size_t)row * D_ + i];
    __syncthreads();
    const int w = threadIdx.x >> 5, lane = threadIdx.x & 31;   // warp = head
    const float* wb = Wb + w * D_;
    const float* wa = Wa + w * D_;
    float db = 0.f, da = 0.f;
    for (int k = lane; k < D_; k += 32) {
        float xv = sx[k];
        db = fmaf(xv, wb[k], db);
        da = fmaf(xv, wa[k], da);
    }
#pragma unroll
    for (int off = 16; off; off >>= 1) {
        db += __shfl_down_sync(0xffffffffu, db, off);
        da += __shfl_down_sync(0xffffffffu, da, off);
    }
    if (lane == 0) {
        g_beta[row * H_ + w] = 1.f / (1.f + expf(-db));
        float z = da + dt_bias[w];
        float sp = (z > 20.f) ? z : log1pf(expf(z));
        g_dec[row * H_ + w] = -expf(A_log[w]) * sp;
    }
}

// ---------------- causal depthwise conv + SiLU + beta --------------------------
__global__ void conv_silu(const float* __restrict__ conv_w, const float* __restrict__ conv_b) {
    long idx = (long)blockIdx.x * 256 + threadIdx.x;   // over B*T*D
    const int d = (int)(idx & (D_ - 1));
    const long bt = idx >> 10;
    const int t = (int)(bt & (T_ - 1));
    float acc = conv_b[d];
#pragma unroll
    for (int j = 0; j < 4; j++) {
        int tt = t + j - 3;
        if (tt >= 0) acc = fmaf(g_xwv[idx + (long)(j - 3) * D_], conv_w[d * 4 + j], acc);
    }
    float s = acc / (1.f + expf(-acc));                // silu
    g_v[idx] = s * g_beta[bt * H_ + (d >> 7)];
}

// ---------------- rk / wk per-head L2 norms ------------------------------------
__global__ void __launch_bounds__(128) norm_rw(const float* __restrict__ x) {
    const int bh = blockIdx.x;       // (b*T+t)*H + h
    const int h = bh & 7;
    const long bt = (long)(bh >> 3);
    const int t = (int)(bt & (T_ - 1));
    const int k = threadIdx.x;
    float xv = x[bt * D_ + h * K_ + k];
    float xs = (t > 0) ? x[(bt - 1) * D_ + h * K_ + k] : 0.f;
    float s1 = xv * xv, s2 = xs * xs;
#pragma unroll
    for (int off = 16; off; off >>= 1) {
        s1 += __shfl_xor_sync(0xffffffffu, s1, off);
        s2 += __shfl_xor_sync(0xffffffffu, s2, off);
    }
    __shared__ float r1[4], r2[4];
    const int w = k >> 5, lane = k & 31;
    if (lane == 0) { r1[w] = s1; r2[w] = s2; }
    __syncthreads();
    float S1 = r1[0] + r1[1] + r1[2] + r1[3];
    float S2 = r2[0] + r2[1] + r2[2] + r2[3];
    g_rk[(long)bh * K_ + k] = xv * rsqrtf(S1 + 1e-6f) * 0.08838834764831845f; // /sqrt(128)
    g_wk[(long)bh * K_ + k] = xs * rsqrtf(S2 + 1e-6f);
}

// ---------------- within-chunk cumulative decay --------------------------------
__global__ void __launch_bounds__(64) cumsum_dec() {
    const int id = blockIdx.x;       // (b*H+h)*NCH + chunk
    const int chunk = id & 63;
    const int bh = id >> 6;
    const int b = bh >> 3, h = bh & 7;
    __shared__ float s[C_];
    const int c = threadIdx.x;
    const long base = (long)b * T_ + chunk * C_;
    s[c] = g_dec[(base + c) * H_ + h];
    __syncthreads();
    float acc = 0.f;
    for (int j = 0; j <= c; j++) acc += s[j];
    g_dcum[(base + c) * H_ + h] = acc;
}

// ---------------- per-chunk: A_strict, attn, triangular solve -------------------
__global__ void __launch_bounds__(128) chunk_prep() {
    extern __shared__ float sm[];
    float* sA = sm;                 // 64*64
    float* s1 = sm + 4096;          // 64*RS : wk -> u
    float* s2 = s1 + C_ * RS;       // 64*RS : rk -> v
    __shared__ float sdec[C_], sbeta[C_];
    const int id = blockIdx.x;      // (b*H+h)*NCH + chunk
    const int chunk = id & 63;
    const int bh = id >> 6;
    const int b = bh >> 3, h = bh & 7;
    const long t0 = (long)b * T_ + chunk * C_;
    const long base = (t0 * H_ + h) * K_;       // token row stride = D_
    const int tid = threadIdx.x;

    for (int i = tid; i < C_ * K_; i += 128) {
        int c = i >> 7, k = i & 127;
        s1[c * RS + k] = g_wk[base + (long)c * D_ + k];
        s2[c * RS + k] = g_rk[base + (long)c * D_ + k];
    }
    if (tid < C_) {
        sdec[tid] = g_dcum[(t0 + tid) * H_ + h];
        sbeta[tid] = g_beta[(t0 + tid) * H_ + h];
    }
    __syncthreads();

    // A_strict (smem) and attn (global), both (i,j) with L_ij = exp(dec_i - dec_j)
    for (int p = tid; p < C_ * C_; p += 128) {
        int i = p >> 6, j = p & 63;
        float av = 0.f, atv = 0.f;
        if (j <= i) {
            const float* wi = s1 + i * RS;
            const float* wj = s1 + j * RS;
            const float* ri = s2 + i * RS;
            float dwk = 0.f, drk = 0.f;
#pragma unroll 4
            for (int k = 0; k < K_; k++) {
                float w = wj[k];
                dwk = fmaf(wi[k], w, dwk);
                drk = fmaf(ri[k], w, drk);
            }
            float l = __expf(sdec[i] - sdec[j]);
            atv = drk * l;
            if (j < i) av = -dwk * sbeta[i] * l;
        }
        g_attn[(long)id * 4096 + p] = atv;
        sA[p] = av;
    }
    __syncthreads();

    // s1 -> u = wk*beta*exp(dcum),  s2 -> v
    for (int i = tid; i < C_ * K_; i += 128) {
        int c = i >> 7, k = i & 127;
        s1[c * RS + k] *= sbeta[c] * __expf(sdec[c]);
        s2[c * RS + k] = g_v[base + (long)c * D_ + k];
    }
    __syncthreads();

    // forward substitution: X[i] += sum_{j<i} A[i,j] X[j]  (per-column, no deps)
    {
        const int k = tid;           // 128 threads == 128 columns
        for (int i = 1; i < C_; i++) {
            float a1 = 0.f, a2 = 0.f;
            const float* Ai = sA + i * 64;
#pragma unroll 4
            for (int j = 0; j < i; j++) {
                float a = Ai[j];
                a1 = fmaf(a, s1[j * RS + k], a1);
                a2 = fmaf(a, s2[j * RS + k], a2);
            }
            s1[i * RS + k] += a1;
            s2[i * RS + k] += a2;
        }
    }
    __syncthreads();

    for (int i = tid; i < C_ * K_; i += 128) {
        int c = i >> 7, k = i & 127;
        g_wkc[base + (long)c * D_ + k] = s1[c * RS + k];
        g_v  [base + (long)c * D_ + k] = s2[c * RS + k];
    }
}

// ---------------- sequential chunk scan (value-dim sliced) ----------------------
__global__ void __launch_bounds__(256) scan_kernel() {
    extern __shared__ float sm[];
    float* sS    = sm;               // 128*32
    float* srk   = sS + 4096;        // 64*128
    float* swk   = srk + 8192;       // 64*128
    float* swkc  = swk + 8192;       // 64*128
    float* sattn = swkc + 8192;      // 64*64
    float* sv    = sattn + 4096;     // 64*32
    __shared__ float sdec[C_], sdw[C_];
    const int bh = blockIdx.x >> 2;
    const int slice = blockIdx.x & 3;
    const int b = bh >> 3, h = bh & 7;
    const int j0g = slice * SW;
    const int tid = threadIdx.x;

    for (int i = tid; i < 4096; i += 256) sS[i] = 0.f;
    __syncthreads();

    for (int chunk = 0; chunk < NCH; chunk++) {
        const long t0 = (long)b * T_ + chunk * C_;
        const long base = (t0 * H_ + h) * K_;
        for (int i = tid; i < C_ * K_; i += 256) {
            int c = i >> 7, k = i & 127;
            long g = base + (long)c * D_ + k;
            srk[i] = g_rk[g]; swk[i] = g_wk[g]; swkc[i] = g_wkc[g];
        }
        for (int i = tid; i < C_ * SW; i += 256) {
            int c = i >> 5, j = i & 31;
            sv[i] = g_v[base + (long)c * D_ + j0g + j];
        }
        {
            long ab = ((long)bh * NCH + chunk) * 4096;
            for (int i = tid; i < 4096; i += 256) sattn[i] = g_attn[ab + i];
        }
        if (tid < C_) sdec[tid] = g_dcum[(t0 + tid) * H_ + h];
        __syncthreads();
        if (tid < C_) sdw[tid] = __expf(sdec[63] - sdec[tid]);   // used after 2 syncs

        // v_new = v - wkc @ S
        {
            const int c = tid >> 2, j0 = (tid & 3) << 3;
            float acc[8];
#pragma unroll
            for (int i = 0; i < 8; i++) acc[i] = sv[c * SW + j0 + i];
            for (int k = 0; k < K_; k++) {
                float w = swkc[c * K_ + k];
                const float* sp = sS + k * SW + j0;
#pragma unroll
                for (int i = 0; i < 8; i++) acc[i] = fmaf(-w, sp[i], acc[i]);
            }
#pragma unroll
            for (int i = 0; i < 8; i++) sv[c * SW + j0 + i] = acc[i];
        }
        __syncthreads();

        // o = exp(dec_c) * (rk @ S) + attn @ v_new
        {
            const int c = tid >> 2, j0 = (tid & 3) << 3;
            float acc[8];
#pragma unroll
            for (int i = 0; i < 8; i++) acc[i] = 0.f;
            for (int k = 0; k < K_; k++) {
                float r = srk[c * K_ + k];
                const float* sp = sS + k * SW + j0;
#pragma unroll
                for (int i = 0; i < 8; i++) acc[i] = fmaf(r, sp[i], acc[i]);
            }
            float ec = __expf(sdec[c]);
#pragma unroll
            for (int i = 0; i < 8; i++) acc[i] *= ec;
            for (int jj = 0; jj < C_; jj++) {
                float a = sattn[c * 64 + jj];
                const float* vp = sv + jj * SW + j0;
#pragma unroll
                for (int i = 0; i < 8; i++) acc[i] = fmaf(a, vp[i], acc[i]);
            }
            float* op = g_o + base + (long)c * D_ + j0g + j0;
#pragma unroll
            for (int i = 0; i < 8; i++) op[i] = acc[i];
        }
        __syncthreads();

        // S = S*exp(dec_63) + (wk * dw)^T @ v_new
        {
            const int k = tid >> 1, j0 = (tid & 1) << 4;
            float acc[16];
#pragma unroll
            for (int i = 0; i < 16; i++) acc[i] = 0.f;
            for (int c = 0; c < C_; c++) {
                float w = swk[c * K_ + k] * sdw[c];
                const float* vp = sv + c * SW + j0;
#pragma unroll
                for (int i = 0; i < 16; i++) acc[i] = fmaf(w, vp[i], acc[i]);
            }
            float e63 = __expf(sdec[63]);
            float* sp = sS + k * SW + j0;
#pragma unroll
            for (int i = 0; i < 16; i++) sp[i] = sp[i] * e63 + acc[i];
        }
        __syncthreads();
    }
}

// ---------------- per-head RMSNorm + gated SiLU (writes split bf16) --------------
__global__ void __launch_bounds__(128) rms_gate(const float* __restrict__ norm_w) {
    const int bhk = blockIdx.x;      // (b*T+t)*H + h
    const int k = threadIdx.x;
    const long gi = (long)bhk * K_ + k;    // == bt*D_ + h*K_ + k
    float ov = g_o[gi];
    float s = ov * ov;
#pragma unroll
    for (int off = 16; off; off >>= 1) s += __shfl_xor_sync(0xffffffffu, s, off);
    __shared__ float red[4];
    if ((k & 31) == 0) red[k >> 5] = s;
    __syncthreads();
    float tot = red[0] + red[1] + red[2] + red[3];
    float r = rsqrtf(tot * (1.f / 128.f) + 1e-5f);
    float g = g_gate[gi];
    float sg = g / (1.f + expf(-g));
    float val = ov * r * norm_w[k] * sg;
    __nv_bfloat16 hbv = __float2bfloat16(val);
    g_ahi[gi] = hbv;
    g_alo[gi] = __float2bfloat16(val - __bfloat162float(hbv));
}

// ---------------- launcher ------------------------------------------------------
extern "C" void kernel_launch(void* const* d_in, const int* in_sizes, int n_in,
                              void* d_out, int out_size) {
    const float* x       = (const float*)d_in[0];
    const float* Wv      = (const float*)d_in[1];
    const float* Wg      = (const float*)d_in[2];
    const float* Wo      = (const float*)d_in[3];
    const float* Wb      = (const float*)d_in[4];
    const float* Wa      = (const float*)d_in[5];
    const float* dt_bias = (const float*)d_in[6];
    const float* A_log   = (const float*)d_in[7];
    const float* norm_w  = (const float*)d_in[8];
    const float* conv_w  = (const float*)d_in[9];
    const float* conv_b  = (const float*)d_in[10];
    float* out = (float*)d_out;

    const int CP_SMEM   = (4096 + 2 * C_ * RS) * 4;                       // 82432 B
    const int SCAN_SMEM = (4096 + 3 * 8192 + 4096 + 2048) * 4;            // 139264 B
    cudaFuncSetAttribute(chunk_prep,  cudaFuncAttributeMaxDynamicSharedMemorySize, CP_SMEM);
    cudaFuncSetAttribute(scan_kernel, cudaFuncAttributeMaxDynamicSharedMemorySize, SCAN_SMEM);

    dim3 gg(D_ / 128, M_ / 128);   // (8, 128)

    split_x_k<<<(M_ * D_) / 1024, 256>>>(x);
    split_w_k<<<(3 * D_ * D_) / 1024, 256>>>(Wv, Wg, Wo);
    gemm_v_tc<<<gg, 256>>>();
    gemm_g_tc<<<gg, 256>>>();
    proj_small<<<M_, 256>>>(x, Wb, Wa, dt_bias, A_log);
    conv_silu<<<(B_ * T_ * D_) / 256, 256>>>(conv_w, conv_b);
    norm_rw<<<M_ * H_, 128>>>(x);
    cumsum_dec<<<B_ * H_ * NCH, C_>>>();
    chunk_prep<<<B_ * H_ * NCH, 128, CP_SMEM>>>();
    scan_kernel<<<B_ * H_ * SLICES, 256, SCAN_SMEM>>>();
    rms_gate<<<M_ * H_, 128>>>(norm_w);
    gemm_o_tc<<<gg, 256>>>(out);
}

// round 4
// speedup vs baseline: 1.7635x; 1.2932x over previous
#include <cuda_runtime.h>
#include <cuda_bf16.h>
#include <math.h>
#include <cstdint>

#define B_ 4
#define T_ 4096
#define D_ 1024
#define H_ 8
#define K_ 128
#define C_ 64
#define NCH 64
#define M_ (B_*T_)
#define RS 129
#define SLICES 4
#define SW 32
#define GSTR 40           // bf16 smem stride for GEMM tiles
// scan smem strides (bank-conflict-free per access pattern)
#define SSS 33            // sS: 128 x 32
#define SRS 132           // rk/wk/wkc: 64 x 128
#define SAS 68            // attn: 64 x 64
#define SVS 33            // sv: 64 x 32

// ---------------- scratch -------------------------------------------------------
__device__ float g_xwv [B_*T_*D_];
__device__ float g_gate[B_*T_*D_];
__device__ float g_v   [B_*T_*D_];
__device__ float g_rk  [B_*T_*D_];
__device__ float g_wk  [B_*T_*D_];
__device__ float g_wkc [B_*T_*D_];
__device__ float g_o   [B_*T_*D_];
__device__ float g_beta[B_*T_*H_];
__device__ float g_dec [B_*T_*H_];
__device__ float g_dcum[B_*T_*H_];
__device__ float g_attn[B_*H_*NCH*C_*C_];
__device__ __nv_bfloat16 g_xhi[M_*D_], g_xlo[M_*D_];
__device__ __nv_bfloat16 g_ahi[M_*D_], g_alo[M_*D_];
__device__ __nv_bfloat16 g_Wvhi[D_*D_], g_Wvlo[D_*D_];
__device__ __nv_bfloat16 g_Wghi[D_*D_], g_Wglo[D_*D_];
__device__ __nv_bfloat16 g_Wohi[D_*D_], g_Wolo[D_*D_];

// ================= low-level helpers ===========================================
__device__ __forceinline__ uint32_t smem_u32(const void* p) {
    uint32_t a;
    asm("{ .reg .u64 t; cvta.to.shared.u64 t, %1; cvt.u32.u64 %0, t; }" : "=r"(a) : "l"(p));
    return a;
}
__device__ __forceinline__ void cpasync16(uint32_t saddr, const void* gaddr) {
    asm volatile("cp.async.cg.shared.global [%0], [%1], 16;" :: "r"(saddr), "l"(gaddr));
}
__device__ __forceinline__ void cpasync4(uint32_t saddr, const void* gaddr) {
    asm volatile("cp.async.ca.shared.global [%0], [%1], 4;" :: "r"(saddr), "l"(gaddr));
}
#define CP_COMMIT() asm volatile("cp.async.commit_group;" ::: "memory")
#define CP_WAIT0()  asm volatile("cp.async.wait_group 0;" ::: "memory")

__device__ __forceinline__ void ldsm4(uint32_t* r, uint32_t saddr) {
    asm volatile("ldmatrix.sync.aligned.m8n8.x4.shared.b16 {%0,%1,%2,%3}, [%4];"
        : "=r"(r[0]), "=r"(r[1]), "=r"(r[2]), "=r"(r[3]) : "r"(saddr));
}
__device__ __forceinline__ void mma16816(float* c, const uint32_t* a, uint32_t b0, uint32_t b1) {
    asm volatile(
        "mma.sync.aligned.m16n8k16.row.col.f32.bf16.bf16.f32 "
        "{%0,%1,%2,%3}, {%4,%5,%6,%7}, {%8,%9}, {%0,%1,%2,%3};"
        : "+f"(c[0]), "+f"(c[1]), "+f"(c[2]), "+f"(c[3])
        : "r"(a[0]), "r"(a[1]), "r"(a[2]), "r"(a[3]), "r"(b0), "r"(b1));
}

// ================= split-bf16 conversion ========================================
__device__ __forceinline__ void split4(const float* __restrict__ src,
                                       __nv_bfloat16* __restrict__ hi,
                                       __nv_bfloat16* __restrict__ lo, long i) {
    float4 v = *reinterpret_cast<const float4*>(src + i);
    __nv_bfloat16 h0 = __float2bfloat16(v.x), h1 = __float2bfloat16(v.y);
    __nv_bfloat16 h2 = __float2bfloat16(v.z), h3 = __float2bfloat16(v.w);
    __nv_bfloat16 l0 = __float2bfloat16(v.x - __bfloat162float(h0));
    __nv_bfloat16 l1 = __float2bfloat16(v.y - __bfloat162float(h1));
    __nv_bfloat16 l2 = __float2bfloat16(v.z - __bfloat162float(h2));
    __nv_bfloat16 l3 = __float2bfloat16(v.w - __bfloat162float(h3));
    *reinterpret_cast<__nv_bfloat162*>(hi + i)     = __nv_bfloat162(h0, h1);
    *reinterpret_cast<__nv_bfloat162*>(hi + i + 2) = __nv_bfloat162(h2, h3);
    *reinterpret_cast<__nv_bfloat162*>(lo + i)     = __nv_bfloat162(l0, l1);
    *reinterpret_cast<__nv_bfloat162*>(lo + i + 2) = __nv_bfloat162(l2, l3);
}
__global__ void __launch_bounds__(256) split_x_k(const float* __restrict__ x) {
    long i = ((long)blockIdx.x * 256 + threadIdx.x) * 4;
    split4(x, g_xhi, g_xlo, i);
}
__global__ void __launch_bounds__(256) split_w_k(const float* __restrict__ Wv,
                                                 const float* __restrict__ Wg,
                                                 const float* __restrict__ Wo) {
    long i = ((long)blockIdx.x * 256 + threadIdx.x) * 4;
    if (i < 1048576)            split4(Wv, g_Wvhi, g_Wvlo, i);
    else if (i < 2097152)       split4(Wg, g_Wghi, g_Wglo, i - 1048576);
    else                        split4(Wo, g_Wohi, g_Wolo, i - 2097152);
}

// ================= HMMA split-bf16 GEMM (4-tile stages, 3 passes per load) ======
#define TILE_E (128 * GSTR)          // elements per tile
#define STAGE_E (4 * TILE_E)         // elements per stage
__device__ __forceinline__ void gemm_hmma_body(
    const __nv_bfloat16* __restrict__ Ahi, const __nv_bfloat16* __restrict__ Alo,
    const __nv_bfloat16* __restrict__ Bhi, const __nv_bfloat16* __restrict__ Blo,
    float* __restrict__ Cm) {
    extern __shared__ __nv_bfloat16 dsm[];
    const int tid = threadIdx.x;
    const int wid = tid >> 5, lane = tid & 31;
    const int wm = wid & 1;
    const int wn = wid >> 1;
    const int m0 = blockIdx.y * 128;
    const int n0 = blockIdx.x * 128;

    float acc[4][4][4];
#pragma unroll
    for (int mt = 0; mt < 4; mt++)
#pragma unroll
        for (int nt = 0; nt < 4; nt++)
#pragma unroll
            for (int q = 0; q < 4; q++) acc[mt][nt][q] = 0.f;

    const int lrow = tid >> 2, lseg = (tid & 3) * 8;

    const __nv_bfloat16* gp[4];
    gp[0] = Ahi + (size_t)m0 * 1024;
    gp[1] = Alo + (size_t)m0 * 1024;
    gp[2] = Bhi + (size_t)n0 * 1024;
    gp[3] = Blo + (size_t)n0 * 1024;

    auto load_chunk = [&](int kc, int buf) {
#pragma unroll
        for (int t = 0; t < 4; t++) {
            const __nv_bfloat16* g = gp[t] + kc * 32;
            uint32_t s = smem_u32(&dsm[buf * STAGE_E + t * TILE_E]);
            cpasync16(s + (lrow * GSTR + lseg) * 2, g + (size_t)lrow * 1024 + lseg);
            cpasync16(s + ((lrow + 64) * GSTR + lseg) * 2, g + (size_t)(lrow + 64) * 1024 + lseg);
        }
        CP_COMMIT();
    };

    const int r8 = lane & 7, sel = lane >> 3;

    load_chunk(0, 0);
    for (int kc = 0; kc < 32; kc++) {
        CP_WAIT0();
        __syncthreads();
        if (kc + 1 < 32) load_chunk(kc + 1, (kc + 1) & 1);
        const int buf = kc & 1;
        const uint32_t sAhi = smem_u32(&dsm[buf * STAGE_E + 0 * TILE_E]);
        const uint32_t sAlo = sAhi + TILE_E * 2;
        const uint32_t sBhi = sAhi + 2 * TILE_E * 2;
        const uint32_t sBlo = sAhi + 3 * TILE_E * 2;
#pragma unroll
        for (int ks = 0; ks < 2; ks++) {
            const int k16 = ks * 16;
            const int acol = k16 + (sel >> 1) * 8;
            const int bcol = k16 + (sel & 1) * 8;
            uint32_t ah[4][4], al[4][4], bb[2][4];
#pragma unroll
            for (int mt = 0; mt < 4; mt++) {
                int row = wm * 64 + mt * 16 + (sel & 1) * 8 + r8;
                ldsm4(ah[mt], sAhi + (row * GSTR + acol) * 2);
                ldsm4(al[mt], sAlo + (row * GSTR + acol) * 2);
            }
#pragma unroll
            for (int bt = 0; bt < 2; bt++) {
                int nrow = wn * 32 + bt * 16 + (sel >> 1) * 8 + r8;
                ldsm4(bb[bt], sBhi + (nrow * GSTR + bcol) * 2);
            }
#pragma unroll
            for (int mt = 0; mt < 4; mt++)
#pragma unroll
                for (int nt = 0; nt < 4; nt++) {
                    mma16816(acc[mt][nt], ah[mt], bb[nt >> 1][(nt & 1) * 2], bb[nt >> 1][(nt & 1) * 2 + 1]);
                    mma16816(acc[mt][nt], al[mt], bb[nt >> 1][(nt & 1) * 2], bb[nt >> 1][(nt & 1) * 2 + 1]);
                }
#pragma unroll
            for (int bt = 0; bt < 2; bt++) {
                int nrow = wn * 32 + bt * 16 + (sel >> 1) * 8 + r8;
                ldsm4(bb[bt], sBlo + (nrow * GSTR + bcol) * 2);
            }
#pragma unroll
            for (int mt = 0; mt < 4; mt++)
#pragma unroll
                for (int nt = 0; nt < 4; nt++)
                    mma16816(acc[mt][nt], ah[mt], bb[nt >> 1][(nt & 1) * 2], bb[nt >> 1][(nt & 1) * 2 + 1]);
        }
        __syncthreads();
    }

    const int erow = lane >> 2, ecol = (lane & 3) * 2;
#pragma unroll
    for (int mt = 0; mt < 4; mt++) {
        const size_t row0 = (size_t)(m0 + wm * 64 + mt * 16 + erow);
#pragma unroll
        for (int nt = 0; nt < 4; nt++) {
            const size_t cb = (size_t)(n0 + wn * 32 + nt * 8 + ecol);
            *reinterpret_cast<float2*>(Cm + row0 * 1024 + cb) =
                make_float2(acc[mt][nt][0], acc[mt][nt][1]);
            *reinterpret_cast<float2*>(Cm + (row0 + 8) * 1024 + cb) =
                make_float2(acc[mt][nt][2], acc[mt][nt][3]);
        }
    }
}

__global__ void __launch_bounds__(256, 2) gemm_v_tc() { gemm_hmma_body(g_xhi, g_xlo, g_Wvhi, g_Wvlo, g_xwv); }
__global__ void __launch_bounds__(256, 2) gemm_g_tc() { gemm_hmma_body(g_xhi, g_xlo, g_Wghi, g_Wglo, g_gate); }
__global__ void __launch_bounds__(256, 2) gemm_o_tc(float* __restrict__ out) {
    gemm_hmma_body(g_ahi, g_alo, g_Wohi, g_Wolo, out);
}

// ---------------- beta / decay small projections ------------------------------
__global__ void __launch_bounds__(256) proj_small(const float* __restrict__ x,
                                                  const float* __restrict__ Wb,
                                                  const float* __restrict__ Wa,
                                                  const float* __restrict__ dt_bias,
                                                  const float* __restrict__ A_log) {
    const int row = blockIdx.x;
    __shared__ float sx[D_];
    for (int i = threadIdx.x; i < D_; i += 256) sx[i] = x[(size_t)row * D_ + i];
    __syncthreads();
    const int w = threadIdx.x >> 5, lane = threadIdx.x & 31;
    const float* wb = Wb + w * D_;
    const float* wa = Wa + w * D_;
    float db = 0.f, da = 0.f;
    for (int k = lane; k < D_; k += 32) {
        float xv = sx[k];
        db = fmaf(xv, wb[k], db);
        da = fmaf(xv, wa[k], da);
    }
#pragma unroll
    for (int off = 16; off; off >>= 1) {
        db += __shfl_down_sync(0xffffffffu, db, off);
        da += __shfl_down_sync(0xffffffffu, da, off);
    }
    if (lane == 0) {
        g_beta[row * H_ + w] = 1.f / (1.f + expf(-db));
        float z = da + dt_bias[w];
        float sp = (z > 20.f) ? z : log1pf(expf(z));
        g_dec[row * H_ + w] = -expf(A_log[w]) * sp;
    }
}

// ---------------- causal depthwise conv + SiLU + beta --------------------------
__global__ void conv_silu(const float* __restrict__ conv_w, const float* __restrict__ conv_b) {
    long idx = (long)blockIdx.x * 256 + threadIdx.x;
    const int d = (int)(idx & (D_ - 1));
    const long bt = idx >> 10;
    const int t = (int)(bt & (T_ - 1));
    float acc = conv_b[d];
#pragma unroll
    for (int j = 0; j < 4; j++) {
        int tt = t + j - 3;
        if (tt >= 0) acc = fmaf(g_xwv[idx + (long)(j - 3) * D_], conv_w[d * 4 + j], acc);
    }
    float s = acc / (1.f + expf(-acc));
    g_v[idx] = s * g_beta[bt * H_ + (d >> 7)];
}

// ---------------- rk / wk per-head L2 norms ------------------------------------
__global__ void __launch_bounds__(128) norm_rw(const float* __restrict__ x) {
    const int bh = blockIdx.x;
    const int h = bh & 7;
    const long bt = (long)(bh >> 3);
    const int t = (int)(bt & (T_ - 1));
    const int k = threadIdx.x;
    float xv = x[bt * D_ + h * K_ + k];
    float xs = (t > 0) ? x[(bt - 1) * D_ + h * K_ + k] : 0.f;
    float s1 = xv * xv, s2 = xs * xs;
#pragma unroll
    for (int off = 16; off; off >>= 1) {
        s1 += __shfl_xor_sync(0xffffffffu, s1, off);
        s2 += __shfl_xor_sync(0xffffffffu, s2, off);
    }
    __shared__ float r1[4], r2[4];
    const int w = k >> 5, lane = k & 31;
    if (lane == 0) { r1[w] = s1; r2[w] = s2; }
    __syncthreads();
    float S1 = r1[0] + r1[1] + r1[2] + r1[3];
    float S2 = r2[0] + r2[1] + r2[2] + r2[3];
    g_rk[(long)bh * K_ + k] = xv * rsqrtf(S1 + 1e-6f) * 0.08838834764831845f;
    g_wk[(long)bh * K_ + k] = xs * rsqrtf(S2 + 1e-6f);
}

// ---------------- per-chunk: cumsum, A_strict, attn, triangular solve ------------
__global__ void __launch_bounds__(256) chunk_prep() {
    extern __shared__ float sm[];
    float* sA = sm;                 // 64*64
    float* s1 = sm + 4096;          // 64*RS
    float* s2 = s1 + C_ * RS;       // 64*RS
    __shared__ float sdec[C_], sbeta[C_], sraw[C_];
    const int id = blockIdx.x;
    const int chunk = id & 63;
    const int bh = id >> 6;
    const int b = bh >> 3, h = bh & 7;
    const long t0 = (long)b * T_ + chunk * C_;
    const long base = (t0 * H_ + h) * K_;
    const int tid = threadIdx.x;

    for (int i = tid; i < C_ * K_; i += 256) {
        int c = i >> 7, k = i & 127;
        s1[c * RS + k] = g_wk[base + (long)c * D_ + k];
        s2[c * RS + k] = g_rk[base + (long)c * D_ + k];
    }
    if (tid < C_) {
        sraw[tid] = g_dec[(t0 + tid) * H_ + h];
        sbeta[tid] = g_beta[(t0 + tid) * H_ + h];
    }
    __syncthreads();
    if (tid < C_) {
        float acc = 0.f;
        for (int j = 0; j <= tid; j++) acc += sraw[j];
        sdec[tid] = acc;
        g_dcum[(t0 + tid) * H_ + h] = acc;
    }
    __syncthreads();

    for (int p = tid; p < C_ * C_; p += 256) {
        int i = p >> 6, j = p & 63;
        float av = 0.f, atv = 0.f;
        if (j <= i) {
            const float* wi = s1 + i * RS;
            const float* wj = s1 + j * RS;
            const float* ri = s2 + i * RS;
            float dwk = 0.f, drk = 0.f;
#pragma unroll 4
            for (int k = 0; k < K_; k++) {
                float w = wj[k];
                dwk = fmaf(wi[k], w, dwk);
                drk = fmaf(ri[k], w, drk);
            }
            float l = __expf(sdec[i] - sdec[j]);
            atv = drk * l;
            if (j < i) av = -dwk * sbeta[i] * l;
        }
        g_attn[(long)id * 4096 + p] = atv;
        sA[p] = av;
    }
    __syncthreads();

    for (int i = tid; i < C_ * K_; i += 256) {
        int c = i >> 7, k = i & 127;
        s1[c * RS + k] *= sbeta[c] * __expf(sdec[c]);
        s2[c * RS + k] = g_v[base + (long)c * D_ + k];
    }
    __syncthreads();

    // forward substitution: halves handle s1 / s2 columns independently
    {
        float* sx = (tid < 128) ? s1 : s2;
        const int k = tid & 127;
        for (int i = 1; i < C_; i++) {
            float a1 = 0.f;
            const float* Ai = sA + i * 64;
#pragma unroll 4
            for (int j = 0; j < i; j++)
                a1 = fmaf(Ai[j], sx[j * RS + k], a1);
            sx[i * RS + k] += a1;
        }
    }
    __syncthreads();

    for (int i = tid; i < C_ * K_; i += 256) {
        int c = i >> 7, k = i & 127;
        g_wkc[base + (long)c * D_ + k] = s1[c * RS + k];
        g_v  [base + (long)c * D_ + k] = s2[c * RS + k];
    }
}

// ---------------- sequential chunk scan (512 threads, cp.async staging) ---------
__global__ void __launch_bounds__(512) scan_kernel() {
    extern __shared__ float sm[];
    float* sS    = sm;                       // 128*SSS
    float* srk   = sS + 128 * SSS;           // 64*SRS
    float* swk   = srk + C_ * SRS;
    float* swkc  = swk + C_ * SRS;
    float* sattn = swkc + C_ * SRS;          // 64*SAS
    float* sv    = sattn + C_ * SAS;         // 64*SVS
    __shared__ float sdec[C_], sdw[C_];
    const int bh = blockIdx.x >> 2;
    const int slice = blockIdx.x & 3;
    const int b = bh >> 3, h = bh & 7;
    const int j0g = slice * SW;
    const int tid = threadIdx.x;

    const uint32_t srk_s = smem_u32(srk), swk_s = smem_u32(swk), swkc_s = smem_u32(swkc);
    const uint32_t sattn_s = smem_u32(sattn), sv_s = smem_u32(sv);

    for (int i = tid; i < 128 * SSS; i += 512) sS[i] = 0.f;
    __syncthreads();

    for (int chunk = 0; chunk < NCH; chunk++) {
        const long t0 = (long)b * T_ + chunk * C_;
        const long base = (t0 * H_ + h) * K_;
        // stage tiles via cp.async
#pragma unroll
        for (int q = 0; q < 4; q++) {
            int u = tid + q * 512;           // 0..2047
            int row = u >> 5, seg = (u & 31) * 4;
            uint32_t soff = (row * SRS + seg) * 4;
            long goff = base + (long)row * D_ + seg;
            cpasync16(srk_s + soff, g_rk + goff);
            cpasync16(swk_s + soff, g_wk + goff);
            cpasync16(swkc_s + soff, g_wkc + goff);
        }
        {
            long ab = ((long)bh * NCH + chunk) * 4096;
#pragma unroll
            for (int q = 0; q < 2; q++) {
                int u = tid + q * 512;       // 0..1023
                int row = u >> 4, seg = (u & 15) * 4;
                cpasync16(sattn_s + (row * SAS + seg) * 4, g_attn + ab + row * 64 + seg);
            }
        }
#pragma unroll
        for (int q = 0; q < 4; q++) {
            int u = tid + q * 512;           // 0..2047
            int row = u >> 5, col = u & 31;
            cpasync4(sv_s + (row * SVS + col) * 4, g_v + base + (long)row * D_ + j0g + col);
        }
        CP_COMMIT();
        if (tid < C_) sdec[tid] = g_dcum[(t0 + tid) * H_ + h];
        CP_WAIT0();
        __syncthreads();
        if (tid < C_) sdw[tid] = __expf(sdec[63] - sdec[tid]);

        // v_new = v - wkc @ S
        {
            const int c = tid >> 3, j0 = (tid & 7) << 2;
            float acc[4];
            float* vp = sv + c * SVS + j0;
#pragma unroll
            for (int i = 0; i < 4; i++) acc[i] = vp[i];
            const float* wrow = swkc + c * SRS;
            for (int k = 0; k < K_; k++) {
                float w = wrow[k];
                const float* sp = sS + k * SSS + j0;
#pragma unroll
                for (int i = 0; i < 4; i++) acc[i] = fmaf(-w, sp[i], acc[i]);
            }
#pragma unroll
            for (int i = 0; i < 4; i++) vp[i] = acc[i];
        }
        __syncthreads();

        // o = exp(dec_c) * (rk @ S) + attn @ v_new
        {
            const int c = tid >> 3, j0 = (tid & 7) << 2;
            float acc[4] = {0.f, 0.f, 0.f, 0.f};
            const float* rrow = srk + c * SRS;
            for (int k = 0; k < K_; k++) {
                float r = rrow[k];
                const float* sp = sS + k * SSS + j0;
#pragma unroll
                for (int i = 0; i < 4; i++) acc[i] = fmaf(r, sp[i], acc[i]);
            }
            float ec = __expf(sdec[c]);
#pragma unroll
            for (int i = 0; i < 4; i++) acc[i] *= ec;
            const float* arow = sattn + c * SAS;
            for (int jj = 0; jj < C_; jj++) {
                float a = arow[jj];
                const float* vp = sv + jj * SVS + j0;
#pragma unroll
                for (int i = 0; i < 4; i++) acc[i] = fmaf(a, vp[i], acc[i]);
            }
            float* op = g_o + base + (long)c * D_ + j0g + j0;
#pragma unroll
            for (int i = 0; i < 4; i++) op[i] = acc[i];
        }
        __syncthreads();

        // S = S*exp(dec_63) + (wk * dw)^T @ v_new
        {
            const int k = tid >> 2, j0 = (tid & 3) << 3;
            float acc[8];
#pragma unroll
            for (int i = 0; i < 8; i++) acc[i] = 0.f;
            for (int c = 0; c < C_; c++) {
                float w = swk[c * SRS + k] * sdw[c];
                const float* vp = sv + c * SVS + j0;
#pragma unroll
                for (int i = 0; i < 8; i++) acc[i] = fmaf(w, vp[i], acc[i]);
            }
            float e63 = __expf(sdec[63]);
            float* sp = sS + k * SSS + j0;
#pragma unroll
            for (int i = 0; i < 8; i++) sp[i] = sp[i] * e63 + acc[i];
        }
        __syncthreads();
    }
}

// ---------------- per-head RMSNorm + gated SiLU (writes split bf16) --------------
__global__ void __launch_bounds__(128) rms_gate(const float* __restrict__ norm_w) {
    const int bhk = blockIdx.x;
    const int k = threadIdx.x;
    const long gi = (long)bhk * K_ + k;
    float ov = g_o[gi];
    float s = ov * ov;
#pragma unroll
    for (int off = 16; off; off >>= 1) s += __shfl_xor_sync(0xffffffffu, s, off);
    __shared__ float red[4];
    if ((k & 31) == 0) red[k >> 5] = s;
    __syncthreads();
    float tot = red[0] + red[1] + red[2] + red[3];
    float r = rsqrtf(tot * (1.f / 128.f) + 1e-5f);
    float g = g_gate[gi];
    float sg = g / (1.f + expf(-g));
    float val = ov * r * norm_w[k] * sg;
    __nv_bfloat16 hbv = __float2bfloat16(val);
    g_ahi[gi] = hbv;
    g_alo[gi] = __float2bfloat16(val - __bfloat162float(hbv));
}

// ---------------- launcher ------------------------------------------------------
extern "C" void kernel_launch(void* const* d_in, const int* in_sizes, int n_in,
                              void* d_out, int out_size) {
    const float* x       = (const float*)d_in[0];
    const float* Wv      = (const float*)d_in[1];
    const float* Wg      = (const float*)d_in[2];
    const float* Wo      = (const float*)d_in[3];
    const float* Wb      = (const float*)d_in[4];
    const float* Wa      = (const float*)d_in[5];
    const float* dt_bias = (const float*)d_in[6];
    const float* A_log   = (const float*)d_in[7];
    const float* norm_w  = (const float*)d_in[8];
    const float* conv_w  = (const float*)d_in[9];
    const float* conv_b  = (const float*)d_in[10];
    float* out = (float*)d_out;

    const int CP_SMEM   = (4096 + 2 * C_ * RS) * 4;
    const int SCAN_SMEM = (128 * SSS + 3 * C_ * SRS + C_ * SAS + C_ * SVS) * 4;
    const int GEMM_SMEM = 2 * STAGE_E * 2;   // 81920 B
    cudaFuncSetAttribute(chunk_prep,  cudaFuncAttributeMaxDynamicSharedMemorySize, CP_SMEM);
    cudaFuncSetAttribute(scan_kernel, cudaFuncAttributeMaxDynamicSharedMemorySize, SCAN_SMEM);
    cudaFuncSetAttribute(gemm_v_tc,   cudaFuncAttributeMaxDynamicSharedMemorySize, GEMM_SMEM);
    cudaFuncSetAttribute(gemm_g_tc,   cudaFuncAttributeMaxDynamicSharedMemorySize, GEMM_SMEM);
    cudaFuncSetAttribute(gemm_o_tc,   cudaFuncAttributeMaxDynamicSharedMemorySize, GEMM_SMEM);

    dim3 gg(D_ / 128, M_ / 128);

    split_x_k<<<(M_ * D_) / 1024, 256>>>(x);
    split_w_k<<<(3 * D_ * D_) / 1024, 256>>>(Wv, Wg, Wo);
    gemm_v_tc<<<gg, 256, GEMM_SMEM>>>();
    gemm_g_tc<<<gg, 256, GEMM_SMEM>>>();
    proj_small<<<M_, 256>>>(x, Wb, Wa, dt_bias, A_log);
    conv_silu<<<(B_ * T_ * D_) / 256, 256>>>(conv_w, conv_b);
    norm_rw<<<M_ * H_, 128>>>(x);
    chunk_prep<<<B_ * H_ * NCH, 256, CP_SMEM>>>();
    scan_kernel<<<B_ * H_ * SLICES, 512, SCAN_SMEM>>>();
    rms_gate<<<M_ * H_, 128>>>(norm_w);
    gemm_o_tc<<<gg, 256, GEMM_SMEM>>>(out);
}

// round 5
// speedup vs baseline: 2.6111x; 1.4806x over previous
#include <cuda_runtime.h>
#include <cuda_bf16.h>
#include <math.h>
#include <cstdint>

#define B_ 4
#define T_ 4096
#define D_ 1024
#define H_ 8
#define K_ 128
#define C_ 64
#define NCH 64
#define M_ (B_*T_)
#define RS 129
#define SLICES 4
#define SW 32
#define GSTR 40           // bf16 smem stride for GEMM tiles

// ---------------- scratch -------------------------------------------------------
__device__ float g_xwv [B_*T_*D_];
__device__ float g_gate[B_*T_*D_];
__device__ float g_v   [B_*T_*D_];
__device__ float g_rk  [B_*T_*D_];
__device__ float g_wk  [B_*T_*D_];
__device__ float g_o   [B_*T_*D_];
__device__ float g_beta[B_*T_*H_];
__device__ float g_dec [B_*T_*H_];
__device__ float g_dcum[B_*T_*H_];
__device__ __nv_bfloat16 g_attn_h[B_*H_*NCH*C_*C_], g_attn_l[B_*H_*NCH*C_*C_];
__device__ __nv_bfloat16 g_rk_h [M_*D_], g_rk_l [M_*D_];
__device__ __nv_bfloat16 g_wk_h [M_*D_], g_wk_l [M_*D_];
__device__ __nv_bfloat16 g_wkc_h[M_*D_], g_wkc_l[M_*D_];
__device__ __nv_bfloat16 g_xhi[M_*D_], g_xlo[M_*D_];
__device__ __nv_bfloat16 g_ahi[M_*D_], g_alo[M_*D_];
__device__ __nv_bfloat16 g_Wvhi[D_*D_], g_Wvlo[D_*D_];
__device__ __nv_bfloat16 g_Wghi[D_*D_], g_Wglo[D_*D_];
__device__ __nv_bfloat16 g_Wohi[D_*D_], g_Wolo[D_*D_];

// ================= low-level helpers ===========================================
__device__ __forceinline__ uint32_t smem_u32(const void* p) {
    uint32_t a;
    asm("{ .reg .u64 t; cvta.to.shared.u64 t, %1; cvt.u32.u64 %0, t; }" : "=r"(a) : "l"(p));
    return a;
}
__device__ __forceinline__ void cpasync16(uint32_t saddr, const void* gaddr) {
    asm volatile("cp.async.cg.shared.global [%0], [%1], 16;" :: "r"(saddr), "l"(gaddr));
}
#define CP_COMMIT() asm volatile("cp.async.commit_group;" ::: "memory")
#define CP_WAIT0()  asm volatile("cp.async.wait_group 0;" ::: "memory")

__device__ __forceinline__ void ldsm4(uint32_t* r, uint32_t saddr) {
    asm volatile("ldmatrix.sync.aligned.m8n8.x4.shared.b16 {%0,%1,%2,%3}, [%4];"
        : "=r"(r[0]), "=r"(r[1]), "=r"(r[2]), "=r"(r[3]) : "r"(saddr));
}
__device__ __forceinline__ void ldsm4t(uint32_t* r, uint32_t saddr) {
    asm volatile("ldmatrix.sync.aligned.m8n8.x4.trans.shared.b16 {%0,%1,%2,%3}, [%4];"
        : "=r"(r[0]), "=r"(r[1]), "=r"(r[2]), "=r"(r[3]) : "r"(saddr));
}
__device__ __forceinline__ void mma16816(float* c, const uint32_t* a, uint32_t b0, uint32_t b1) {
    asm volatile(
        "mma.sync.aligned.m16n8k16.row.col.f32.bf16.bf16.f32 "
        "{%0,%1,%2,%3}, {%4,%5,%6,%7}, {%8,%9}, {%0,%1,%2,%3};"
        : "+f"(c[0]), "+f"(c[1]), "+f"(c[2]), "+f"(c[3])
        : "r"(a[0]), "r"(a[1]), "r"(a[2]), "r"(a[3]), "r"(b0), "r"(b1));
}
__device__ __forceinline__ void bfsplit(float v, __nv_bfloat16& h, __nv_bfloat16& l) {
    h = __float2bfloat16(v);
    l = __float2bfloat16(v - __bfloat162float(h));
}

// ================= split-bf16 conversion ========================================
__device__ __forceinline__ void split4(const float* __restrict__ src,
                                       __nv_bfloat16* __restrict__ hi,
                                       __nv_bfloat16* __restrict__ lo, long i) {
    float4 v = *reinterpret_cast<const float4*>(src + i);
    __nv_bfloat16 h0, h1, h2, h3, l0, l1, l2, l3;
    bfsplit(v.x, h0, l0); bfsplit(v.y, h1, l1);
    bfsplit(v.z, h2, l2); bfsplit(v.w, h3, l3);
    *reinterpret_cast<__nv_bfloat162*>(hi + i)     = __nv_bfloat162(h0, h1);
    *reinterpret_cast<__nv_bfloat162*>(hi + i + 2) = __nv_bfloat162(h2, h3);
    *reinterpret_cast<__nv_bfloat162*>(lo + i)     = __nv_bfloat162(l0, l1);
    *reinterpret_cast<__nv_bfloat162*>(lo + i + 2) = __nv_bfloat162(l2, l3);
}
__global__ void __launch_bounds__(256) split_x_k(const float* __restrict__ x) {
    long i = ((long)blockIdx.x * 256 + threadIdx.x) * 4;
    split4(x, g_xhi, g_xlo, i);
}
__global__ void __launch_bounds__(256) split_w_k(const float* __restrict__ Wv,
                                                 const float* __restrict__ Wg,
                                                 const float* __restrict__ Wo) {
    long i = ((long)blockIdx.x * 256 + threadIdx.x) * 4;
    if (i < 1048576)            split4(Wv, g_Wvhi, g_Wvlo, i);
    else if (i < 2097152)       split4(Wg, g_Wghi, g_Wglo, i - 1048576);
    else                        split4(Wo, g_Wohi, g_Wolo, i - 2097152);
}

// ================= HMMA split-bf16 GEMM (unchanged from R4) =====================
#define TILE_E (128 * GSTR)
#define STAGE_E (4 * TILE_E)
__device__ __forceinline__ void gemm_hmma_body(
    const __nv_bfloat16* __restrict__ Ahi, const __nv_bfloat16* __restrict__ Alo,
    const __nv_bfloat16* __restrict__ Bhi, const __nv_bfloat16* __restrict__ Blo,
    float* __restrict__ Cm) {
    extern __shared__ __nv_bfloat16 dsm[];
    const int tid = threadIdx.x;
    const int wid = tid >> 5, lane = tid & 31;
    const int wm = wid & 1;
    const int wn = wid >> 1;
    const int m0 = blockIdx.y * 128;
    const int n0 = blockIdx.x * 128;

    float acc[4][4][4];
#pragma unroll
    for (int mt = 0; mt < 4; mt++)
#pragma unroll
        for (int nt = 0; nt < 4; nt++)
#pragma unroll
            for (int q = 0; q < 4; q++) acc[mt][nt][q] = 0.f;

    const int lrow = tid >> 2, lseg = (tid & 3) * 8;

    const __nv_bfloat16* gp[4];
    gp[0] = Ahi + (size_t)m0 * 1024;
    gp[1] = Alo + (size_t)m0 * 1024;
    gp[2] = Bhi + (size_t)n0 * 1024;
    gp[3] = Blo + (size_t)n0 * 1024;

    auto load_chunk = [&](int kc, int buf) {
#pragma unroll
        for (int t = 0; t < 4; t++) {
            const __nv_bfloat16* g = gp[t] + kc * 32;
            uint32_t s = smem_u32(&dsm[buf * STAGE_E + t * TILE_E]);
            cpasync16(s + (lrow * GSTR + lseg) * 2, g + (size_t)lrow * 1024 + lseg);
            cpasync16(s + ((lrow + 64) * GSTR + lseg) * 2, g + (size_t)(lrow + 64) * 1024 + lseg);
        }
        CP_COMMIT();
    };

    const int r8 = lane & 7, sel = lane >> 3;

    load_chunk(0, 0);
    for (int kc = 0; kc < 32; kc++) {
        CP_WAIT0();
        __syncthreads();
        if (kc + 1 < 32) load_chunk(kc + 1, (kc + 1) & 1);
        const int buf = kc & 1;
        const uint32_t sAhi = smem_u32(&dsm[buf * STAGE_E + 0 * TILE_E]);
        const uint32_t sAlo = sAhi + TILE_E * 2;
        const uint32_t sBhi = sAhi + 2 * TILE_E * 2;
        const uint32_t sBlo = sAhi + 3 * TILE_E * 2;
#pragma unroll
        for (int ks = 0; ks < 2; ks++) {
            const int k16 = ks * 16;
            const int acol = k16 + (sel >> 1) * 8;
            const int bcol = k16 + (sel & 1) * 8;
            uint32_t ah[4][4], al[4][4], bb[2][4];
#pragma unroll
            for (int mt = 0; mt < 4; mt++) {
                int row = wm * 64 + mt * 16 + (sel & 1) * 8 + r8;
                ldsm4(ah[mt], sAhi + (row * GSTR + acol) * 2);
                ldsm4(al[mt], sAlo + (row * GSTR + acol) * 2);
            }
#pragma unroll
            for (int bt = 0; bt < 2; bt++) {
                int nrow = wn * 32 + bt * 16 + (sel >> 1) * 8 + r8;
                ldsm4(bb[bt], sBhi + (nrow * GSTR + bcol) * 2);
            }
#pragma unroll
            for (int mt = 0; mt < 4; mt++)
#pragma unroll
                for (int nt = 0; nt < 4; nt++) {
                    mma16816(acc[mt][nt], ah[mt], bb[nt >> 1][(nt & 1) * 2], bb[nt >> 1][(nt & 1) * 2 + 1]);
                    mma16816(acc[mt][nt], al[mt], bb[nt >> 1][(nt & 1) * 2], bb[nt >> 1][(nt & 1) * 2 + 1]);
                }
#pragma unroll
            for (int bt = 0; bt < 2; bt++) {
                int nrow = wn * 32 + bt * 16 + (sel >> 1) * 8 + r8;
                ldsm4(bb[bt], sBlo + (nrow * GSTR + bcol) * 2);
            }
#pragma unroll
            for (int mt = 0; mt < 4; mt++)
#pragma unroll
                for (int nt = 0; nt < 4; nt++)
                    mma16816(acc[mt][nt], ah[mt], bb[nt >> 1][(nt & 1) * 2], bb[nt >> 1][(nt & 1) * 2 + 1]);
        }
        __syncthreads();
    }

    const int erow = lane >> 2, ecol = (lane & 3) * 2;
#pragma unroll
    for (int mt = 0; mt < 4; mt++) {
        const size_t row0 = (size_t)(m0 + wm * 64 + mt * 16 + erow);
#pragma unroll
        for (int nt = 0; nt < 4; nt++) {
            const size_t cb = (size_t)(n0 + wn * 32 + nt * 8 + ecol);
            *reinterpret_cast<float2*>(Cm + row0 * 1024 + cb) =
                make_float2(acc[mt][nt][0], acc[mt][nt][1]);
            *reinterpret_cast<float2*>(Cm + (row0 + 8) * 1024 + cb) =
                make_float2(acc[mt][nt][2], acc[mt][nt][3]);
        }
    }
}

__global__ void __launch_bounds__(256, 2) gemm_v_tc() { gemm_hmma_body(g_xhi, g_xlo, g_Wvhi, g_Wvlo, g_xwv); }
__global__ void __launch_bounds__(256, 2) gemm_g_tc() { gemm_hmma_body(g_xhi, g_xlo, g_Wghi, g_Wglo, g_gate); }
__global__ void __launch_bounds__(256, 2) gemm_o_tc(float* __restrict__ out) {
    gemm_hmma_body(g_ahi, g_alo, g_Wohi, g_Wolo, out);
}

// ---------------- beta / decay small projections ------------------------------
__global__ void __launch_bounds__(256) proj_small(const float* __restrict__ x,
                                                  const float* __restrict__ Wb,
                                                  const float* __restrict__ Wa,
                                                  const float* __restrict__ dt_bias,
                                                  const float* __restrict__ A_log) {
    const int row = blockIdx.x;
    __shared__ float sx[D_];
    for (int i = threadIdx.x; i < D_; i += 256) sx[i] = x[(size_t)row * D_ + i];
    __syncthreads();
    const int w = threadIdx.x >> 5, lane = threadIdx.x & 31;
    const float* wb = Wb + w * D_;
    const float* wa = Wa + w * D_;
    float db = 0.f, da = 0.f;
    for (int k = lane; k < D_; k += 32) {
        float xv = sx[k];
        db = fmaf(xv, wb[k], db);
        da = fmaf(xv, wa[k], da);
    }
#pragma unroll
    for (int off = 16; off; off >>= 1) {
        db += __shfl_down_sync(0xffffffffu, db, off);
        da += __shfl_down_sync(0xffffffffu, da, off);
    }
    if (lane == 0) {
        g_beta[row * H_ + w] = 1.f / (1.f + expf(-db));
        float z = da + dt_bias[w];
        float sp = (z > 20.f) ? z : log1pf(expf(z));
        g_dec[row * H_ + w] = -expf(A_log[w]) * sp;
    }
}

// ---------------- causal depthwise conv + SiLU + beta --------------------------
__global__ void conv_silu(const float* __restrict__ conv_w, const float* __restrict__ conv_b) {
    long idx = (long)blockIdx.x * 256 + threadIdx.x;
    const int d = (int)(idx & (D_ - 1));
    const long bt = idx >> 10;
    const int t = (int)(bt & (T_ - 1));
    float acc = conv_b[d];
#pragma unroll
    for (int j = 0; j < 4; j++) {
        int tt = t + j - 3;
        if (tt >= 0) acc = fmaf(g_xwv[idx + (long)(j - 3) * D_], conv_w[d * 4 + j], acc);
    }
    float s = acc / (1.f + expf(-acc));
    g_v[idx] = s * g_beta[bt * H_ + (d >> 7)];
}

// ---------------- rk / wk per-head L2 norms (also writes bf16 splits) ----------
__global__ void __launch_bounds__(128) norm_rw(const float* __restrict__ x) {
    const int bh = blockIdx.x;
    const int h = bh & 7;
    const long bt = (long)(bh >> 3);
    const int t = (int)(bt & (T_ - 1));
    const int k = threadIdx.x;
    float xv = x[bt * D_ + h * K_ + k];
    float xs = (t > 0) ? x[(bt - 1) * D_ + h * K_ + k] : 0.f;
    float s1 = xv * xv, s2 = xs * xs;
#pragma unroll
    for (int off = 16; off; off >>= 1) {
        s1 += __shfl_xor_sync(0xffffffffu, s1, off);
        s2 += __shfl_xor_sync(0xffffffffu, s2, off);
    }
    __shared__ float r1[4], r2[4];
    const int w = k >> 5, lane = k & 31;
    if (lane == 0) { r1[w] = s1; r2[w] = s2; }
    __syncthreads();
    float S1 = r1[0] + r1[1] + r1[2] + r1[3];
    float S2 = r2[0] + r2[1] + r2[2] + r2[3];
    float rkv = xv * rsqrtf(S1 + 1e-6f) * 0.08838834764831845f;
    float wkv = xs * rsqrtf(S2 + 1e-6f);
    const long gi = (long)bh * K_ + k;
    g_rk[gi] = rkv;
    g_wk[gi] = wkv;
    __nv_bfloat16 hh, ll;
    bfsplit(rkv, hh, ll); g_rk_h[gi] = hh; g_rk_l[gi] = ll;
    bfsplit(wkv, hh, ll); g_wk_h[gi] = hh; g_wk_l[gi] = ll;
}

// ---------------- per-chunk: cumsum, A_strict, attn(bf16), solve ----------------
__global__ void __launch_bounds__(256) chunk_prep() {
    extern __shared__ float sm[];
    float* sA = sm;                 // 64*64
    float* s1 = sm + 4096;          // 64*RS
    float* s2 = s1 + C_ * RS;       // 64*RS
    __shared__ float sdec[C_], sbeta[C_], sraw[C_];
    const int id = blockIdx.x;
    const int chunk = id & 63;
    const int bh = id >> 6;
    const int b = bh >> 3, h = bh & 7;
    const long t0 = (long)b * T_ + chunk * C_;
    const long base = (t0 * H_ + h) * K_;
    const int tid = threadIdx.x;

    for (int i = tid; i < C_ * K_; i += 256) {
        int c = i >> 7, k = i & 127;
        s1[c * RS + k] = g_wk[base + (long)c * D_ + k];
        s2[c * RS + k] = g_rk[base + (long)c * D_ + k];
    }
    if (tid < C_) {
        sraw[tid] = g_dec[(t0 + tid) * H_ + h];
        sbeta[tid] = g_beta[(t0 + tid) * H_ + h];
    }
    __syncthreads();
    if (tid < C_) {
        float acc = 0.f;
        for (int j = 0; j <= tid; j++) acc += sraw[j];
        sdec[tid] = acc;
        g_dcum[(t0 + tid) * H_ + h] = acc;
    }
    __syncthreads();

    for (int p = tid; p < C_ * C_; p += 256) {
        int i = p >> 6, j = p & 63;
        float av = 0.f, atv = 0.f;
        if (j <= i) {
            const float* wi = s1 + i * RS;
            const float* wj = s1 + j * RS;
            const float* ri = s2 + i * RS;
            float dwk = 0.f, drk = 0.f;
#pragma unroll 4
            for (int k = 0; k < K_; k++) {
                float w = wj[k];
                dwk = fmaf(wi[k], w, dwk);
                drk = fmaf(ri[k], w, drk);
            }
            float l = __expf(sdec[i] - sdec[j]);
            atv = drk * l;
            if (j < i) av = -dwk * sbeta[i] * l;
        }
        __nv_bfloat16 hh, ll;
        bfsplit(atv, hh, ll);
        g_attn_h[(long)id * 4096 + p] = hh;
        g_attn_l[(long)id * 4096 + p] = ll;
        sA[p] = av;
    }
    __syncthreads();

    for (int i = tid; i < C_ * K_; i += 256) {
        int c = i >> 7, k = i & 127;
        s1[c * RS + k] *= sbeta[c] * __expf(sdec[c]);
        s2[c * RS + k] = g_v[base + (long)c * D_ + k];
    }
    __syncthreads();

    {
        float* sx = (tid < 128) ? s1 : s2;
        const int k = tid & 127;
        for (int i = 1; i < C_; i++) {
            float a1 = 0.f;
            const float* Ai = sA + i * 64;
#pragma unroll 4
            for (int j = 0; j < i; j++)
                a1 = fmaf(Ai[j], sx[j * RS + k], a1);
            sx[i * RS + k] += a1;
        }
    }
    __syncthreads();

    for (int i = tid; i < C_ * K_; i += 256) {
        int c = i >> 7, k = i & 127;
        float u = s1[c * RS + k];
        __nv_bfloat16 hh, ll;
        bfsplit(u, hh, ll);
        g_wkc_h[base + (long)c * D_ + k] = hh;
        g_wkc_l[base + (long)c * D_ + k] = ll;
        g_v[base + (long)c * D_ + k] = s2[c * RS + k];
    }
}

// ---------------- HMMA chunk scan -----------------------------------------------
// smem strides (elements)
#define SSF 33     // sS fp32 128x33
#define SHS 56     // Shi/Slo, svh/svl, sv2h/l bf16 (rows 112B, 16B-aligned, conflict-free)
#define SAB 136    // sA / swk bf16 (rows 272B)
#define STB 72     // attn bf16 (rows 144B)
#define SVF 36     // sv fp32 (rows 144B, cp.async-aligned)

__global__ void __launch_bounds__(256) scan_kernel() {
    extern __shared__ char smraw[];
    float* sS = (float*)smraw;                                     // 16896 B
    __nv_bfloat16* sShi = (__nv_bfloat16*)(smraw + 16896);         // 128*56
    __nv_bfloat16* sSlo = sShi + 128 * SHS;
    __nv_bfloat16* sAh  = sSlo + 128 * SHS;                        // 128*136
    __nv_bfloat16* sAl  = sAh + 128 * SAB;
    __nv_bfloat16* sWh  = sAl + 128 * SAB;                         // 64*136
    __nv_bfloat16* sWl  = sWh + 64 * SAB;
    __nv_bfloat16* sTh  = sWl + 64 * SAB;                          // 64*72
    __nv_bfloat16* sTl  = sTh + 64 * STB;
    __nv_bfloat16* svh  = sTl + 64 * STB;                          // 64*56
    __nv_bfloat16* svl  = svh + 64 * SHS;
    __nv_bfloat16* s2h  = svl + 64 * SHS;
    __nv_bfloat16* s2l  = s2h + 64 * SHS;
    float* sv = (float*)(s2l + 64 * SHS);                          // 64*36 fp32
    __shared__ float sdec[C_], sdw[C_];

    const int bh = blockIdx.x >> 2;
    const int slice = blockIdx.x & 3;
    const int b = bh >> 3, h = bh & 7;
    const int j0g = slice * SW;
    const int tid = threadIdx.x;
    const int wid = tid >> 5, lane = tid & 31;
    const int g8 = lane >> 3, r8 = lane & 7;
    const int aro = (g8 & 1) * 8 + r8;     // standard A row offset
    const int aco = (g8 >> 1) * 8;         // standard A col offset
    const int bro = (g8 & 1) * 8 + r8;     // trans-B k-row offset
    const int bco = (g8 >> 1) * 8;         // trans-B n-col offset
    const int tro = (g8 >> 1) * 8 + r8;    // trans-A c-row offset
    const int tco = (g8 & 1) * 8;          // trans-A m-col offset
    const int er = lane >> 2, ec = (lane & 3) * 2;

    const uint32_t sShi_s = smem_u32(sShi), sSlo_s = smem_u32(sSlo);
    const uint32_t sAh_s = smem_u32(sAh), sAl_s = smem_u32(sAl);
    const uint32_t sWh_s = smem_u32(sWh), sWl_s = smem_u32(sWl);
    const uint32_t sTh_s = smem_u32(sTh), sTl_s = smem_u32(sTl);
    const uint32_t svh_s = smem_u32(svh), svl_s = smem_u32(svl);
    const uint32_t s2h_s = smem_u32(s2h), s2l_s = smem_u32(s2l);
    const uint32_t sv_s = smem_u32(sv);

    auto issue_loads = [&](int chunk) {
        const long t0 = (long)b * T_ + chunk * C_;
        const long base = t0 * D_ + h * K_;
#pragma unroll
        for (int q = 0; q < 8; q++) {
            int u = tid + q * 256;              // 0..2047
            int row = u >> 4, seg = (u & 15) * 8;
            uint32_t d = (uint32_t)(row * SAB + seg) * 2;
            if (row < 64) {
                long g = base + (long)row * D_ + seg;
                cpasync16(sAh_s + d, g_wkc_h + g);
                cpasync16(sAl_s + d, g_wkc_l + g);
            } else {
                long g = base + (long)(row - 64) * D_ + seg;
                cpasync16(sAh_s + d, g_rk_h + g);
                cpasync16(sAl_s + d, g_rk_l + g);
            }
        }
#pragma unroll
        for (int q = 0; q < 4; q++) {
            int u = tid + q * 256;              // 0..1023
            int row = u >> 4, seg = (u & 15) * 8;
            uint32_t d = (uint32_t)(row * SAB + seg) * 2;
            long g = base + (long)row * D_ + seg;
            cpasync16(sWh_s + d, g_wk_h + g);
            cpasync16(sWl_s + d, g_wk_l + g);
        }
#pragma unroll
        for (int q = 0; q < 2; q++) {
            int u = tid + q * 256;              // 0..511
            int row = u >> 3, seg = (u & 7) * 8;
            uint32_t d = (uint32_t)(row * STB + seg) * 2;
            long g = ((long)bh * NCH + chunk) * 4096 + row * 64 + seg;
            cpasync16(sTh_s + d, g_attn_h + g);
            cpasync16(sTl_s + d, g_attn_l + g);
        }
#pragma unroll
        for (int q = 0; q < 2; q++) {
            int u = tid + q * 256;              // 0..511
            int row = u >> 3, seg = (u & 7) * 4;
            cpasync16(sv_s + (uint32_t)(row * SVF + seg) * 4,
                      g_v + base + (long)row * D_ + j0g + seg);
        }
        CP_COMMIT();
    };

    for (int i = tid; i < 128 * SSF; i += 256) sS[i] = 0.f;
    issue_loads(0);

    const int m0 = wid * 16;

    for (int chunk = 0; chunk < NCH; chunk++) {
        const long t0 = (long)b * T_ + chunk * C_;
        const long obase = t0 * D_ + h * K_;
        CP_WAIT0();
        if (tid < C_) sdec[tid] = g_dcum[(t0 + tid) * H_ + h];
        __syncthreads();

        // convert S -> bf16 hi/lo; compute dw
#pragma unroll
        for (int i = 0; i < 16; i++) {
            int idx = tid + i * 256;
            int row = idx >> 5, col = idx & 31;
            float vS = sS[row * SSF + col];
            __nv_bfloat16 hh, ll;
            bfsplit(vS, hh, ll);
            sShi[row * SHS + col] = hh;
            sSlo[row * SHS + col] = ll;
        }
        if (tid < C_) sdw[tid] = __expf(sdec[63] - sdec[tid]);
        __syncthreads();

        // ---- HMMA1: P(128x32) = [wkc; rk] @ S, 3-pass split ----
        float acc[4][4];
#pragma unroll
        for (int nt = 0; nt < 4; nt++)
#pragma unroll
            for (int q = 0; q < 4; q++) acc[nt][q] = 0.f;
#pragma unroll
        for (int ks = 0; ks < 8; ks++) {
            uint32_t ah[4], al[4], bhf[2][4], blf[2][4];
            uint32_t aoff = (uint32_t)((m0 + aro) * SAB + ks * 16 + aco) * 2;
            ldsm4(ah, sAh_s + aoff);
            ldsm4(al, sAl_s + aoff);
#pragma unroll
            for (int nh = 0; nh < 2; nh++) {
                uint32_t boff = (uint32_t)((ks * 16 + bro) * SHS + nh * 16 + bco) * 2;
                ldsm4t(bhf[nh], sShi_s + boff);
                ldsm4t(blf[nh], sSlo_s + boff);
            }
#pragma unroll
            for (int nt = 0; nt < 4; nt++) {
                uint32_t b0h = bhf[nt >> 1][(nt & 1) * 2], b1h = bhf[nt >> 1][(nt & 1) * 2 + 1];
                uint32_t b0l = blf[nt >> 1][(nt & 1) * 2], b1l = blf[nt >> 1][(nt & 1) * 2 + 1];
                mma16816(acc[nt], ah, b0h, b1h);
                mma16816(acc[nt], al, b0h, b1h);
                mma16816(acc[nt], ah, b0l, b1l);
            }
        }

        // ---- epilogue 1 ----
        if (wid < 4) {
            const int c1 = m0 + er, c2 = c1 + 8;
            const float dw1 = sdw[c1], dw2 = sdw[c2];
#pragma unroll
            for (int nt = 0; nt < 4; nt++) {
                const int col = nt * 8 + ec;
                float a0 = sv[c1 * SVF + col]     - acc[nt][0];
                float a1 = sv[c1 * SVF + col + 1] - acc[nt][1];
                float a2 = sv[c2 * SVF + col]     - acc[nt][2];
                float a3 = sv[c2 * SVF + col + 1] - acc[nt][3];
                __nv_bfloat16 h0, l0, h1, l1, h2, l2, h3, l3;
                bfsplit(a0, h0, l0); bfsplit(a1, h1, l1);
                bfsplit(a2, h2, l2); bfsplit(a3, h3, l3);
                *reinterpret_cast<__nv_bfloat162*>(svh + c1 * SHS + col) = __nv_bfloat162(h0, h1);
                *reinterpret_cast<__nv_bfloat162*>(svl + c1 * SHS + col) = __nv_bfloat162(l0, l1);
                *reinterpret_cast<__nv_bfloat162*>(svh + c2 * SHS + col) = __nv_bfloat162(h2, h3);
                *reinterpret_cast<__nv_bfloat162*>(svl + c2 * SHS + col) = __nv_bfloat162(l2, l3);
                float b0 = dw1 * a0, b1 = dw1 * a1, b2 = dw2 * a2, b3 = dw2 * a3;
                bfsplit(b0, h0, l0); bfsplit(b1, h1, l1);
                bfsplit(b2, h2, l2); bfsplit(b3, h3, l3);
                *reinterpret_cast<__nv_bfloat162*>(s2h + c1 * SHS + col) = __nv_bfloat162(h0, h1);
                *reinterpret_cast<__nv_bfloat162*>(s2l + c1 * SHS + col) = __nv_bfloat162(l0, l1);
                *reinterpret_cast<__nv_bfloat162*>(s2h + c2 * SHS + col) = __nv_bfloat162(h2, h3);
                *reinterpret_cast<__nv_bfloat162*>(s2l + c2 * SHS + col) = __nv_bfloat162(l2, l3);
            }
        } else {
            const int c1 = m0 - 64 + er, c2 = c1 + 8;
            const float e1 = __expf(sdec[c1]), e2 = __expf(sdec[c2]);
#pragma unroll
            for (int nt = 0; nt < 4; nt++) {
                acc[nt][0] *= e1; acc[nt][1] *= e1;
                acc[nt][2] *= e2; acc[nt][3] *= e2;
            }
        }
        __syncthreads();

        if (wid >= 4) {
            // ---- o = e*rkS (in acc) + attn @ v_new ----
            const int m0o = (wid - 4) * 16;
#pragma unroll
            for (int ks = 0; ks < 4; ks++) {
                uint32_t ah[4], al[4], bhf[2][4], blf[2][4];
                uint32_t aoff = (uint32_t)((m0o + aro) * STB + ks * 16 + aco) * 2;
                ldsm4(ah, sTh_s + aoff);
                ldsm4(al, sTl_s + aoff);
#pragma unroll
                for (int nh = 0; nh < 2; nh++) {
                    uint32_t boff = (uint32_t)((ks * 16 + bro) * SHS + nh * 16 + bco) * 2;
                    ldsm4t(bhf[nh], svh_s + boff);
                    ldsm4t(blf[nh], svl_s + boff);
                }
#pragma unroll
                for (int nt = 0; nt < 4; nt++) {
                    uint32_t b0h = bhf[nt >> 1][(nt & 1) * 2], b1h = bhf[nt >> 1][(nt & 1) * 2 + 1];
                    uint32_t b0l = blf[nt >> 1][(nt & 1) * 2], b1l = blf[nt >> 1][(nt & 1) * 2 + 1];
                    mma16816(acc[nt], ah, b0h, b1h);
                    mma16816(acc[nt], al, b0h, b1h);
                    mma16816(acc[nt], ah, b0l, b1l);
                }
            }
            const int c1 = m0o + er, c2 = c1 + 8;
#pragma unroll
            for (int nt = 0; nt < 4; nt++) {
                const int col = nt * 8 + ec;
                *reinterpret_cast<float2*>(g_o + obase + (long)c1 * D_ + j0g + col) =
                    make_float2(acc[nt][0], acc[nt][1]);
                *reinterpret_cast<float2*>(g_o + obase + (long)c2 * D_ + j0g + col) =
                    make_float2(acc[nt][2], acc[nt][3]);
            }
        } else {
            // ---- S = e63*S + wk^T @ (dw*v_new) ----
            const float e63 = __expf(sdec[63]);
#pragma unroll
            for (int mt = 0; mt < 2; mt++) {
                const int m0s = wid * 32 + mt * 16;
                float a2c[4][4];
#pragma unroll
                for (int nt = 0; nt < 4; nt++)
#pragma unroll
                    for (int q = 0; q < 4; q++) a2c[nt][q] = 0.f;
#pragma unroll
                for (int ks = 0; ks < 4; ks++) {
                    uint32_t ah[4], al[4], bhf[2][4], blf[2][4];
                    uint32_t aoff = (uint32_t)((ks * 16 + tro) * SAB + m0s + tco) * 2;
                    ldsm4t(ah, sWh_s + aoff);
                    ldsm4t(al, sWl_s + aoff);
#pragma unroll
                    for (int nh = 0; nh < 2; nh++) {
                        uint32_t boff = (uint32_t)((ks * 16 + bro) * SHS + nh * 16 + bco) * 2;
                        ldsm4t(bhf[nh], s2h_s + boff);
                        ldsm4t(blf[nh], s2l_s + boff);
                    }
#pragma unroll
                    for (int nt = 0; nt < 4; nt++) {
                        uint32_t b0h = bhf[nt >> 1][(nt & 1) * 2], b1h = bhf[nt >> 1][(nt & 1) * 2 + 1];
                        uint32_t b0l = blf[nt >> 1][(nt & 1) * 2], b1l = blf[nt >> 1][(nt & 1) * 2 + 1];
                        mma16816(a2c[nt], ah, b0h, b1h);
                        mma16816(a2c[nt], al, b0h, b1h);
                        mma16816(a2c[nt], ah, b0l, b1l);
                    }
                }
                const int k1 = m0s + er, k2 = k1 + 8;
#pragma unroll
                for (int nt = 0; nt < 4; nt++) {
                    const int col = nt * 8 + ec;
                    sS[k1 * SSF + col]     = sS[k1 * SSF + col]     * e63 + a2c[nt][0];
                    sS[k1 * SSF + col + 1] = sS[k1 * SSF + col + 1] * e63 + a2c[nt][1];
                    sS[k2 * SSF + col]     = sS[k2 * SSF + col]     * e63 + a2c[nt][2];
                    sS[k2 * SSF + col + 1] = sS[k2 * SSF + col + 1] * e63 + a2c[nt][3];
                }
            }
        }
        __syncthreads();
        if (chunk + 1 < NCH) issue_loads(chunk + 1);
    }
}

// ---------------- per-head RMSNorm + gated SiLU (writes split bf16) --------------
__global__ void __launch_bounds__(128) rms_gate(const float* __restrict__ norm_w) {
    const int bhk = blockIdx.x;
    const int k = threadIdx.x;
    const long gi = (long)bhk * K_ + k;
    float ov = g_o[gi];
    float s = ov * ov;
#pragma unroll
    for (int off = 16; off; off >>= 1) s += __shfl_xor_sync(0xffffffffu, s, off);
    __shared__ float red[4];
    if ((k & 31) == 0) red[k >> 5] = s;
    __syncthreads();
    float tot = red[0] + red[1] + red[2] + red[3];
    float r = rsqrtf(tot * (1.f / 128.f) + 1e-5f);
    float g = g_gate[gi];
    float sg = g / (1.f + expf(-g));
    float val = ov * r * norm_w[k] * sg;
    __nv_bfloat16 hh, ll;
    bfsplit(val, hh, ll);
    g_ahi[gi] = hh;
    g_alo[gi] = ll;
}

// ---------------- launcher ------------------------------------------------------
extern "C" void kernel_launch(void* const* d_in, const int* in_sizes, int n_in,
                              void* d_out, int out_size) {
    const float* x       = (const float*)d_in[0];
    const float* Wv      = (const float*)d_in[1];
    const float* Wg      = (const float*)d_in[2];
    const float* Wo      = (const float*)d_in[3];
    const float* Wb      = (const float*)d_in[4];
    const float* Wa      = (const float*)d_in[5];
    const float* dt_bias = (const float*)d_in[6];
    const float* A_log   = (const float*)d_in[7];
    const float* norm_w  = (const float*)d_in[8];
    const float* conv_w  = (const float*)d_in[9];
    const float* conv_b  = (const float*)d_in[10];
    float* out = (float*)d_out;

    const int CP_SMEM   = (4096 + 2 * C_ * RS) * 4;
    const int SCAN_SMEM = 16896 + (2 * 128 * SHS + 2 * 128 * SAB + 2 * 64 * SAB +
                                   2 * 64 * STB + 4 * 64 * SHS) * 2 + 64 * SVF * 4;
    const int GEMM_SMEM = 2 * STAGE_E * 2;
    cudaFuncSetAttribute(chunk_prep,  cudaFuncAttributeMaxDynamicSharedMemorySize, CP_SMEM);
    cudaFuncSetAttribute(scan_kernel, cudaFuncAttributeMaxDynamicSharedMemorySize, SCAN_SMEM);
    cudaFuncSetAttribute(gemm_v_tc,   cudaFuncAttributeMaxDynamicSharedMemorySize, GEMM_SMEM);
    cudaFuncSetAttribute(gemm_g_tc,   cudaFuncAttributeMaxDynamicSharedMemorySize, GEMM_SMEM);
    cudaFuncSetAttribute(gemm_o_tc,   cudaFuncAttributeMaxDynamicSharedMemorySize, GEMM_SMEM);

    dim3 gg(D_ / 128, M_ / 128);

    split_x_k<<<(M_ * D_) / 1024, 256>>>(x);
    split_w_k<<<(3 * D_ * D_) / 1024, 256>>>(Wv, Wg, Wo);
    gemm_v_tc<<<gg, 256, GEMM_SMEM>>>();
    gemm_g_tc<<<gg, 256, GEMM_SMEM>>>();
    proj_small<<<M_, 256>>>(x, Wb, Wa, dt_bias, A_log);
    conv_silu<<<(B_ * T_ * D_) / 256, 256>>>(conv_w, conv_b);
    norm_rw<<<M_ * H_, 128>>>(x);
    chunk_prep<<<B_ * H_ * NCH, 256, CP_SMEM>>>();
    scan_kernel<<<B_ * H_ * SLICES, 256, SCAN_SMEM>>>();
    rms_gate<<<M_ * H_, 128>>>(norm_w);
    gemm_o_tc<<<gg, 256, GEMM_SMEM>>>(out);
}

// round 6
// speedup vs baseline: 3.2493x; 1.2444x over previous
#include <cuda_runtime.h>
#include <cuda_bf16.h>
#include <math.h>
#include <cstdint>

#define B_ 4
#define T_ 4096
#define D_ 1024
#define H_ 8
#define K_ 128
#define C_ 64
#define NCH 64
#define M_ (B_*T_)
#define RS 129
#define SLICES 4
#define SW 32
#define GSTR 40           // bf16 smem stride for GEMM tiles
#define CAB 136           // chunk_prep bf16 tile stride

// ---------------- scratch -------------------------------------------------------
__device__ float g_xwv [B_*T_*D_];
__device__ float g_gate[B_*T_*D_];
__device__ float g_v   [B_*T_*D_];
__device__ float g_o   [B_*T_*D_];
__device__ float g_beta[B_*T_*H_];
__device__ float g_dec [B_*T_*H_];
__device__ float g_dcum[B_*T_*H_];
__device__ __nv_bfloat16 g_attn_h[B_*H_*NCH*C_*C_], g_attn_l[B_*H_*NCH*C_*C_];
__device__ __nv_bfloat16 g_rk_h [M_*D_], g_rk_l [M_*D_];
__device__ __nv_bfloat16 g_wk_h [M_*D_], g_wk_l [M_*D_];
__device__ __nv_bfloat16 g_wkc_h[M_*D_], g_wkc_l[M_*D_];
__device__ __nv_bfloat16 g_xhi[M_*D_], g_xlo[M_*D_];
__device__ __nv_bfloat16 g_ahi[M_*D_], g_alo[M_*D_];
__device__ __nv_bfloat16 g_Wvhi[D_*D_], g_Wvlo[D_*D_];
__device__ __nv_bfloat16 g_Wghi[D_*D_], g_Wglo[D_*D_];
__device__ __nv_bfloat16 g_Wohi[D_*D_], g_Wolo[D_*D_];

// ================= low-level helpers ===========================================
__device__ __forceinline__ uint32_t smem_u32(const void* p) {
    uint32_t a;
    asm("{ .reg .u64 t; cvta.to.shared.u64 t, %1; cvt.u32.u64 %0, t; }" : "=r"(a) : "l"(p));
    return a;
}
__device__ __forceinline__ void cpasync16(uint32_t saddr, const void* gaddr) {
    asm volatile("cp.async.cg.shared.global [%0], [%1], 16;" :: "r"(saddr), "l"(gaddr));
}
#define CP_COMMIT() asm volatile("cp.async.commit_group;" ::: "memory")
#define CP_WAIT0()  asm volatile("cp.async.wait_group 0;" ::: "memory")

__device__ __forceinline__ void ldsm4(uint32_t* r, uint32_t saddr) {
    asm volatile("ldmatrix.sync.aligned.m8n8.x4.shared.b16 {%0,%1,%2,%3}, [%4];"
        : "=r"(r[0]), "=r"(r[1]), "=r"(r[2]), "=r"(r[3]) : "r"(saddr));
}
__device__ __forceinline__ void ldsm4t(uint32_t* r, uint32_t saddr) {
    asm volatile("ldmatrix.sync.aligned.m8n8.x4.trans.shared.b16 {%0,%1,%2,%3}, [%4];"
        : "=r"(r[0]), "=r"(r[1]), "=r"(r[2]), "=r"(r[3]) : "r"(saddr));
}
__device__ __forceinline__ void mma16816(float* c, const uint32_t* a, uint32_t b0, uint32_t b1) {
    asm volatile(
        "mma.sync.aligned.m16n8k16.row.col.f32.bf16.bf16.f32 "
        "{%0,%1,%2,%3}, {%4,%5,%6,%7}, {%8,%9}, {%0,%1,%2,%3};"
        : "+f"(c[0]), "+f"(c[1]), "+f"(c[2]), "+f"(c[3])
        : "r"(a[0]), "r"(a[1]), "r"(a[2]), "r"(a[3]), "r"(b0), "r"(b1));
}
__device__ __forceinline__ void bfsplit(float v, __nv_bfloat16& h, __nv_bfloat16& l) {
    h = __float2bfloat16(v);
    l = __float2bfloat16(v - __bfloat162float(h));
}

// ================= fused token prep: x-splits, rk/wk norms, beta/dec ===========
__global__ void __launch_bounds__(256) prep_tokens(const float* __restrict__ x,
                                                   const float* __restrict__ Wb,
                                                   const float* __restrict__ Wa,
                                                   const float* __restrict__ dt_bias,
                                                   const float* __restrict__ A_log) {
    const int row = blockIdx.x;                 // b*T + t
    const int t = row & (T_ - 1);
    __shared__ float sx[D_], sxp[D_];
    const int tid = threadIdx.x;
    {
        float4 v = reinterpret_cast<const float4*>(x + (size_t)row * D_)[tid];
        reinterpret_cast<float4*>(sx)[tid] = v;
        float4 vp = (t > 0) ? reinterpret_cast<const float4*>(x + (size_t)(row - 1) * D_)[tid]
                            : make_float4(0.f, 0.f, 0.f, 0.f);
        reinterpret_cast<float4*>(sxp)[tid] = vp;
    }
    __syncthreads();

    // x splits
    {
        float4 v = reinterpret_cast<float4*>(sx)[tid];
        long i = (long)row * D_ + tid * 4;
        __nv_bfloat16 h0, h1, h2, h3, l0, l1, l2, l3;
        bfsplit(v.x, h0, l0); bfsplit(v.y, h1, l1);
        bfsplit(v.z, h2, l2); bfsplit(v.w, h3, l3);
        *reinterpret_cast<__nv_bfloat162*>(g_xhi + i)     = __nv_bfloat162(h0, h1);
        *reinterpret_cast<__nv_bfloat162*>(g_xhi + i + 2) = __nv_bfloat162(h2, h3);
        *reinterpret_cast<__nv_bfloat162*>(g_xlo + i)     = __nv_bfloat162(l0, l1);
        *reinterpret_cast<__nv_bfloat162*>(g_xlo + i + 2) = __nv_bfloat162(l2, l3);
    }

    const int w = tid >> 5, lane = tid & 31;    // warp = head
    // per-head L2 norms for rk (this row) and wk (prev row)
    {
        float4 xv = reinterpret_cast<float4*>(sx)[w * 32 + lane];
        float4 xs = reinterpret_cast<float4*>(sxp)[w * 32 + lane];
        float s1 = xv.x * xv.x + xv.y * xv.y + xv.z * xv.z + xv.w * xv.w;
        float s2 = xs.x * xs.x + xs.y * xs.y + xs.z * xs.z + xs.w * xs.w;
#pragma unroll
        for (int off = 16; off; off >>= 1) {
            s1 += __shfl_xor_sync(0xffffffffu, s1, off);
            s2 += __shfl_xor_sync(0xffffffffu, s2, off);
        }
        float r1 = rsqrtf(s1 + 1e-6f) * 0.08838834764831845f;
        float r2 = rsqrtf(s2 + 1e-6f);
        long gi = (long)row * D_ + w * K_ + lane * 4;
        __nv_bfloat16 h0, h1, h2, h3, l0, l1, l2, l3;
        bfsplit(xv.x * r1, h0, l0); bfsplit(xv.y * r1, h1, l1);
        bfsplit(xv.z * r1, h2, l2); bfsplit(xv.w * r1, h3, l3);
        *reinterpret_cast<__nv_bfloat162*>(g_rk_h + gi)     = __nv_bfloat162(h0, h1);
        *reinterpret_cast<__nv_bfloat162*>(g_rk_h + gi + 2) = __nv_bfloat162(h2, h3);
        *reinterpret_cast<__nv_bfloat162*>(g_rk_l + gi)     = __nv_bfloat162(l0, l1);
        *reinterpret_cast<__nv_bfloat162*>(g_rk_l + gi + 2) = __nv_bfloat162(l2, l3);
        bfsplit(xs.x * r2, h0, l0); bfsplit(xs.y * r2, h1, l1);
        bfsplit(xs.z * r2, h2, l2); bfsplit(xs.w * r2, h3, l3);
        *reinterpret_cast<__nv_bfloat162*>(g_wk_h + gi)     = __nv_bfloat162(h0, h1);
        *reinterpret_cast<__nv_bfloat162*>(g_wk_h + gi + 2) = __nv_bfloat162(h2, h3);
        *reinterpret_cast<__nv_bfloat162*>(g_wk_l + gi)     = __nv_bfloat162(l0, l1);
        *reinterpret_cast<__nv_bfloat162*>(g_wk_l + gi + 2) = __nv_bfloat162(l2, l3);
    }

    // beta / dec projections
    {
        const float* wb = Wb + w * D_;
        const float* wa = Wa + w * D_;
        float db = 0.f, da = 0.f;
        for (int k = lane; k < D_; k += 32) {
            float xv = sx[k];
            db = fmaf(xv, wb[k], db);
            da = fmaf(xv, wa[k], da);
        }
#pragma unroll
        for (int off = 16; off; off >>= 1) {
            db += __shfl_down_sync(0xffffffffu, db, off);
            da += __shfl_down_sync(0xffffffffu, da, off);
        }
        if (lane == 0) {
            g_beta[row * H_ + w] = 1.f / (1.f + expf(-db));
            float z = da + dt_bias[w];
            float sp = (z > 20.f) ? z : log1pf(expf(z));
            g_dec[row * H_ + w] = -expf(A_log[w]) * sp;
        }
    }
}

// ================= weight splits =================================================
__device__ __forceinline__ void split4(const float* __restrict__ src,
                                       __nv_bfloat16* __restrict__ hi,
                                       __nv_bfloat16* __restrict__ lo, long i) {
    float4 v = *reinterpret_cast<const float4*>(src + i);
    __nv_bfloat16 h0, h1, h2, h3, l0, l1, l2, l3;
    bfsplit(v.x, h0, l0); bfsplit(v.y, h1, l1);
    bfsplit(v.z, h2, l2); bfsplit(v.w, h3, l3);
    *reinterpret_cast<__nv_bfloat162*>(hi + i)     = __nv_bfloat162(h0, h1);
    *reinterpret_cast<__nv_bfloat162*>(hi + i + 2) = __nv_bfloat162(h2, h3);
    *reinterpret_cast<__nv_bfloat162*>(lo + i)     = __nv_bfloat162(l0, l1);
    *reinterpret_cast<__nv_bfloat162*>(lo + i + 2) = __nv_bfloat162(l2, l3);
}
__global__ void __launch_bounds__(256) split_w_k(const float* __restrict__ Wv,
                                                 const float* __restrict__ Wg,
                                                 const float* __restrict__ Wo) {
    long i = ((long)blockIdx.x * 256 + threadIdx.x) * 4;
    if (i < 1048576)            split4(Wv, g_Wvhi, g_Wvlo, i);
    else if (i < 2097152)       split4(Wg, g_Wghi, g_Wglo, i - 1048576);
    else                        split4(Wo, g_Wohi, g_Wolo, i - 2097152);
}

// ================= HMMA split-bf16 GEMM ==========================================
#define TILE_E (128 * GSTR)
#define STAGE_E (4 * TILE_E)
__device__ __forceinline__ void gemm_hmma_body(
    const __nv_bfloat16* __restrict__ Ahi, const __nv_bfloat16* __restrict__ Alo,
    const __nv_bfloat16* __restrict__ Bhi, const __nv_bfloat16* __restrict__ Blo,
    float* __restrict__ Cm) {
    extern __shared__ __nv_bfloat16 dsm[];
    const int tid = threadIdx.x;
    const int wid = tid >> 5, lane = tid & 31;
    const int wm = wid & 1;
    const int wn = wid >> 1;
    const int m0 = blockIdx.y * 128;
    const int n0 = blockIdx.x * 128;

    float acc[4][4][4];
#pragma unroll
    for (int mt = 0; mt < 4; mt++)
#pragma unroll
        for (int nt = 0; nt < 4; nt++)
#pragma unroll
            for (int q = 0; q < 4; q++) acc[mt][nt][q] = 0.f;

    const int lrow = tid >> 2, lseg = (tid & 3) * 8;

    const __nv_bfloat16* gp[4];
    gp[0] = Ahi + (size_t)m0 * 1024;
    gp[1] = Alo + (size_t)m0 * 1024;
    gp[2] = Bhi + (size_t)n0 * 1024;
    gp[3] = Blo + (size_t)n0 * 1024;

    auto load_chunk = [&](int kc, int buf) {
#pragma unroll
        for (int t = 0; t < 4; t++) {
            const __nv_bfloat16* g = gp[t] + kc * 32;
            uint32_t s = smem_u32(&dsm[buf * STAGE_E + t * TILE_E]);
            cpasync16(s + (lrow * GSTR + lseg) * 2, g + (size_t)lrow * 1024 + lseg);
            cpasync16(s + ((lrow + 64) * GSTR + lseg) * 2, g + (size_t)(lrow + 64) * 1024 + lseg);
        }
        CP_COMMIT();
    };

    const int r8 = lane & 7, sel = lane >> 3;

    load_chunk(0, 0);
    for (int kc = 0; kc < 32; kc++) {
        CP_WAIT0();
        __syncthreads();
        if (kc + 1 < 32) load_chunk(kc + 1, (kc + 1) & 1);
        const int buf = kc & 1;
        const uint32_t sAhi = smem_u32(&dsm[buf * STAGE_E + 0 * TILE_E]);
        const uint32_t sAlo = sAhi + TILE_E * 2;
        const uint32_t sBhi = sAhi + 2 * TILE_E * 2;
        const uint32_t sBlo = sAhi + 3 * TILE_E * 2;
#pragma unroll
        for (int ks = 0; ks < 2; ks++) {
            const int k16 = ks * 16;
            const int acol = k16 + (sel >> 1) * 8;
            const int bcol = k16 + (sel & 1) * 8;
            uint32_t ah[4][4], al[4][4], bb[2][4];
#pragma unroll
            for (int mt = 0; mt < 4; mt++) {
                int row = wm * 64 + mt * 16 + (sel & 1) * 8 + r8;
                ldsm4(ah[mt], sAhi + (row * GSTR + acol) * 2);
                ldsm4(al[mt], sAlo + (row * GSTR + acol) * 2);
            }
#pragma unroll
            for (int bt = 0; bt < 2; bt++) {
                int nrow = wn * 32 + bt * 16 + (sel >> 1) * 8 + r8;
                ldsm4(bb[bt], sBhi + (nrow * GSTR + bcol) * 2);
            }
#pragma unroll
            for (int mt = 0; mt < 4; mt++)
#pragma unroll
                for (int nt = 0; nt < 4; nt++) {
                    mma16816(acc[mt][nt], ah[mt], bb[nt >> 1][(nt & 1) * 2], bb[nt >> 1][(nt & 1) * 2 + 1]);
                    mma16816(acc[mt][nt], al[mt], bb[nt >> 1][(nt & 1) * 2], bb[nt >> 1][(nt & 1) * 2 + 1]);
                }
#pragma unroll
            for (int bt = 0; bt < 2; bt++) {
                int nrow = wn * 32 + bt * 16 + (sel >> 1) * 8 + r8;
                ldsm4(bb[bt], sBlo + (nrow * GSTR + bcol) * 2);
            }
#pragma unroll
            for (int mt = 0; mt < 4; mt++)
#pragma unroll
                for (int nt = 0; nt < 4; nt++)
                    mma16816(acc[mt][nt], ah[mt], bb[nt >> 1][(nt & 1) * 2], bb[nt >> 1][(nt & 1) * 2 + 1]);
        }
        __syncthreads();
    }

    const int erow = lane >> 2, ecol = (lane & 3) * 2;
#pragma unroll
    for (int mt = 0; mt < 4; mt++) {
        const size_t row0 = (size_t)(m0 + wm * 64 + mt * 16 + erow);
#pragma unroll
        for (int nt = 0; nt < 4; nt++) {
            const size_t cb = (size_t)(n0 + wn * 32 + nt * 8 + ecol);
            *reinterpret_cast<float2*>(Cm + row0 * 1024 + cb) =
                make_float2(acc[mt][nt][0], acc[mt][nt][1]);
            *reinterpret_cast<float2*>(Cm + (row0 + 8) * 1024 + cb) =
                make_float2(acc[mt][nt][2], acc[mt][nt][3]);
        }
    }
}

__global__ void __launch_bounds__(256, 2) gemm_v_tc() { gemm_hmma_body(g_xhi, g_xlo, g_Wvhi, g_Wvlo, g_xwv); }
__global__ void __launch_bounds__(256, 2) gemm_g_tc() { gemm_hmma_body(g_xhi, g_xlo, g_Wghi, g_Wglo, g_gate); }
__global__ void __launch_bounds__(256, 2) gemm_o_tc(float* __restrict__ out) {
    gemm_hmma_body(g_ahi, g_alo, g_Wohi, g_Wolo, out);
}

// ---------------- causal depthwise conv + SiLU + beta --------------------------
__global__ void conv_silu(const float* __restrict__ conv_w, const float* __restrict__ conv_b) {
    long idx = (long)blockIdx.x * 256 + threadIdx.x;
    const int d = (int)(idx & (D_ - 1));
    const long bt = idx >> 10;
    const int t = (int)(bt & (T_ - 1));
    float acc = conv_b[d];
#pragma unroll
    for (int j = 0; j < 4; j++) {
        int tt = t + j - 3;
        if (tt >= 0) acc = fmaf(g_xwv[idx + (long)(j - 3) * D_], conv_w[d * 4 + j], acc);
    }
    float s = acc / (1.f + expf(-acc));
    g_v[idx] = s * g_beta[bt * H_ + (d >> 7)];
}

// ---------------- per-chunk: cumsum, HMMA dots, attn(bf16), blocked solve --------
__global__ void __launch_bounds__(256, 2) chunk_prep() {
    extern __shared__ char cpsm[];
    __nv_bfloat16* swh = (__nv_bfloat16*)cpsm;             // 64*CAB
    __nv_bfloat16* swl = swh + 64 * CAB;
    __nv_bfloat16* srh = swl + 64 * CAB;
    __nv_bfloat16* srl = srh + 64 * CAB;                   // end 69632 B
    float* sA = (float*)(cpsm + 69632);                    // 64*64 fp32 -> end 86016 B
    float* s1 = (float*)(cpsm + 34816);                    // aliases srh/srl (33024 B)
    float* s2 = (float*)cpsm;                              // aliases swh/swl (33024 B)
    __shared__ float sdec[C_], sbeta[C_], sraw[C_];
    const int id = blockIdx.x;
    const int chunk = id & 63;
    const int bh = id >> 6;
    const int b = bh >> 3, h = bh & 7;
    const long t0 = (long)b * T_ + chunk * C_;
    const long base = t0 * D_ + h * K_;
    const int tid = threadIdx.x;
    const int wid = tid >> 5, lane = tid & 31;
    const int g8 = lane >> 3, r8 = lane & 7;

    // stage wk/rk hi/lo tiles
    {
        const uint32_t swh_s = smem_u32(swh), swl_s = smem_u32(swl);
        const uint32_t srh_s = smem_u32(srh), srl_s = smem_u32(srl);
#pragma unroll
        for (int q = 0; q < 4; q++) {
            int u = tid + q * 256;             // 0..1023
            int row = u >> 4, seg = (u & 15) * 8;
            uint32_t d = (uint32_t)(row * CAB + seg) * 2;
            long g = base + (long)row * D_ + seg;
            cpasync16(swh_s + d, g_wk_h + g);
            cpasync16(swl_s + d, g_wk_l + g);
            cpasync16(srh_s + d, g_rk_h + g);
            cpasync16(srl_s + d, g_rk_l + g);
        }
        CP_COMMIT();
    }
    if (tid < C_) {
        sraw[tid] = g_dec[(t0 + tid) * H_ + h];
        sbeta[tid] = g_beta[(t0 + tid) * H_ + h];
    }
    __syncthreads();
    if (tid < C_) {
        float acc = 0.f;
        for (int j = 0; j <= tid; j++) acc += sraw[j];
        sdec[tid] = acc;
        g_dcum[(t0 + tid) * H_ + h] = acc;
    }
    CP_WAIT0();
    __syncthreads();

    // HMMA: P = [wk; rk] @ wk^T  (3-pass split-bf16)
    {
        const uint32_t swh_s = smem_u32(swh), swl_s = smem_u32(swl);
        const uint32_t srh_s = smem_u32(srh), srl_s = smem_u32(srl);
        const uint32_t ash = (wid < 4) ? swh_s : srh_s;
        const uint32_t asl = (wid < 4) ? swl_s : srl_s;
        const int am0 = (wid & 3) * 16;
        const int aro = (g8 & 1) * 8 + r8, aco = (g8 >> 1) * 8;
        const int bro = (g8 >> 1) * 8 + r8, bco = (g8 & 1) * 8;
        float acc[8][4];
#pragma unroll
        for (int nt = 0; nt < 8; nt++)
#pragma unroll
            for (int q = 0; q < 4; q++) acc[nt][q] = 0.f;
#pragma unroll
        for (int ks = 0; ks < 8; ks++) {
            uint32_t ah[4], al[4], bh4[4][4], bl4[4][4];
            uint32_t aoff = (uint32_t)((am0 + aro) * CAB + ks * 16 + aco) * 2;
            ldsm4(ah, ash + aoff);
            ldsm4(al, asl + aoff);
#pragma unroll
            for (int bt = 0; bt < 4; bt++) {
                uint32_t boff = (uint32_t)((bt * 16 + bro) * CAB + ks * 16 + bco) * 2;
                ldsm4(bh4[bt], swh_s + boff);
                ldsm4(bl4[bt], swl_s + boff);
            }
#pragma unroll
            for (int nt = 0; nt < 8; nt++) {
                uint32_t b0h = bh4[nt >> 1][(nt & 1) * 2], b1h = bh4[nt >> 1][(nt & 1) * 2 + 1];
                uint32_t b0l = bl4[nt >> 1][(nt & 1) * 2], b1l = bl4[nt >> 1][(nt & 1) * 2 + 1];
                mma16816(acc[nt], ah, b0h, b1h);
                mma16816(acc[nt], al, b0h, b1h);
                mma16816(acc[nt], ah, b0l, b1l);
            }
        }
        // epilogue: warps 0-3 -> A_strict (smem), warps 4-7 -> attn (global bf16)
        const int er = lane >> 2, ec = (lane & 3) * 2;
        const int i1 = am0 + er, i2 = i1 + 8;
        if (wid < 4) {
            const float b1v = sbeta[i1], b2v = sbeta[i2];
            const float d1 = sdec[i1], d2 = sdec[i2];
#pragma unroll
            for (int nt = 0; nt < 8; nt++) {
                const int j = nt * 8 + ec;
                float a00 = (j     < i1) ? -acc[nt][0] * b1v * __expf(d1 - sdec[j])     : 0.f;
                float a01 = (j + 1 < i1) ? -acc[nt][1] * b1v * __expf(d1 - sdec[j + 1]) : 0.f;
                float a10 = (j     < i2) ? -acc[nt][2] * b2v * __expf(d2 - sdec[j])     : 0.f;
                float a11 = (j + 1 < i2) ? -acc[nt][3] * b2v * __expf(d2 - sdec[j + 1]) : 0.f;
                sA[i1 * 64 + j] = a00; sA[i1 * 64 + j + 1] = a01;
                sA[i2 * 64 + j] = a10; sA[i2 * 64 + j + 1] = a11;
            }
        } else {
            const float d1 = sdec[i1], d2 = sdec[i2];
            const long ab = (long)id * 4096;
#pragma unroll
            for (int nt = 0; nt < 8; nt++) {
                const int j = nt * 8 + ec;
                float a00 = (j     <= i1) ? acc[nt][0] * __expf(d1 - sdec[j])     : 0.f;
                float a01 = (j + 1 <= i1) ? acc[nt][1] * __expf(d1 - sdec[j + 1]) : 0.f;
                float a10 = (j     <= i2) ? acc[nt][2] * __expf(d2 - sdec[j])     : 0.f;
                float a11 = (j + 1 <= i2) ? acc[nt][3] * __expf(d2 - sdec[j + 1]) : 0.f;
                __nv_bfloat16 h0, l0, h1, l1;
                bfsplit(a00, h0, l0); bfsplit(a01, h1, l1);
                *reinterpret_cast<__nv_bfloat162*>(g_attn_h + ab + i1 * 64 + j) = __nv_bfloat162(h0, h1);
                *reinterpret_cast<__nv_bfloat162*>(g_attn_l + ab + i1 * 64 + j) = __nv_bfloat162(l0, l1);
                bfsplit(a10, h0, l0); bfsplit(a11, h1, l1);
                *reinterpret_cast<__nv_bfloat162*>(g_attn_h + ab + i2 * 64 + j) = __nv_bfloat162(h0, h1);
                *reinterpret_cast<__nv_bfloat162*>(g_attn_l + ab + i2 * 64 + j) = __nv_bfloat162(l0, l1);
            }
        }
    }
    if (tid < C_) sraw[tid] = sbeta[tid] * __expf(sdec[tid]);   // beta*exp(dcum)
    __syncthreads();

    // u = wk * beta * exp(dcum) into s1 (aliases rk tiles; reads wk tiles)
    for (int i = tid; i < C_ * K_; i += 256) {
        int c = i >> 7, k = i & 127;
        float wv = __bfloat162float(swh[c * CAB + k]) + __bfloat162float(swl[c * CAB + k]);
        s1[c * RS + k] = wv * sraw[c];
    }
    __syncthreads();
    // v into s2 (aliases wk tiles; wk now dead)
    for (int i = tid; i < C_ * K_; i += 256) {
        int c = i >> 7, k = i & 127;
        s2[c * RS + k] = g_v[base + (long)c * D_ + k];
    }
    __syncthreads();

    // 32-blocked forward substitution on both matrices
    {
        float* sx = (tid < 128) ? s1 : s2;
        const int k = tid & 127;
        // block 0 serial
        for (int i = 1; i < 32; i++) {
            float a = 0.f;
            const float* Ai = sA + i * 64;
#pragma unroll 4
            for (int j = 0; j < i; j++)
                a = fmaf(Ai[j], sx[j * RS + k], a);
            sx[i * RS + k] += a;
        }
        // rank-32 update of block 1
        float up[32];
#pragma unroll
        for (int i = 0; i < 32; i++) up[i] = 0.f;
        for (int j = 0; j < 32; j++) {
            float xv = sx[j * RS + k];
#pragma unroll
            for (int i = 0; i < 32; i++)
                up[i] = fmaf(sA[(32 + i) * 64 + j], xv, up[i]);
        }
#pragma unroll
        for (int i = 0; i < 32; i++)
            sx[(32 + i) * RS + k] += up[i];
        // block 1 serial
        for (int i = 33; i < 64; i++) {
            float a = 0.f;
            const float* Ai = sA + i * 64;
#pragma unroll 4
            for (int j = 32; j < i; j++)
                a = fmaf(Ai[j], sx[j * RS + k], a);
            sx[i * RS + k] += a;
        }
    }
    __syncthreads();

    for (int i = tid; i < C_ * K_; i += 256) {
        int c = i >> 7, k = i & 127;
        float u = s1[c * RS + k];
        __nv_bfloat16 hh, ll;
        bfsplit(u, hh, ll);
        g_wkc_h[base + (long)c * D_ + k] = hh;
        g_wkc_l[base + (long)c * D_ + k] = ll;
        g_v[base + (long)c * D_ + k] = s2[c * RS + k];
    }
}

// ---------------- HMMA chunk scan -----------------------------------------------
#define SSF 33     // sS fp32 128x33
#define SHS 56     // Shi/Slo, svh/svl, s2h/l bf16
#define SAB 136    // sA / swk bf16
#define STB 72     // attn bf16
#define SVF 36     // sv fp32

__global__ void __launch_bounds__(256) scan_kernel() {
    extern __shared__ char smraw[];
    float* sS = (float*)smraw;                                     // 16896 B
    __nv_bfloat16* sShi = (__nv_bfloat16*)(smraw + 16896);
    __nv_bfloat16* sSlo = sShi + 128 * SHS;
    __nv_bfloat16* sAh  = sSlo + 128 * SHS;
    __nv_bfloat16* sAl  = sAh + 128 * SAB;
    __nv_bfloat16* sWh  = sAl + 128 * SAB;
    __nv_bfloat16* sWl  = sWh + 64 * SAB;
    __nv_bfloat16* sTh  = sWl + 64 * SAB;
    __nv_bfloat16* sTl  = sTh + 64 * STB;
    __nv_bfloat16* svh  = sTl + 64 * STB;
    __nv_bfloat16* svl  = svh + 64 * SHS;
    __nv_bfloat16* s2h  = svl + 64 * SHS;
    __nv_bfloat16* s2l  = s2h + 64 * SHS;
    float* sv = (float*)(s2l + 64 * SHS);

    const int bh = blockIdx.x >> 2;
    const int slice = blockIdx.x & 3;
    const int b = bh >> 3, h = bh & 7;
    const int j0g = slice * SW;
    const int tid = threadIdx.x;
    const int wid = tid >> 5, lane = tid & 31;
    const int g8 = lane >> 3, r8 = lane & 7;
    const int aro = (g8 & 1) * 8 + r8;
    const int aco = (g8 >> 1) * 8;
    const int bro = (g8 & 1) * 8 + r8;     // trans-B k-row offset
    const int bco = (g8 >> 1) * 8;
    const int tro = (g8 >> 1) * 8 + r8;    // trans-A row offset
    const int tco = (g8 & 1) * 8;
    const int er = lane >> 2, ec = (lane & 3) * 2;

    const uint32_t sShi_s = smem_u32(sShi), sSlo_s = smem_u32(sSlo);
    const uint32_t sAh_s = smem_u32(sAh), sAl_s = smem_u32(sAl);
    const uint32_t sWh_s = smem_u32(sWh), sWl_s = smem_u32(sWl);
    const uint32_t sTh_s = smem_u32(sTh), sTl_s = smem_u32(sTl);
    const uint32_t svh_s = smem_u32(svh), svl_s = smem_u32(svl);
    const uint32_t s2h_s = smem_u32(s2h), s2l_s = smem_u32(s2l);
    const uint32_t sv_s = smem_u32(sv);

    auto issue_Av = [&](int chunk) {
        const long base = ((long)b * T_ + chunk * C_) * D_ + h * K_;
#pragma unroll
        for (int q = 0; q < 8; q++) {
            int u = tid + q * 256;
            int row = u >> 4, seg = (u & 15) * 8;
            uint32_t d = (uint32_t)(row * SAB + seg) * 2;
            if (row < 64) {
                long g = base + (long)row * D_ + seg;
                cpasync16(sAh_s + d, g_wkc_h + g);
                cpasync16(sAl_s + d, g_wkc_l + g);
            } else {
                long g = base + (long)(row - 64) * D_ + seg;
                cpasync16(sAh_s + d, g_rk_h + g);
                cpasync16(sAl_s + d, g_rk_l + g);
            }
        }
#pragma unroll
        for (int q = 0; q < 2; q++) {
            int u = tid + q * 256;
            int row = u >> 3, seg = (u & 7) * 4;
            cpasync16(sv_s + (uint32_t)(row * SVF + seg) * 4,
                      g_v + base + (long)row * D_ + j0g + seg);
        }
        CP_COMMIT();
    };
    auto issue_W = [&](int chunk) {   // warps 0-3 only
        const long base = ((long)b * T_ + chunk * C_) * D_ + h * K_;
        const int lt = tid;           // 0..127
#pragma unroll
        for (int q = 0; q < 8; q++) {
            int u = lt + q * 128;     // 0..1023
            int row = u >> 4, seg = (u & 15) * 8;
            uint32_t d = (uint32_t)(row * SAB + seg) * 2;
            long g = base + (long)row * D_ + seg;
            cpasync16(sWh_s + d, g_wk_h + g);
            cpasync16(sWl_s + d, g_wk_l + g);
        }
        CP_COMMIT();
    };
    auto issue_T = [&](int chunk) {   // warps 4-7 only
        const int lt = tid - 128;     // 0..127
        const long ab = ((long)bh * NCH + chunk) * 4096;
#pragma unroll
        for (int q = 0; q < 4; q++) {
            int u = lt + q * 128;     // 0..511
            int row = u >> 3, seg = (u & 7) * 8;
            uint32_t d = (uint32_t)(row * STB + seg) * 2;
            cpasync16(sTh_s + d, g_attn_h + ab + row * 64 + seg);
            cpasync16(sTl_s + d, g_attn_l + ab + row * 64 + seg);
        }
        CP_COMMIT();
    };

    for (int i = tid; i < 128 * SSF; i += 256) sS[i] = 0.f;
    for (int i = tid; i < 128 * SHS; i += 256) {
        sShi[i] = __float2bfloat16(0.f);
        sSlo[i] = __float2bfloat16(0.f);
    }
    issue_Av(0);
    if (wid < 4) issue_W(0); else issue_T(0);

    const int m0 = wid * 16;

    for (int chunk = 0; chunk < NCH; chunk++) {
        const long t0 = (long)b * T_ + chunk * C_;
        const long obase = t0 * D_ + h * K_;
        CP_WAIT0();
        const int myrow = (wid < 4) ? (m0 + er) : (m0 - 64 + er);
        const float dec63 = g_dcum[(t0 + 63) * H_ + h];
        const float decA = g_dcum[(t0 + myrow) * H_ + h];
        const float decB = g_dcum[(t0 + myrow + 8) * H_ + h];
        __syncthreads();

        // ---- HMMA1: P(128x32) = [wkc; rk] @ S ----
        float acc[4][4];
#pragma unroll
        for (int nt = 0; nt < 4; nt++)
#pragma unroll
            for (int q = 0; q < 4; q++) acc[nt][q] = 0.f;
#pragma unroll
        for (int ks = 0; ks < 8; ks++) {
            uint32_t ah[4], al[4], bhf[2][4], blf[2][4];
            uint32_t aoff = (uint32_t)((m0 + aro) * SAB + ks * 16 + aco) * 2;
            ldsm4(ah, sAh_s + aoff);
            ldsm4(al, sAl_s + aoff);
#pragma unroll
            for (int nh = 0; nh < 2; nh++) {
                uint32_t boff = (uint32_t)((ks * 16 + bro) * SHS + nh * 16 + bco) * 2;
                ldsm4t(bhf[nh], sShi_s + boff);
                ldsm4t(blf[nh], sSlo_s + boff);
            }
#pragma unroll
            for (int nt = 0; nt < 4; nt++) {
                uint32_t b0h = bhf[nt >> 1][(nt & 1) * 2], b1h = bhf[nt >> 1][(nt & 1) * 2 + 1];
                uint32_t b0l = blf[nt >> 1][(nt & 1) * 2], b1l = blf[nt >> 1][(nt & 1) * 2 + 1];
                mma16816(acc[nt], ah, b0h, b1h);
                mma16816(acc[nt], al, b0h, b1h);
                mma16816(acc[nt], ah, b0l, b1l);
            }
        }

        // ---- epilogue 1 ----
        if (wid < 4) {
            const int c1 = m0 + er, c2 = c1 + 8;
            const float dw1 = __expf(dec63 - decA), dw2 = __expf(dec63 - decB);
#pragma unroll
            for (int nt = 0; nt < 4; nt++) {
                const int col = nt * 8 + ec;
                float a0 = sv[c1 * SVF + col]     - acc[nt][0];
                float a1 = sv[c1 * SVF + col + 1] - acc[nt][1];
                float a2 = sv[c2 * SVF + col]     - acc[nt][2];
                float a3 = sv[c2 * SVF + col + 1] - acc[nt][3];
                __nv_bfloat16 h0, l0, h1, l1, h2, l2, h3, l3;
                bfsplit(a0, h0, l0); bfsplit(a1, h1, l1);
                bfsplit(a2, h2, l2); bfsplit(a3, h3, l3);
                *reinterpret_cast<__nv_bfloat162*>(svh + c1 * SHS + col) = __nv_bfloat162(h0, h1);
                *reinterpret_cast<__nv_bfloat162*>(svl + c1 * SHS + col) = __nv_bfloat162(l0, l1);
                *reinterpret_cast<__nv_bfloat162*>(svh + c2 * SHS + col) = __nv_bfloat162(h2, h3);
                *reinterpret_cast<__nv_bfloat162*>(svl + c2 * SHS + col) = __nv_bfloat162(l2, l3);
                float b0 = dw1 * a0, b1 = dw1 * a1, b2 = dw2 * a2, b3 = dw2 * a3;
                bfsplit(b0, h0, l0); bfsplit(b1, h1, l1);
                bfsplit(b2, h2, l2); bfsplit(b3, h3, l3);
                *reinterpret_cast<__nv_bfloat162*>(s2h + c1 * SHS + col) = __nv_bfloat162(h0, h1);
                *reinterpret_cast<__nv_bfloat162*>(s2l + c1 * SHS + col) = __nv_bfloat162(l0, l1);
                *reinterpret_cast<__nv_bfloat162*>(s2h + c2 * SHS + col) = __nv_bfloat162(h2, h3);
                *reinterpret_cast<__nv_bfloat162*>(s2l + c2 * SHS + col) = __nv_bfloat162(l2, l3);
            }
        } else {
            const float e1 = __expf(decA), e2 = __expf(decB);
#pragma unroll
            for (int nt = 0; nt < 4; nt++) {
                acc[nt][0] *= e1; acc[nt][1] *= e1;
                acc[nt][2] *= e2; acc[nt][3] *= e2;
            }
        }
        __syncthreads();
        if (chunk + 1 < NCH) issue_Av(chunk + 1);

        if (wid >= 4) {
            // ---- o = e*rkS (in acc) + attn @ v_new ----
            const int m0o = (wid - 4) * 16;
#pragma unroll
            for (int ks = 0; ks < 4; ks++) {
                uint32_t ah[4], al[4], bhf[2][4], blf[2][4];
                uint32_t aoff = (uint32_t)((m0o + aro) * STB + ks * 16 + aco) * 2;
                ldsm4(ah, sTh_s + aoff);
                ldsm4(al, sTl_s + aoff);
#pragma unroll
                for (int nh = 0; nh < 2; nh++) {
                    uint32_t boff = (uint32_t)((ks * 16 + bro) * SHS + nh * 16 + bco) * 2;
                    ldsm4t(bhf[nh], svh_s + boff);
                    ldsm4t(blf[nh], svl_s + boff);
                }
#pragma unroll
                for (int nt = 0; nt < 4; nt++) {
                    uint32_t b0h = bhf[nt >> 1][(nt & 1) * 2], b1h = bhf[nt >> 1][(nt & 1) * 2 + 1];
                    uint32_t b0l = blf[nt >> 1][(nt & 1) * 2], b1l = blf[nt >> 1][(nt & 1) * 2 + 1];
                    mma16816(acc[nt], ah, b0h, b1h);
                    mma16816(acc[nt], al, b0h, b1h);
                    mma16816(acc[nt], ah, b0l, b1l);
                }
            }
            const int c1 = m0o + er, c2 = c1 + 8;
#pragma unroll
            for (int nt = 0; nt < 4; nt++) {
                const int col = nt * 8 + ec;
                *reinterpret_cast<float2*>(g_o + obase + (long)c1 * D_ + j0g + col) =
                    make_float2(acc[nt][0], acc[nt][1]);
                *reinterpret_cast<float2*>(g_o + obase + (long)c2 * D_ + j0g + col) =
                    make_float2(acc[nt][2], acc[nt][3]);
            }
            if (chunk + 1 < NCH) issue_T(chunk + 1);
        } else {
            // ---- S = e63*S + wk^T @ (dw*v_new); also write Shi/Slo ----
            const float e63 = __expf(dec63);
#pragma unroll
            for (int mt = 0; mt < 2; mt++) {
                const int m0s = wid * 32 + mt * 16;
                float a2c[4][4];
#pragma unroll
                for (int nt = 0; nt < 4; nt++)
#pragma unroll
                    for (int q = 0; q < 4; q++) a2c[nt][q] = 0.f;
#pragma unroll
                for (int ks = 0; ks < 4; ks++) {
                    uint32_t ah[4], al[4], bhf[2][4], blf[2][4];
                    uint32_t aoff = (uint32_t)((ks * 16 + tro) * SAB + m0s + tco) * 2;
                    ldsm4t(ah, sWh_s + aoff);
                    ldsm4t(al, sWl_s + aoff);
#pragma unroll
                    for (int nh = 0; nh < 2; nh++) {
                        uint32_t boff = (uint32_t)((ks * 16 + bro) * SHS + nh * 16 + bco) * 2;
                        ldsm4t(bhf[nh], s2h_s + boff);
                        ldsm4t(blf[nh], s2l_s + boff);
                    }
#pragma unroll
                    for (int nt = 0; nt < 4; nt++) {
                        uint32_t b0h = bhf[nt >> 1][(nt & 1) * 2], b1h = bhf[nt >> 1][(nt & 1) * 2 + 1];
                        uint32_t b0l = blf[nt >> 1][(nt & 1) * 2], b1l = blf[nt >> 1][(nt & 1) * 2 + 1];
                        mma16816(a2c[nt], ah, b0h, b1h);
                        mma16816(a2c[nt], al, b0h, b1h);
                        mma16816(a2c[nt], ah, b0l, b1l);
                    }
                }
                const int k1 = m0s + er, k2 = k1 + 8;
#pragma unroll
                for (int nt = 0; nt < 4; nt++) {
                    const int col = nt * 8 + ec;
                    float n00 = sS[k1 * SSF + col]     * e63 + a2c[nt][0];
                    float n01 = sS[k1 * SSF + col + 1] * e63 + a2c[nt][1];
                    float n10 = sS[k2 * SSF + col]     * e63 + a2c[nt][2];
                    float n11 = sS[k2 * SSF + col + 1] * e63 + a2c[nt][3];
                    sS[k1 * SSF + col] = n00; sS[k1 * SSF + col + 1] = n01;
                    sS[k2 * SSF + col] = n10; sS[k2 * SSF + col + 1] = n11;
                    __nv_bfloat16 hh, ll;
                    bfsplit(n00, hh, ll); sShi[k1 * SHS + col] = hh;     sSlo[k1 * SHS + col] = ll;
                    bfsplit(n01, hh, ll); sShi[k1 * SHS + col + 1] = hh; sSlo[k1 * SHS + col + 1] = ll;
                    bfsplit(n10, hh, ll); sShi[k2 * SHS + col] = hh;     sSlo[k2 * SHS + col] = ll;
                    bfsplit(n11, hh, ll); sShi[k2 * SHS + col + 1] = hh; sSlo[k2 * SHS + col + 1] = ll;
                }
            }
            if (chunk + 1 < NCH) issue_W(chunk + 1);
        }
    }
}

// ---------------- per-head RMSNorm + gated SiLU (writes split bf16) --------------
__global__ void __launch_bounds__(128) rms_gate(const float* __restrict__ norm_w) {
    const int bhk = blockIdx.x;
    const int k = threadIdx.x;
    const long gi = (long)bhk * K_ + k;
    float ov = g_o[gi];
    float s = ov * ov;
#pragma unroll
    for (int off = 16; off; off >>= 1) s += __shfl_xor_sync(0xffffffffu, s, off);
    __shared__ float red[4];
    if ((k & 31) == 0) red[k >> 5] = s;
    __syncthreads();
    float tot = red[0] + red[1] + red[2] + red[3];
    float r = rsqrtf(tot * (1.f / 128.f) + 1e-5f);
    float g = g_gate[gi];
    float sg = g / (1.f + expf(-g));
    float val = ov * r * norm_w[k] * sg;
    __nv_bfloat16 hh, ll;
    bfsplit(val, hh, ll);
    g_ahi[gi] = hh;
    g_alo[gi] = ll;
}

// ---------------- launcher ------------------------------------------------------
extern "C" void kernel_launch(void* const* d_in, const int* in_sizes, int n_in,
                              void* d_out, int out_size) {
    const float* x       = (const float*)d_in[0];
    const float* Wv      = (const float*)d_in[1];
    const float* Wg      = (const float*)d_in[2];
    const float* Wo      = (const float*)d_in[3];
    const float* Wb      = (const float*)d_in[4];
    const float* Wa      = (const float*)d_in[5];
    const float* dt_bias = (const float*)d_in[6];
    const float* A_log   = (const float*)d_in[7];
    const float* norm_w  = (const float*)d_in[8];
    const float* conv_w  = (const float*)d_in[9];
    const float* conv_b  = (const float*)d_in[10];
    float* out = (float*)d_out;

    const int CP_SMEM   = 86016;
    const int SCAN_SMEM = 16896 + (2 * 128 * SHS + 2 * 128 * SAB + 2 * 64 * SAB +
                                   2 * 64 * STB + 4 * 64 * SHS) * 2 + 64 * SVF * 4;
    const int GEMM_SMEM = 2 * STAGE_E * 2;
    cudaFuncSetAttribute(chunk_prep,  cudaFuncAttributeMaxDynamicSharedMemorySize, CP_SMEM);
    cudaFuncSetAttribute(scan_kernel, cudaFuncAttributeMaxDynamicSharedMemorySize, SCAN_SMEM);
    cudaFuncSetAttribute(gemm_v_tc,   cudaFuncAttributeMaxDynamicSharedMemorySize, GEMM_SMEM);
    cudaFuncSetAttribute(gemm_g_tc,   cudaFuncAttributeMaxDynamicSharedMemorySize, GEMM_SMEM);
    cudaFuncSetAttribute(gemm_o_tc,   cudaFuncAttributeMaxDynamicSharedMemorySize, GEMM_SMEM);

    dim3 gg(D_ / 128, M_ / 128);

    prep_tokens<<<M_, 256>>>(x, Wb, Wa, dt_bias, A_log);
    split_w_k<<<(3 * D_ * D_) / 1024, 256>>>(Wv, Wg, Wo);
    gemm_v_tc<<<gg, 256, GEMM_SMEM>>>();
    gemm_g_tc<<<gg, 256, GEMM_SMEM>>>();
    conv_silu<<<(B_ * T_ * D_) / 256, 256>>>(conv_w, conv_b);
    chunk_prep<<<B_ * H_ * NCH, 256, CP_SMEM>>>();
    scan_kernel<<<B_ * H_ * SLICES, 256, SCAN_SMEM>>>();
    rms_gate<<<M_ * H_, 128>>>(norm_w);
    gemm_o_tc<<<gg, 256, GEMM_SMEM>>>(out);
}

// round 8
// speedup vs baseline: 3.5344x; 1.0877x over previous
#include <cuda_runtime.h>
#include <cuda_bf16.h>
#include <math.h>
#include <cstdint>

#define B_ 4
#define T_ 4096
#define D_ 1024
#define H_ 8
#define K_ 128
#define C_ 64
#define NCH 64
#define M_ (B_*T_)
#define RS 129
#define SLICES 4
#define SW 32
#define GSTR 40           // bf16 smem stride for GEMM tiles
#define CAB 136           // chunk_prep bf16 tile stride

// ---------------- scratch -------------------------------------------------------
__device__ float g_xwv [B_*T_*D_];
__device__ float g_gate[B_*T_*D_];
__device__ float g_v   [B_*T_*D_];
__device__ float g_o   [B_*T_*D_];
__device__ float g_beta[B_*T_*H_];
__device__ float g_dec [B_*T_*H_];
__device__ float g_dcum[B_*T_*H_];
__device__ __nv_bfloat16 g_attn_h[B_*H_*NCH*C_*C_], g_attn_l[B_*H_*NCH*C_*C_];
__device__ __nv_bfloat16 g_rk_h [M_*D_], g_rk_l [M_*D_];
__device__ __nv_bfloat16 g_wk_h [M_*D_], g_wk_l [M_*D_];
__device__ __nv_bfloat16 g_wkc_h[M_*D_], g_wkc_l[M_*D_];
__device__ __nv_bfloat16 g_xhi[M_*D_], g_xlo[M_*D_];
__device__ __nv_bfloat16 g_ahi[M_*D_], g_alo[M_*D_];
__device__ __nv_bfloat16 g_Wvhi[D_*D_], g_Wvlo[D_*D_];
__device__ __nv_bfloat16 g_Wghi[D_*D_], g_Wglo[D_*D_];
__device__ __nv_bfloat16 g_Wohi[D_*D_], g_Wolo[D_*D_];

// ---------------- streams/events for graph-captured fork (created pre-run) ------
static cudaStream_t s_aux1 = nullptr, s_aux2 = nullptr;
static cudaEvent_t ev_root = nullptr, ev_w = nullptr, ev_p = nullptr, ev_g = nullptr;
static bool s_ok = false;
struct _StreamInit {
    _StreamInit() {
        s_ok = (cudaStreamCreateWithFlags(&s_aux1, cudaStreamNonBlocking) == cudaSuccess) &&
               (cudaStreamCreateWithFlags(&s_aux2, cudaStreamNonBlocking) == cudaSuccess) &&
               (cudaEventCreateWithFlags(&ev_root, cudaEventDisableTiming) == cudaSuccess) &&
               (cudaEventCreateWithFlags(&ev_w, cudaEventDisableTiming) == cudaSuccess) &&
               (cudaEventCreateWithFlags(&ev_p, cudaEventDisableTiming) == cudaSuccess) &&
               (cudaEventCreateWithFlags(&ev_g, cudaEventDisableTiming) == cudaSuccess);
    }
};
static _StreamInit _stream_init_obj;

// ================= low-level helpers ===========================================
__device__ __forceinline__ uint32_t smem_u32(const void* p) {
    uint32_t a;
    asm("{ .reg .u64 t; cvta.to.shared.u64 t, %1; cvt.u32.u64 %0, t; }" : "=r"(a) : "l"(p));
    return a;
}
__device__ __forceinline__ void cpasync16(uint32_t saddr, const void* gaddr) {
    asm volatile("cp.async.cg.shared.global [%0], [%1], 16;" :: "r"(saddr), "l"(gaddr));
}
#define CP_COMMIT() asm volatile("cp.async.commit_group;" ::: "memory")
#define CP_WAIT0()  asm volatile("cp.async.wait_group 0;" ::: "memory")

__device__ __forceinline__ void ldsm4(uint32_t* r, uint32_t saddr) {
    asm volatile("ldmatrix.sync.aligned.m8n8.x4.shared.b16 {%0,%1,%2,%3}, [%4];"
        : "=r"(r[0]), "=r"(r[1]), "=r"(r[2]), "=r"(r[3]) : "r"(saddr));
}
__device__ __forceinline__ void ldsm4t(uint32_t* r, uint32_t saddr) {
    asm volatile("ldmatrix.sync.aligned.m8n8.x4.trans.shared.b16 {%0,%1,%2,%3}, [%4];"
        : "=r"(r[0]), "=r"(r[1]), "=r"(r[2]), "=r"(r[3]) : "r"(saddr));
}
__device__ __forceinline__ void mma16816(float* c, const uint32_t* a, uint32_t b0, uint32_t b1) {
    asm volatile(
        "mma.sync.aligned.m16n8k16.row.col.f32.bf16.bf16.f32 "
        "{%0,%1,%2,%3}, {%4,%5,%6,%7}, {%8,%9}, {%0,%1,%2,%3};"
        : "+f"(c[0]), "+f"(c[1]), "+f"(c[2]), "+f"(c[3])
        : "r"(a[0]), "r"(a[1]), "r"(a[2]), "r"(a[3]), "r"(b0), "r"(b1));
}
__device__ __forceinline__ void bfsplit(float v, __nv_bfloat16& h, __nv_bfloat16& l) {
    h = __float2bfloat16(v);
    l = __float2bfloat16(v - __bfloat162float(h));
}

// ================= fused token prep: x-splits, rk/wk norms, beta/dec ===========
__global__ void __launch_bounds__(256) prep_tokens(const float* __restrict__ x,
                                                   const float* __restrict__ Wb,
                                                   const float* __restrict__ Wa,
                                                   const float* __restrict__ dt_bias,
                                                   const float* __restrict__ A_log) {
    const int row = blockIdx.x;                 // b*T + t
    const int t = row & (T_ - 1);
    __shared__ float sx[D_], sxp[D_];
    const int tid = threadIdx.x;
    {
        float4 v = reinterpret_cast<const float4*>(x + (size_t)row * D_)[tid];
        reinterpret_cast<float4*>(sx)[tid] = v;
        float4 vp = (t > 0) ? reinterpret_cast<const float4*>(x + (size_t)(row - 1) * D_)[tid]
                            : make_float4(0.f, 0.f, 0.f, 0.f);
        reinterpret_cast<float4*>(sxp)[tid] = vp;
    }
    __syncthreads();

    // x splits
    {
        float4 v = reinterpret_cast<float4*>(sx)[tid];
        long i = (long)row * D_ + tid * 4;
        __nv_bfloat16 h0, h1, h2, h3, l0, l1, l2, l3;
        bfsplit(v.x, h0, l0); bfsplit(v.y, h1, l1);
        bfsplit(v.z, h2, l2); bfsplit(v.w, h3, l3);
        *reinterpret_cast<__nv_bfloat162*>(g_xhi + i)     = __nv_bfloat162(h0, h1);
        *reinterpret_cast<__nv_bfloat162*>(g_xhi + i + 2) = __nv_bfloat162(h2, h3);
        *reinterpret_cast<__nv_bfloat162*>(g_xlo + i)     = __nv_bfloat162(l0, l1);
        *reinterpret_cast<__nv_bfloat162*>(g_xlo + i + 2) = __nv_bfloat162(l2, l3);
    }

    const int w = tid >> 5, lane = tid & 31;    // warp = head
    {
        float4 xv = reinterpret_cast<float4*>(sx)[w * 32 + lane];
        float4 xs = reinterpret_cast<float4*>(sxp)[w * 32 + lane];
        float s1 = xv.x * xv.x + xv.y * xv.y + xv.z * xv.z + xv.w * xv.w;
        float s2 = xs.x * xs.x + xs.y * xs.y + xs.z * xs.z + xs.w * xs.w;
#pragma unroll
        for (int off = 16; off; off >>= 1) {
            s1 += __shfl_xor_sync(0xffffffffu, s1, off);
            s2 += __shfl_xor_sync(0xffffffffu, s2, off);
        }
        float r1 = rsqrtf(s1 + 1e-6f) * 0.08838834764831845f;
        float r2 = rsqrtf(s2 + 1e-6f);
        long gi = (long)row * D_ + w * K_ + lane * 4;
        __nv_bfloat16 h0, h1, h2, h3, l0, l1, l2, l3;
        bfsplit(xv.x * r1, h0, l0); bfsplit(xv.y * r1, h1, l1);
        bfsplit(xv.z * r1, h2, l2); bfsplit(xv.w * r1, h3, l3);
        *reinterpret_cast<__nv_bfloat162*>(g_rk_h + gi)     = __nv_bfloat162(h0, h1);
        *reinterpret_cast<__nv_bfloat162*>(g_rk_h + gi + 2) = __nv_bfloat162(h2, h3);
        *reinterpret_cast<__nv_bfloat162*>(g_rk_l + gi)     = __nv_bfloat162(l0, l1);
        *reinterpret_cast<__nv_bfloat162*>(g_rk_l + gi + 2) = __nv_bfloat162(l2, l3);
        bfsplit(xs.x * r2, h0, l0); bfsplit(xs.y * r2, h1, l1);
        bfsplit(xs.z * r2, h2, l2); bfsplit(xs.w * r2, h3, l3);
        *reinterpret_cast<__nv_bfloat162*>(g_wk_h + gi)     = __nv_bfloat162(h0, h1);
        *reinterpret_cast<__nv_bfloat162*>(g_wk_h + gi + 2) = __nv_bfloat162(h2, h3);
        *reinterpret_cast<__nv_bfloat162*>(g_wk_l + gi)     = __nv_bfloat162(l0, l1);
        *reinterpret_cast<__nv_bfloat162*>(g_wk_l + gi + 2) = __nv_bfloat162(l2, l3);
    }

    // beta / dec projections
    {
        const float* wb = Wb + w * D_;
        const float* wa = Wa + w * D_;
        float db = 0.f, da = 0.f;
        for (int k = lane; k < D_; k += 32) {
            float xv = sx[k];
            db = fmaf(xv, wb[k], db);
            da = fmaf(xv, wa[k], da);
        }
#pragma unroll
        for (int off = 16; off; off >>= 1) {
            db += __shfl_down_sync(0xffffffffu, db, off);
            da += __shfl_down_sync(0xffffffffu, da, off);
        }
        if (lane == 0) {
            g_beta[row * H_ + w] = 1.f / (1.f + expf(-db));
            float z = da + dt_bias[w];
            float sp = (z > 20.f) ? z : log1pf(expf(z));
            g_dec[row * H_ + w] = -expf(A_log[w]) * sp;
        }
    }
}

// ================= weight splits =================================================
__device__ __forceinline__ void split4(const float* __restrict__ src,
                                       __nv_bfloat16* __restrict__ hi,
                                       __nv_bfloat16* __restrict__ lo, long i) {
    float4 v = *reinterpret_cast<const float4*>(src + i);
    __nv_bfloat16 h0, h1, h2, h3, l0, l1, l2, l3;
    bfsplit(v.x, h0, l0); bfsplit(v.y, h1, l1);
    bfsplit(v.z, h2, l2); bfsplit(v.w, h3, l3);
    *reinterpret_cast<__nv_bfloat162*>(hi + i)     = __nv_bfloat162(h0, h1);
    *reinterpret_cast<__nv_bfloat162*>(hi + i + 2) = __nv_bfloat162(h2, h3);
    *reinterpret_cast<__nv_bfloat162*>(lo + i)     = __nv_bfloat162(l0, l1);
    *reinterpret_cast<__nv_bfloat162*>(lo + i + 2) = __nv_bfloat162(l2, l3);
}
__global__ void __launch_bounds__(256) split_w_k(const float* __restrict__ Wv,
                                                 const float* __restrict__ Wg,
                                                 const float* __restrict__ Wo) {
    long i = ((long)blockIdx.x * 256 + threadIdx.x) * 4;
    if (i < 1048576)            split4(Wv, g_Wvhi, g_Wvlo, i);
    else if (i < 2097152)       split4(Wg, g_Wghi, g_Wglo, i - 1048576);
    else                        split4(Wo, g_Wohi, g_Wolo, i - 2097152);
}

// ================= HMMA split-bf16 GEMM ==========================================
#define TILE_E (128 * GSTR)
#define STAGE_E (4 * TILE_E)
__device__ __forceinline__ void gemm_hmma_body(
    const __nv_bfloat16* __restrict__ Ahi, const __nv_bfloat16* __restrict__ Alo,
    const __nv_bfloat16* __restrict__ Bhi, const __nv_bfloat16* __restrict__ Blo,
    float* __restrict__ Cm) {
    extern __shared__ __nv_bfloat16 dsm[];
    const int tid = threadIdx.x;
    const int wid = tid >> 5, lane = tid & 31;
    const int wm = wid & 1;
    const int wn = wid >> 1;
    const int m0 = blockIdx.y * 128;
    const int n0 = blockIdx.x * 128;

    float acc[4][4][4];
#pragma unroll
    for (int mt = 0; mt < 4; mt++)
#pragma unroll
        for (int nt = 0; nt < 4; nt++)
#pragma unroll
            for (int q = 0; q < 4; q++) acc[mt][nt][q] = 0.f;

    const int lrow = tid >> 2, lseg = (tid & 3) * 8;

    const __nv_bfloat16* gp[4];
    gp[0] = Ahi + (size_t)m0 * 1024;
    gp[1] = Alo + (size_t)m0 * 1024;
    gp[2] = Bhi + (size_t)n0 * 1024;
    gp[3] = Blo + (size_t)n0 * 1024;

    auto load_chunk = [&](int kc, int buf) {
#pragma unroll
        for (int t = 0; t < 4; t++) {
            const __nv_bfloat16* g = gp[t] + kc * 32;
            uint32_t s = smem_u32(&dsm[buf * STAGE_E + t * TILE_E]);
            cpasync16(s + (lrow * GSTR + lseg) * 2, g + (size_t)lrow * 1024 + lseg);
            cpasync16(s + ((lrow + 64) * GSTR + lseg) * 2, g + (size_t)(lrow + 64) * 1024 + lseg);
        }
        CP_COMMIT();
    };

    const int r8 = lane & 7, sel = lane >> 3;

    load_chunk(0, 0);
    for (int kc = 0; kc < 32; kc++) {
        CP_WAIT0();
        __syncthreads();
        if (kc + 1 < 32) load_chunk(kc + 1, (kc + 1) & 1);
        const int buf = kc & 1;
        const uint32_t sAhi = smem_u32(&dsm[buf * STAGE_E + 0 * TILE_E]);
        const uint32_t sAlo = sAhi + TILE_E * 2;
        const uint32_t sBhi = sAhi + 2 * TILE_E * 2;
        const uint32_t sBlo = sAhi + 3 * TILE_E * 2;
#pragma unroll
        for (int ks = 0; ks < 2; ks++) {
            const int k16 = ks * 16;
            const int acol = k16 + (sel >> 1) * 8;
            const int bcol = k16 + (sel & 1) * 8;
            uint32_t ah[4][4], al[4][4], bb[2][4];
#pragma unroll
            for (int mt = 0; mt < 4; mt++) {
                int row = wm * 64 + mt * 16 + (sel & 1) * 8 + r8;
                ldsm4(ah[mt], sAhi + (row * GSTR + acol) * 2);
                ldsm4(al[mt], sAlo + (row * GSTR + acol) * 2);
            }
#pragma unroll
            for (int bt = 0; bt < 2; bt++) {
                int nrow = wn * 32 + bt * 16 + (sel >> 1) * 8 + r8;
                ldsm4(bb[bt], sBhi + (nrow * GSTR + bcol) * 2);
            }
#pragma unroll
            for (int mt = 0; mt < 4; mt++)
#pragma unroll
                for (int nt = 0; nt < 4; nt++) {
                    mma16816(acc[mt][nt], ah[mt], bb[nt >> 1][(nt & 1) * 2], bb[nt >> 1][(nt & 1) * 2 + 1]);
                    mma16816(acc[mt][nt], al[mt], bb[nt >> 1][(nt & 1) * 2], bb[nt >> 1][(nt & 1) * 2 + 1]);
                }
#pragma unroll
            for (int bt = 0; bt < 2; bt++) {
                int nrow = wn * 32 + bt * 16 + (sel >> 1) * 8 + r8;
                ldsm4(bb[bt], sBlo + (nrow * GSTR + bcol) * 2);
            }
#pragma unroll
            for (int mt = 0; mt < 4; mt++)
#pragma unroll
                for (int nt = 0; nt < 4; nt++)
                    mma16816(acc[mt][nt], ah[mt], bb[nt >> 1][(nt & 1) * 2], bb[nt >> 1][(nt & 1) * 2 + 1]);
        }
        // no bottom barrier — top-of-loop CP_WAIT0+__syncthreads orders buffer reuse
    }

    const int erow = lane >> 2, ecol = (lane & 3) * 2;
#pragma unroll
    for (int mt = 0; mt < 4; mt++) {
        const size_t row0 = (size_t)(m0 + wm * 64 + mt * 16 + erow);
#pragma unroll
        for (int nt = 0; nt < 4; nt++) {
            const size_t cb = (size_t)(n0 + wn * 32 + nt * 8 + ecol);
            *reinterpret_cast<float2*>(Cm + row0 * 1024 + cb) =
                make_float2(acc[mt][nt][0], acc[mt][nt][1]);
            *reinterpret_cast<float2*>(Cm + (row0 + 8) * 1024 + cb) =
                make_float2(acc[mt][nt][2], acc[mt][nt][3]);
        }
    }
}

__global__ void __launch_bounds__(256, 2) gemm_v_tc() { gemm_hmma_body(g_xhi, g_xlo, g_Wvhi, g_Wvlo, g_xwv); }
__global__ void __launch_bounds__(256, 2) gemm_g_tc() { gemm_hmma_body(g_xhi, g_xlo, g_Wghi, g_Wglo, g_gate); }
__global__ void __launch_bounds__(256, 2) gemm_o_tc(float* __restrict__ out) {
    gemm_hmma_body(g_ahi, g_alo, g_Wohi, g_Wolo, out);
}

// ---------------- causal depthwise conv + SiLU + beta (4 outputs/thread) --------
__global__ void __launch_bounds__(256) conv_silu(const float* __restrict__ conv_w,
                                                 const float* __restrict__ conv_b) {
    const int gb = blockIdx.x;
    const int dblk = gb & 3;                  // 4 d-blocks of 256
    const long tg = (long)(gb >> 2);          // token group (4 tokens)
    const int d = dblk * 256 + threadIdx.x;
    const long bt0 = tg * 4;
    const int t0 = (int)(bt0 & (T_ - 1));
    const int h = d >> 7;

    float xr[7];
#pragma unroll
    for (int j = 0; j < 7; j++) {
        int tt = t0 - 3 + j;
        xr[j] = (tt >= 0) ? g_xwv[(bt0 - 3 + j) * D_ + d] : 0.f;
    }
    const float bs = conv_b[d];
    const float w0 = conv_w[d * 4 + 0], w1 = conv_w[d * 4 + 1];
    const float w2 = conv_w[d * 4 + 2], w3 = conv_w[d * 4 + 3];
#pragma unroll
    for (int i = 0; i < 4; i++) {
        float a = bs;
        a = fmaf(xr[i + 0], w0, a);
        a = fmaf(xr[i + 1], w1, a);
        a = fmaf(xr[i + 2], w2, a);
        a = fmaf(xr[i + 3], w3, a);
        float s = a / (1.f + expf(-a));
        g_v[(bt0 + i) * D_ + d] = s * g_beta[(bt0 + i) * H_ + h];
    }
}

// ---------------- per-chunk: cumsum, HMMA dots, attn(bf16), blocked solve --------
__global__ void __launch_bounds__(256, 2) chunk_prep() {
    extern __shared__ char cpsm[];
    __nv_bfloat16* swh = (__nv_bfloat16*)cpsm;             // 64*CAB
    __nv_bfloat16* swl = swh + 64 * CAB;
    __nv_bfloat16* srh = swl + 64 * CAB;
    __nv_bfloat16* srl = srh + 64 * CAB;                   // end 69632 B
    float* sA = (float*)(cpsm + 69632);                    // 64*64 fp32 -> end 86016 B
    float* s1 = (float*)(cpsm + 34816);                    // aliases srh/srl
    float* s2 = (float*)cpsm;                              // aliases swh/swl
    __shared__ float sdec[C_], sbeta[C_], sraw[C_];
    const int id = blockIdx.x;
    const int chunk = id & 63;
    const int bh = id >> 6;
    const int b = bh >> 3, h = bh & 7;
    const long t0 = (long)b * T_ + chunk * C_;
    const long base = t0 * D_ + h * K_;
    const int tid = threadIdx.x;
    const int wid = tid >> 5, lane = tid & 31;
    const int g8 = lane >> 3, r8 = lane & 7;

    {
        const uint32_t swh_s = smem_u32(swh), swl_s = smem_u32(swl);
        const uint32_t srh_s = smem_u32(srh), srl_s = smem_u32(srl);
#pragma unroll
        for (int q = 0; q < 4; q++) {
            int u = tid + q * 256;
            int row = u >> 4, seg = (u & 15) * 8;
            uint32_t d = (uint32_t)(row * CAB + seg) * 2;
            long g = base + (long)row * D_ + seg;
            cpasync16(swh_s + d, g_wk_h + g);
            cpasync16(swl_s + d, g_wk_l + g);
            cpasync16(srh_s + d, g_rk_h + g);
            cpasync16(srl_s + d, g_rk_l + g);
        }
        CP_COMMIT();
    }
    if (tid < C_) {
        sraw[tid] = g_dec[(t0 + tid) * H_ + h];
        sbeta[tid] = g_beta[(t0 + tid) * H_ + h];
    }
    __syncthreads();
    if (tid < C_) {
        float acc = 0.f;
        for (int j = 0; j <= tid; j++) acc += sraw[j];
        sdec[tid] = acc;
        g_dcum[(t0 + tid) * H_ + h] = acc;
    }
    CP_WAIT0();
    __syncthreads();

    // HMMA: P = [wk; rk] @ wk^T
    {
        const uint32_t swh_s = smem_u32(swh), swl_s = smem_u32(swl);
        const uint32_t srh_s = smem_u32(srh), srl_s = smem_u32(srl);
        const uint32_t ash = (wid < 4) ? swh_s : srh_s;
        const uint32_t asl = (wid < 4) ? swl_s : srl_s;
        const int am0 = (wid & 3) * 16;
        const int aro = (g8 & 1) * 8 + r8, aco = (g8 >> 1) * 8;
        const int bro = (g8 >> 1) * 8 + r8, bco = (g8 & 1) * 8;
        float acc[8][4];
#pragma unroll
        for (int nt = 0; nt < 8; nt++)
#pragma unroll
            for (int q = 0; q < 4; q++) acc[nt][q] = 0.f;
#pragma unroll
        for (int ks = 0; ks < 8; ks++) {
            uint32_t ah[4], al[4], bh4[4][4], bl4[4][4];
            uint32_t aoff = (uint32_t)((am0 + aro) * CAB + ks * 16 + aco) * 2;
            ldsm4(ah, ash + aoff);
            ldsm4(al, asl + aoff);
#pragma unroll
            for (int bt = 0; bt < 4; bt++) {
                uint32_t boff = (uint32_t)((bt * 16 + bro) * CAB + ks * 16 + bco) * 2;
                ldsm4(bh4[bt], swh_s + boff);
                ldsm4(bl4[bt], swl_s + boff);
            }
#pragma unroll
            for (int nt = 0; nt < 8; nt++) {
                uint32_t b0h = bh4[nt >> 1][(nt & 1) * 2], b1h = bh4[nt >> 1][(nt & 1) * 2 + 1];
                uint32_t b0l = bl4[nt >> 1][(nt & 1) * 2], b1l = bl4[nt >> 1][(nt & 1) * 2 + 1];
                mma16816(acc[nt], ah, b0h, b1h);
                mma16816(acc[nt], al, b0h, b1h);
                mma16816(acc[nt], ah, b0l, b1l);
            }
        }
        const int er = lane >> 2, ec = (lane & 3) * 2;
        const int i1 = am0 + er, i2 = i1 + 8;
        if (wid < 4) {
            const float b1v = sbeta[i1], b2v = sbeta[i2];
            const float d1 = sdec[i1], d2 = sdec[i2];
#pragma unroll
            for (int nt = 0; nt < 8; nt++) {
                const int j = nt * 8 + ec;
                float a00 = (j     < i1) ? -acc[nt][0] * b1v * __expf(d1 - sdec[j])     : 0.f;
                float a01 = (j + 1 < i1) ? -acc[nt][1] * b1v * __expf(d1 - sdec[j + 1]) : 0.f;
                float a10 = (j     < i2) ? -acc[nt][2] * b2v * __expf(d2 - sdec[j])     : 0.f;
                float a11 = (j + 1 < i2) ? -acc[nt][3] * b2v * __expf(d2 - sdec[j + 1]) : 0.f;
                sA[i1 * 64 + j] = a00; sA[i1 * 64 + j + 1] = a01;
                sA[i2 * 64 + j] = a10; sA[i2 * 64 + j + 1] = a11;
            }
        } else {
            const float d1 = sdec[i1], d2 = sdec[i2];
            const long ab = (long)id * 4096;
#pragma unroll
            for (int nt = 0; nt < 8; nt++) {
                const int j = nt * 8 + ec;
                float a00 = (j     <= i1) ? acc[nt][0] * __expf(d1 - sdec[j])     : 0.f;
                float a01 = (j + 1 <= i1) ? acc[nt][1] * __expf(d1 - sdec[j + 1]) : 0.f;
                float a10 = (j     <= i2) ? acc[nt][2] * __expf(d2 - sdec[j])     : 0.f;
                float a11 = (j + 1 <= i2) ? acc[nt][3] * __expf(d2 - sdec[j + 1]) : 0.f;
                __nv_bfloat16 h0, l0, h1, l1;
                bfsplit(a00, h0, l0); bfsplit(a01, h1, l1);
                *reinterpret_cast<__nv_bfloat162*>(g_attn_h + ab + i1 * 64 + j) = __nv_bfloat162(h0, h1);
                *reinterpret_cast<__nv_bfloat162*>(g_attn_l + ab + i1 * 64 + j) = __nv_bfloat162(l0, l1);
                bfsplit(a10, h0, l0); bfsplit(a11, h1, l1);
                *reinterpret_cast<__nv_bfloat162*>(g_attn_h + ab + i2 * 64 + j) = __nv_bfloat162(h0, h1);
                *reinterpret_cast<__nv_bfloat162*>(g_attn_l + ab + i2 * 64 + j) = __nv_bfloat162(l0, l1);
            }
        }
    }
    if (tid < C_) sraw[tid] = sbeta[tid] * __expf(sdec[tid]);
    __syncthreads();

    for (int i = tid; i < C_ * K_; i += 256) {
        int c = i >> 7, k = i & 127;
        float wv = __bfloat162float(swh[c * CAB + k]) + __bfloat162float(swl[c * CAB + k]);
        s1[c * RS + k] = wv * sraw[c];
    }
    __syncthreads();
    for (int i = tid; i < C_ * K_; i += 256) {
        int c = i >> 7, k = i & 127;
        s2[c * RS + k] = g_v[base + (long)c * D_ + k];
    }
    __syncthreads();

    {
        float* sx = (tid < 128) ? s1 : s2;
        const int k = tid & 127;
        for (int i = 1; i < 32; i++) {
            float a = 0.f;
            const float* Ai = sA + i * 64;
#pragma unroll 4
            for (int j = 0; j < i; j++)
                a = fmaf(Ai[j], sx[j * RS + k], a);
            sx[i * RS + k] += a;
        }
        float up[32];
#pragma unroll
        for (int i = 0; i < 32; i++) up[i] = 0.f;
        for (int j = 0; j < 32; j++) {
            float xv = sx[j * RS + k];
#pragma unroll
            for (int i = 0; i < 32; i++)
                up[i] = fmaf(sA[(32 + i) * 64 + j], xv, up[i]);
        }
#pragma unroll
        for (int i = 0; i < 32; i++)
            sx[(32 + i) * RS + k] += up[i];
        for (int i = 33; i < 64; i++) {
            float a = 0.f;
            const float* Ai = sA + i * 64;
#pragma unroll 4
            for (int j = 32; j < i; j++)
                a = fmaf(Ai[j], sx[j * RS + k], a);
            sx[i * RS + k] += a;
        }
    }
    __syncthreads();

    for (int i = tid; i < C_ * K_; i += 256) {
        int c = i >> 7, k = i & 127;
        float u = s1[c * RS + k];
        __nv_bfloat16 hh, ll;
        bfsplit(u, hh, ll);
        g_wkc_h[base + (long)c * D_ + k] = hh;
        g_wkc_l[base + (long)c * D_ + k] = ll;
        g_v[base + (long)c * D_ + k] = s2[c * RS + k];
    }
}

// ---------------- HMMA chunk scan (S held in registers of warps 0-3) -------------
#define SHS 56     // Shi/Slo, svh/svl, s2h/l bf16
#define SAB 136    // sA / swk bf16
#define STB 72     // attn bf16
#define SVF 36     // sv fp32

__global__ void __launch_bounds__(256) scan_kernel() {
    extern __shared__ char smraw[];
    __nv_bfloat16* sShi = (__nv_bfloat16*)smraw;                   // 128*SHS
    __nv_bfloat16* sSlo = sShi + 128 * SHS;
    __nv_bfloat16* sAh  = sSlo + 128 * SHS;
    __nv_bfloat16* sAl  = sAh + 128 * SAB;
    __nv_bfloat16* sWh  = sAl + 128 * SAB;
    __nv_bfloat16* sWl  = sWh + 64 * SAB;
    __nv_bfloat16* sTh  = sWl + 64 * SAB;
    __nv_bfloat16* sTl  = sTh + 64 * STB;
    __nv_bfloat16* svh  = sTl + 64 * STB;
    __nv_bfloat16* svl  = svh + 64 * SHS;
    __nv_bfloat16* s2h  = svl + 64 * SHS;
    __nv_bfloat16* s2l  = s2h + 64 * SHS;
    float* sv = (float*)(s2l + 64 * SHS);

    const int bh = blockIdx.x >> 2;
    const int slice = blockIdx.x & 3;
    const int b = bh >> 3, h = bh & 7;
    const int j0g = slice * SW;
    const int tid = threadIdx.x;
    const int wid = tid >> 5, lane = tid & 31;
    const int g8 = lane >> 3, r8 = lane & 7;
    const int aro = (g8 & 1) * 8 + r8;
    const int aco = (g8 >> 1) * 8;
    const int bro = (g8 & 1) * 8 + r8;
    const int bco = (g8 >> 1) * 8;
    const int tro = (g8 >> 1) * 8 + r8;
    const int tco = (g8 & 1) * 8;
    const int er = lane >> 2, ec = (lane & 3) * 2;

    const uint32_t sShi_s = smem_u32(sShi), sSlo_s = smem_u32(sSlo);
    const uint32_t sAh_s = smem_u32(sAh), sAl_s = smem_u32(sAl);
    const uint32_t sWh_s = smem_u32(sWh), sWl_s = smem_u32(sWl);
    const uint32_t sTh_s = smem_u32(sTh), sTl_s = smem_u32(sTl);
    const uint32_t svh_s = smem_u32(svh), svl_s = smem_u32(svl);
    const uint32_t s2h_s = smem_u32(s2h), s2l_s = smem_u32(s2l);
    const uint32_t sv_s = smem_u32(sv);

    auto issue_Av = [&](int chunk) {
        const long base = ((long)b * T_ + chunk * C_) * D_ + h * K_;
#pragma unroll
        for (int q = 0; q < 8; q++) {
            int u = tid + q * 256;
            int row = u >> 4, seg = (u & 15) * 8;
            uint32_t d = (uint32_t)(row * SAB + seg) * 2;
            if (row < 64) {
                long g = base + (long)row * D_ + seg;
                cpasync16(sAh_s + d, g_wkc_h + g);
                cpasync16(sAl_s + d, g_wkc_l + g);
            } else {
                long g = base + (long)(row - 64) * D_ + seg;
                cpasync16(sAh_s + d, g_rk_h + g);
                cpasync16(sAl_s + d, g_rk_l + g);
            }
        }
#pragma unroll
        for (int q = 0; q < 2; q++) {
            int u = tid + q * 256;
            int row = u >> 3, seg = (u & 7) * 4;
            cpasync16(sv_s + (uint32_t)(row * SVF + seg) * 4,
                      g_v + base + (long)row * D_ + j0g + seg);
        }
        CP_COMMIT();
    };
    auto issue_W = [&](int chunk) {
        const long base = ((long)b * T_ + chunk * C_) * D_ + h * K_;
        const int lt = tid;
#pragma unroll
        for (int q = 0; q < 8; q++) {
            int u = lt + q * 128;
            int row = u >> 4, seg = (u & 15) * 8;
            uint32_t d = (uint32_t)(row * SAB + seg) * 2;
            long g = base + (long)row * D_ + seg;
            cpasync16(sWh_s + d, g_wk_h + g);
            cpasync16(sWl_s + d, g_wk_l + g);
        }
        CP_COMMIT();
    };
    auto issue_T = [&](int chunk) {
        const int lt = tid - 128;
        const long ab = ((long)bh * NCH + chunk) * 4096;
#pragma unroll
        for (int q = 0; q < 4; q++) {
            int u = lt + q * 128;
            int row = u >> 3, seg = (u & 7) * 8;
            uint32_t d = (uint32_t)(row * STB + seg) * 2;
            cpasync16(sTh_s + d, g_attn_h + ab + row * 64 + seg);
            cpasync16(sTl_s + d, g_attn_l + ab + row * 64 + seg);
        }
        CP_COMMIT();
    };

    float Sreg[2][16];
#pragma unroll
    for (int mt = 0; mt < 2; mt++)
#pragma unroll
        for (int q = 0; q < 16; q++) Sreg[mt][q] = 0.f;

    for (int i = tid; i < 128 * SHS; i += 256) {
        sShi[i] = __float2bfloat16(0.f);
        sSlo[i] = __float2bfloat16(0.f);
    }
    issue_Av(0);
    if (wid < 4) issue_W(0); else issue_T(0);

    const int m0 = wid * 16;

    for (int chunk = 0; chunk < NCH; chunk++) {
        const long t0 = (long)b * T_ + chunk * C_;
        const long obase = t0 * D_ + h * K_;
        CP_WAIT0();
        const int myrow = (wid < 4) ? (m0 + er) : (m0 - 64 + er);
        const float dec63 = g_dcum[(t0 + 63) * H_ + h];
        const float decA = g_dcum[(t0 + myrow) * H_ + h];
        const float decB = g_dcum[(t0 + myrow + 8) * H_ + h];
        __syncthreads();

        // ---- HMMA1: P(128x32) = [wkc; rk] @ S ----
        float acc[4][4];
#pragma unroll
        for (int nt = 0; nt < 4; nt++)
#pragma unroll
            for (int q = 0; q < 4; q++) acc[nt][q] = 0.f;
#pragma unroll
        for (int ks = 0; ks < 8; ks++) {
            uint32_t ah[4], al[4], bhf[2][4], blf[2][4];
            uint32_t aoff = (uint32_t)((m0 + aro) * SAB + ks * 16 + aco) * 2;
            ldsm4(ah, sAh_s + aoff);
            ldsm4(al, sAl_s + aoff);
#pragma unroll
            for (int nh = 0; nh < 2; nh++) {
                uint32_t boff = (uint32_t)((ks * 16 + bro) * SHS + nh * 16 + bco) * 2;
                ldsm4t(bhf[nh], sShi_s + boff);
                ldsm4t(blf[nh], sSlo_s + boff);
            }
#pragma unroll
            for (int nt = 0; nt < 4; nt++) {
                uint32_t b0h = bhf[nt >> 1][(nt & 1) * 2], b1h = bhf[nt >> 1][(nt & 1) * 2 + 1];
                uint32_t b0l = blf[nt >> 1][(nt & 1) * 2], b1l = blf[nt >> 1][(nt & 1) * 2 + 1];
                mma16816(acc[nt], ah, b0h, b1h);
                mma16816(acc[nt], al, b0h, b1h);
                mma16816(acc[nt], ah, b0l, b1l);
            }
        }

        // ---- epilogue 1 ----
        if (wid < 4) {
            const int c1 = m0 + er, c2 = c1 + 8;
            const float dw1 = __expf(dec63 - decA), dw2 = __expf(dec63 - decB);
#pragma unroll
            for (int nt = 0; nt < 4; nt++) {
                const int col = nt * 8 + ec;
                float a0 = sv[c1 * SVF + col]     - acc[nt][0];
                float a1 = sv[c1 * SVF + col + 1] - acc[nt][1];
                float a2 = sv[c2 * SVF + col]     - acc[nt][2];
                float a3 = sv[c2 * SVF + col + 1] - acc[nt][3];
                __nv_bfloat16 h0, l0, h1, l1, h2, l2, h3, l3;
                bfsplit(a0, h0, l0); bfsplit(a1, h1, l1);
                bfsplit(a2, h2, l2); bfsplit(a3, h3, l3);
                *reinterpret_cast<__nv_bfloat162*>(svh + c1 * SHS + col) = __nv_bfloat162(h0, h1);
                *reinterpret_cast<__nv_bfloat162*>(svl + c1 * SHS + col) = __nv_bfloat162(l0, l1);
                *reinterpret_cast<__nv_bfloat162*>(svh + c2 * SHS + col) = __nv_bfloat162(h2, h3);
                *reinterpret_cast<__nv_bfloat162*>(svl + c2 * SHS + col) = __nv_bfloat162(l2, l3);
                float b0 = dw1 * a0, b1 = dw1 * a1, b2 = dw2 * a2, b3 = dw2 * a3;
                bfsplit(b0, h0, l0); bfsplit(b1, h1, l1);
                bfsplit(b2, h2, l2); bfsplit(b3, h3, l3);
                *reinterpret_cast<__nv_bfloat162*>(s2h + c1 * SHS + col) = __nv_bfloat162(h0, h1);
                *reinterpret_cast<__nv_bfloat162*>(s2l + c1 * SHS + col) = __nv_bfloat162(l0, l1);
                *reinterpret_cast<__nv_bfloat162*>(s2h + c2 * SHS + col) = __nv_bfloat162(h2, h3);
                *reinterpret_cast<__nv_bfloat162*>(s2l + c2 * SHS + col) = __nv_bfloat162(l2, l3);
            }
        } else {
            const float e1 = __expf(decA), e2 = __expf(decB);
#pragma unroll
            for (int nt = 0; nt < 4; nt++) {
                acc[nt][0] *= e1; acc[nt][1] *= e1;
                acc[nt][2] *= e2; acc[nt][3] *= e2;
            }
        }
        __syncthreads();
        if (chunk + 1 < NCH) issue_Av(chunk + 1);

        if (wid >= 4) {
            const int m0o = (wid - 4) * 16;
#pragma unroll
            for (int ks = 0; ks < 4; ks++) {
                uint32_t ah[4], al[4], bhf[2][4], blf[2][4];
                uint32_t aoff = (uint32_t)((m0o + aro) * STB + ks * 16 + aco) * 2;
                ldsm4(ah, sTh_s + aoff);
                ldsm4(al, sTl_s + aoff);
#pragma unroll
                for (int nh = 0; nh < 2; nh++) {
                    uint32_t boff = (uint32_t)((ks * 16 + bro) * SHS + nh * 16 + bco) * 2;
                    ldsm4t(bhf[nh], svh_s + boff);
                    ldsm4t(blf[nh], svl_s + boff);
                }
#pragma unroll
                for (int nt = 0; nt < 4; nt++) {
                    uint32_t b0h = bhf[nt >> 1][(nt & 1) * 2], b1h = bhf[nt >> 1][(nt & 1) * 2 + 1];
                    uint32_t b0l = blf[nt >> 1][(nt & 1) * 2], b1l = blf[nt >> 1][(nt & 1) * 2 + 1];
                    mma16816(acc[nt], ah, b0h, b1h);
                    mma16816(acc[nt], al, b0h, b1h);
                    mma16816(acc[nt], ah, b0l, b1l);
                }
            }
            const int c1 = m0o + er, c2 = c1 + 8;
#pragma unroll
            for (int nt = 0; nt < 4; nt++) {
                const int col = nt * 8 + ec;
                *reinterpret_cast<float2*>(g_o + obase + (long)c1 * D_ + j0g + col) =
                    make_float2(acc[nt][0], acc[nt][1]);
                *reinterpret_cast<float2*>(g_o + obase + (long)c2 * D_ + j0g + col) =
                    make_float2(acc[nt][2], acc[nt][3]);
            }
            if (chunk + 1 < NCH) issue_T(chunk + 1);
        } else {
            // ---- S = e63*S + wk^T @ (dw*v_new), in registers; write Shi/Slo ----
            const float e63 = __expf(dec63);
#pragma unroll
            for (int mt = 0; mt < 2; mt++) {
                const int m0s = wid * 32 + mt * 16;
                float a2c[4][4];
#pragma unroll
                for (int nt = 0; nt < 4; nt++)
#pragma unroll
                    for (int q = 0; q < 4; q++) a2c[nt][q] = 0.f;
#pragma unroll
                for (int ks = 0; ks < 4; ks++) {
                    uint32_t ah[4], al[4], bhf[2][4], blf[2][4];
                    uint32_t aoff = (uint32_t)((ks * 16 + tro) * SAB + m0s + tco) * 2;
                    ldsm4t(ah, sWh_s + aoff);
                    ldsm4t(al, sWl_s + aoff);
#pragma unroll
                    for (int nh = 0; nh < 2; nh++) {
                        uint32_t boff = (uint32_t)((ks * 16 + bro) * SHS + nh * 16 + bco) * 2;
                        ldsm4t(bhf[nh], s2h_s + boff);
                        ldsm4t(blf[nh], s2l_s + boff);
                    }
#pragma unroll
                    for (int nt = 0; nt < 4; nt++) {
                        uint32_t b0h = bhf[nt >> 1][(nt & 1) * 2], b1h = bhf[nt >> 1][(nt & 1) * 2 + 1];
                        uint32_t b0l = blf[nt >> 1][(nt & 1) * 2], b1l = blf[nt >> 1][(nt & 1) * 2 + 1];
                        mma16816(a2c[nt], ah, b0h, b1h);
                        mma16816(a2c[nt], al, b0h, b1h);
                        mma16816(a2c[nt], ah, b0l, b1l);
                    }
                }
                const int k1 = m0s + er, k2 = k1 + 8;
#pragma unroll
                for (int nt = 0; nt < 4; nt++) {
                    const int col = nt * 8 + ec;
                    float n00 = Sreg[mt][nt * 4 + 0] * e63 + a2c[nt][0];
                    float n01 = Sreg[mt][nt * 4 + 1] * e63 + a2c[nt][1];
                    float n10 = Sreg[mt][nt * 4 + 2] * e63 + a2c[nt][2];
                    float n11 = Sreg[mt][nt * 4 + 3] * e63 + a2c[nt][3];
                    Sreg[mt][nt * 4 + 0] = n00; Sreg[mt][nt * 4 + 1] = n01;
                    Sreg[mt][nt * 4 + 2] = n10; Sreg[mt][nt * 4 + 3] = n11;
                    __nv_bfloat16 hh, ll;
                    bfsplit(n00, hh, ll); sShi[k1 * SHS + col] = hh;     sSlo[k1 * SHS + col] = ll;
                    bfsplit(n01, hh, ll); sShi[k1 * SHS + col + 1] = hh; sSlo[k1 * SHS + col + 1] = ll;
                    bfsplit(n10, hh, ll); sShi[k2 * SHS + col] = hh;     sSlo[k2 * SHS + col] = ll;
                    bfsplit(n11, hh, ll); sShi[k2 * SHS + col + 1] = hh; sSlo[k2 * SHS + col + 1] = ll;
                }
            }
            if (chunk + 1 < NCH) issue_W(chunk + 1);
        }
    }
}

// ---------------- per-head RMSNorm + gated SiLU (warp per row) -------------------
__global__ void __launch_bounds__(256) rms_gate(const float* __restrict__ norm_w) {
    const int row = blockIdx.x * 8 + (threadIdx.x >> 5);   // (b*T+t)*H + h
    const int lane = threadIdx.x & 31;
    const long gi = (long)row * K_ + lane * 4;
    float4 ov = *reinterpret_cast<const float4*>(g_o + gi);
    float s = ov.x * ov.x + ov.y * ov.y + ov.z * ov.z + ov.w * ov.w;
#pragma unroll
    for (int off = 16; off; off >>= 1) s += __shfl_xor_sync(0xffffffffu, s, off);
    float r = rsqrtf(s * (1.f / 128.f) + 1e-5f);
    float4 g = *reinterpret_cast<const float4*>(g_gate + gi);
    float4 nw = *reinterpret_cast<const float4*>(norm_w + lane * 4);
    float v0 = ov.x * r * nw.x * (g.x / (1.f + expf(-g.x)));
    float v1 = ov.y * r * nw.y * (g.y / (1.f + expf(-g.y)));
    float v2 = ov.z * r * nw.z * (g.z / (1.f + expf(-g.z)));
    float v3 = ov.w * r * nw.w * (g.w / (1.f + expf(-g.w)));
    __nv_bfloat16 h0, l0, h1, l1, h2, l2, h3, l3;
    bfsplit(v0, h0, l0); bfsplit(v1, h1, l1);
    bfsplit(v2, h2, l2); bfsplit(v3, h3, l3);
    *reinterpret_cast<__nv_bfloat162*>(g_ahi + gi)     = __nv_bfloat162(h0, h1);
    *reinterpret_cast<__nv_bfloat162*>(g_ahi + gi + 2) = __nv_bfloat162(h2, h3);
    *reinterpret_cast<__nv_bfloat162*>(g_alo + gi)     = __nv_bfloat162(l0, l1);
    *reinterpret_cast<__nv_bfloat162*>(g_alo + gi + 2) = __nv_bfloat162(l2, l3);
}

// ---------------- launcher ------------------------------------------------------
extern "C" void kernel_launch(void* const* d_in, const int* in_sizes, int n_in,
                              void* d_out, int out_size) {
    const float* x       = (const float*)d_in[0];
    const float* Wv      = (const float*)d_in[1];
    const float* Wg      = (const float*)d_in[2];
    const float* Wo      = (const float*)d_in[3];
    const float* Wb      = (const float*)d_in[4];
    const float* Wa      = (const float*)d_in[5];
    const float* dt_bias = (const float*)d_in[6];
    const float* A_log   = (const float*)d_in[7];
    const float* norm_w  = (const float*)d_in[8];
    const float* conv_w  = (const float*)d_in[9];
    const float* conv_b  = (const float*)d_in[10];
    float* out = (float*)d_out;

    const int CP_SMEM   = 86016;
    const int SCAN_SMEM = (2 * 128 * SHS + 2 * 128 * SAB + 2 * 64 * SAB +
                           2 * 64 * STB + 4 * 64 * SHS) * 2 + 64 * SVF * 4;
    const int GEMM_SMEM = 2 * STAGE_E * 2;
    cudaFuncSetAttribute(chunk_prep,  cudaFuncAttributeMaxDynamicSharedMemorySize, CP_SMEM);
    cudaFuncSetAttribute(scan_kernel, cudaFuncAttributeMaxDynamicSharedMemorySize, SCAN_SMEM);
    cudaFuncSetAttribute(gemm_v_tc,   cudaFuncAttributeMaxDynamicSharedMemorySize, GEMM_SMEM);
    cudaFuncSetAttribute(gemm_g_tc,   cudaFuncAttributeMaxDynamicSharedMemorySize, GEMM_SMEM);
    cudaFuncSetAttribute(gemm_o_tc,   cudaFuncAttributeMaxDynamicSharedMemorySize, GEMM_SMEM);

    dim3 gg(D_ / 128, M_ / 128);

    if (s_ok) {
        // Capture-legal fork: aux streams join the capture by waiting on an event
        // recorded in the origin stream FIRST, and rejoin stream 0 before the end.
        cudaEventRecord(ev_root, 0);                 // fork point in captured stream
        cudaStreamWaitEvent(s_aux2, ev_root, 0);     // s_aux2 enters capture
        split_w_k<<<(3 * D_ * D_) / 1024, 256, 0, s_aux2>>>(Wv, Wg, Wo);
        cudaEventRecord(ev_w, s_aux2);
        prep_tokens<<<M_, 256>>>(x, Wb, Wa, dt_bias, A_log);
        cudaEventRecord(ev_p, 0);
        cudaStreamWaitEvent(s_aux1, ev_w, 0);        // s_aux1 enters capture
        cudaStreamWaitEvent(s_aux1, ev_p, 0);
        gemm_g_tc<<<gg, 256, GEMM_SMEM, s_aux1>>>();
        cudaEventRecord(ev_g, s_aux1);
        cudaStreamWaitEvent(0, ev_w, 0);             // s_aux2 rejoins
        gemm_v_tc<<<gg, 256, GEMM_SMEM>>>();
        conv_silu<<<(B_ * T_ / 4) * (D_ / 256), 256>>>(conv_w, conv_b);
        chunk_prep<<<B_ * H_ * NCH, 256, CP_SMEM>>>();
        scan_kernel<<<B_ * H_ * SLICES, 256, SCAN_SMEM>>>();
        cudaStreamWaitEvent(0, ev_g, 0);             // s_aux1 rejoins
        rms_gate<<<M_ * H_ / 8, 256>>>(norm_w);
        gemm_o_tc<<<gg, 256, GEMM_SMEM>>>(out);
    } else {
        // sequential fallback
        prep_tokens<<<M_, 256>>>(x, Wb, Wa, dt_bias, A_log);
        split_w_k<<<(3 * D_ * D_) / 1024, 256>>>(Wv, Wg, Wo);
        gemm_v_tc<<<gg, 256, GEMM_SMEM>>>();
        gemm_g_tc<<<gg, 256, GEMM_SMEM>>>();
        conv_silu<<<(B_ * T_ / 4) * (D_ / 256), 256>>>(conv_w, conv_b);
        chunk_prep<<<B_ * H_ * NCH, 256, CP_SMEM>>>();
        scan_kernel<<<B_ * H_ * SLICES, 256, SCAN_SMEM>>>();
        rms_gate<<<M_ * H_ / 8, 256>>>(norm_w);
        gemm_o_tc<<<gg, 256, GEMM_SMEM>>>(out);
    }
}